// round 1
// baseline (speedup 1.0000x reference)
#include <cuda_runtime.h>
#include <math.h>

#define N_NODE 10000
#define N_EDGE 320000
#define HID    128
#define NC     4
#define EDGE_IN 288

#define TE     64      // edges per block (edge kernel)
#define TN     64      // nodes per block (node kernel)
#define KT     32      // k-tile
#define EH_LD  292     // eh smem row stride (pad: mod32==4, mult of 4)
#define BUF_LD 132     // activation buffer stride (pad: mod32==4, mult of 4)
#define NIN_LD 260     // node-input stride

// ---- scratch (static device globals; zeroed via memset nodes each launch) ----
__device__ float g_sumsq[32];
__device__ float g_nagg[N_NODE * HID];
__device__ float g_agg[N_NODE * NC * 3];
__device__ float g_cnt[N_NODE];

__device__ __forceinline__ float silu_f(float x) {
    return x / (1.0f + __expf(-x));
}

// ============================================================================
// Phase A: sums of squares over the edge axis for radial (16) and dist (16).
// Layout matches rad: idx = c*8+f for radial, c*8+4+f for dist.
// ============================================================================
__global__ void sumsq_kernel(const float* __restrict__ coord,
                             const int* __restrict__ row,
                             const int* __restrict__ col)
{
    __shared__ float s_sum[32];
    int tid = threadIdx.x;
    if (tid < 32) s_sum[tid] = 0.0f;
    __syncthreads();

    float p[32];
#pragma unroll
    for (int i = 0; i < 32; i++) p[i] = 0.0f;

    for (int e = blockIdx.x * blockDim.x + tid; e < N_EDGE;
         e += gridDim.x * blockDim.x) {
        const float* ci = coord + row[e] * 12;
        const float* cj = coord + col[e] * 12;
        float a[12], b[12], d[12];
#pragma unroll
        for (int i = 0; i < 12; i++) { a[i] = ci[i]; b[i] = cj[i]; d[i] = a[i] - b[i]; }
#pragma unroll
        for (int c = 0; c < 4; c++) {
#pragma unroll
            for (int f = 0; f < 4; f++) {
                float r = d[c*3+0]*d[f*3+0] + d[c*3+1]*d[f*3+1] + d[c*3+2]*d[f*3+2];
                float dx = a[c*3+0]-b[f*3+0], dy = a[c*3+1]-b[f*3+1], dz = a[c*3+2]-b[f*3+2];
                float d2 = dx*dx + dy*dy + dz*dz;   // dist^2 — sqrt then square cancels
                p[c*8 + f]     += r * r;
                p[c*8 + 4 + f] += d2;
            }
        }
    }
#pragma unroll
    for (int i = 0; i < 32; i++) atomicAdd(&s_sum[i], p[i]);
    __syncthreads();
    if (tid < 32) atomicAdd(&g_sumsq[tid], s_sum[tid]);
}

// ============================================================================
// Shared tiled-GEMM helper: A [64 x K] in smem (row stride lda), W [K x 128]
// row-major in global. 256 threads. Each thread computes 4 rows x 8 cols:
// rows ty*4..ty*4+3 (ty = tid>>4), cols tx + 16*j (tx = tid&15, j=0..7).
// Leaves a trailing __syncthreads() (safe to overwrite A afterward).
// ============================================================================
template <int K>
__device__ __forceinline__ void gemm64(const float* __restrict__ A, int lda,
                                       const float* __restrict__ W,
                                       float* __restrict__ w_sm,
                                       float (&acc)[4][8], int tid)
{
    const int tx = tid & 15, ty = tid >> 4;
#pragma unroll
    for (int i = 0; i < 4; i++)
#pragma unroll
        for (int j = 0; j < 8; j++) acc[i][j] = 0.0f;

    const float* a0 = A + (ty * 4 + 0) * lda;
    const float* a1 = A + (ty * 4 + 1) * lda;
    const float* a2 = A + (ty * 4 + 2) * lda;
    const float* a3 = A + (ty * 4 + 3) * lda;

    for (int k0 = 0; k0 < K; k0 += KT) {
        // stage weight tile [KT x 128]
#pragma unroll
        for (int i = tid * 4; i < KT * 128; i += 256 * 4)
            *(float4*)(w_sm + i) = *(const float4*)(W + k0 * 128 + i);
        __syncthreads();
#pragma unroll 4
        for (int k = 0; k < KT; k++) {
            float b[8];
#pragma unroll
            for (int j = 0; j < 8; j++) b[j] = w_sm[k * 128 + tx + 16 * j];
            float v0 = a0[k0 + k], v1 = a1[k0 + k], v2 = a2[k0 + k], v3 = a3[k0 + k];
#pragma unroll
            for (int j = 0; j < 8; j++) {
                acc[0][j] += v0 * b[j];
                acc[1][j] += v1 * b[j];
                acc[2][j] += v2 * b[j];
                acc[3][j] += v3 * b[j];
            }
        }
        __syncthreads();
    }
}

__device__ __forceinline__ void store_act(const float (&acc)[4][8],
                                          const float* __restrict__ bias,
                                          float* __restrict__ out, int tid,
                                          bool do_silu)
{
    const int tx = tid & 15, ty = tid >> 4;
#pragma unroll
    for (int j = 0; j < 8; j++) {
        int c = tx + 16 * j;
        float bb = bias[c];
#pragma unroll
        for (int i = 0; i < 4; i++) {
            float v = acc[i][j] + bb;
            if (do_silu) v = silu_f(v);
            out[(ty * 4 + i) * BUF_LD + c] = v;
        }
    }
}

// ============================================================================
// Phase B: fused edge kernel. 64 edges / block.
// smem (floats): eh [64*292]=18688 (bufA@0, bufB@8448 overlay),
//   w_sm@18688 (4096), cd@22784 (768), inv@23552 (32),
//   row@23584 (64), col@23648 (64), cw@23712 (512). total 24224 fl = 96896 B.
// ============================================================================
#define EK_OFF_W   18688
#define EK_OFF_CD  22784
#define EK_OFF_INV 23552
#define EK_OFF_ROW 23584
#define EK_OFF_COL 23648
#define EK_OFF_CW  23712
#define EK_SMEM_FL 24224

__global__ void __launch_bounds__(256, 2)
edge_kernel(const float* __restrict__ h, const float* __restrict__ coord,
            const int* __restrict__ row, const int* __restrict__ col,
            const float* __restrict__ e_w1, const float* __restrict__ e_b1,
            const float* __restrict__ e_w2, const float* __restrict__ e_b2,
            const float* __restrict__ c_w1, const float* __restrict__ c_b1,
            const float* __restrict__ c_wout)
{
    extern __shared__ float sm[];
    float* eh    = sm;
    float* bufA  = sm;
    float* bufB  = sm + TE * BUF_LD;
    float* w_sm  = sm + EK_OFF_W;
    float* s_cd  = sm + EK_OFF_CD;
    float* s_inv = sm + EK_OFF_INV;
    int*   s_row = (int*)(sm + EK_OFF_ROW);
    int*   s_col = (int*)(sm + EK_OFF_COL);
    float* s_cw  = sm + EK_OFF_CW;

    const int tid = threadIdx.x;
    const int e0  = blockIdx.x * TE;

    if (tid < 32) {
        float s = g_sumsq[tid];
        s_inv[tid] = 1.0f / fmaxf(sqrtf(s), 1e-12f);
    }
    if (tid < TE) { s_row[tid] = row[e0 + tid]; s_col[tid] = col[e0 + tid]; }
    if (tid < 128) ((float4*)s_cw)[tid] = ((const float4*)c_wout)[tid];
    __syncthreads();

    // gather h[row] | h[col] into eh[:, 0:256]
#pragma unroll
    for (int idx = tid; idx < TE * 64; idx += 256) {
        int e = idx >> 6, q = idx & 63;
        int node = (q < 32) ? s_row[e] : s_col[e];
        int qq = q & 31;
        float4 v = ((const float4*)(h + node * HID))[qq];
        *(float4*)(eh + e * EH_LD + ((q < 32) ? 0 : HID) + qq * 4) = v;
    }
    // rad features into eh[:, 256:288]; coord_diff into s_cd
    if (tid < TE) {
        int e = tid;
        const float* ci = coord + s_row[e] * 12;
        const float* cj = coord + s_col[e] * 12;
        float a[12], b[12], d[12];
#pragma unroll
        for (int i = 0; i < 12; i++) {
            a[i] = ci[i]; b[i] = cj[i]; d[i] = a[i] - b[i];
            s_cd[e * 12 + i] = d[i];
        }
#pragma unroll
        for (int c = 0; c < 4; c++) {
#pragma unroll
            for (int f = 0; f < 4; f++) {
                float r = d[c*3+0]*d[f*3+0] + d[c*3+1]*d[f*3+1] + d[c*3+2]*d[f*3+2];
                float dx = a[c*3+0]-b[f*3+0], dy = a[c*3+1]-b[f*3+1], dz = a[c*3+2]-b[f*3+2];
                float d2 = dx*dx + dy*dy + dz*dz;
                eh[e * EH_LD + 256 + c*8 + f]     = r * s_inv[c*8 + f];
                eh[e * EH_LD + 256 + c*8 + 4 + f] = sqrtf(d2) * s_inv[c*8 + 4 + f];
            }
        }
    }
    __syncthreads();

    float acc[4][8];

    gemm64<EDGE_IN>(eh, EH_LD, e_w1, w_sm, acc, tid);   // t1 = eh @ e_w1
    store_act(acc, e_b1, bufA, tid, true);
    __syncthreads();

    gemm64<HID>(bufA, BUF_LD, e_w2, w_sm, acc, tid);    // m = silu(t1 @ e_w2 + b2)
    store_act(acc, e_b2, bufB, tid, true);
    __syncthreads();

    gemm64<HID>(bufB, BUF_LD, c_w1, w_sm, acc, tid);    // t2 = silu(m @ c_w1 + b)
    store_act(acc, c_b1, bufA, tid, true);
    __syncthreads();

    // w = t2 @ c_wout  (one thread per (edge, channel)) + coord aggregation
    {
        int e = tid >> 2, c = tid & 3;
        float wacc = 0.0f;
#pragma unroll 8
        for (int k = 0; k < HID; k++)
            wacc += bufA[e * BUF_LD + k] * s_cw[k * 4 + c];
        int node = s_row[e];
#pragma unroll
        for (int d3 = 0; d3 < 3; d3++)
            atomicAdd(&g_agg[node * 12 + c * 3 + d3],
                      s_cd[e * 12 + c * 3 + d3] * wacc);
        if (c == 0) atomicAdd(&g_cnt[node], 1.0f);
    }

    // nagg += m  (vectorized global reductions)
    for (int idx = tid; idx < TE * 32; idx += 256) {
        int e = idx >> 5, q = idx & 31;
        float4 v = *(const float4*)(bufB + e * BUF_LD + q * 4);
        float* dst = g_nagg + s_row[e] * HID + q * 4;
        asm volatile("red.global.add.v4.f32 [%0], {%1,%2,%3,%4};"
                     :: "l"(dst), "f"(v.x), "f"(v.y), "f"(v.z), "f"(v.w)
                     : "memory");
    }
}

// ============================================================================
// Phase C: node MLP + residual + coord epilogue. 64 nodes / block.
// smem: nin [64*260]=16640 (bufA overlays @0), w_sm@16640 (4096). 82944 B.
// ============================================================================
#define NK_OFF_W   16640
#define NK_SMEM_FL 20736

__global__ void __launch_bounds__(256, 2)
node_kernel(const float* __restrict__ h, const float* __restrict__ coord,
            const float* __restrict__ n_w1, const float* __restrict__ n_b1,
            const float* __restrict__ n_w2, const float* __restrict__ n_b2,
            float* __restrict__ out_h, float* __restrict__ out_coord)
{
    extern __shared__ float sm[];
    float* nin  = sm;
    float* bufA = sm;
    float* w_sm = sm + NK_OFF_W;

    const int tid = threadIdx.x;
    const int n0  = blockIdx.x * TN;

#pragma unroll
    for (int idx = tid; idx < TN * 64; idx += 256) {
        int r = idx >> 6, q = idx & 63;
        int n = n0 + r;
        int qq = q & 31;
        float4 v = make_float4(0.f, 0.f, 0.f, 0.f);
        if (n < N_NODE) {
            v = (q < 32) ? ((const float4*)(h + n * HID))[qq]
                         : *(const float4*)(g_nagg + n * HID + qq * 4);
        }
        *(float4*)(nin + r * NIN_LD + ((q < 32) ? 0 : HID) + qq * 4) = v;
    }
    __syncthreads();

    float acc[4][8];
    gemm64<2 * HID>(nin, NIN_LD, n_w1, w_sm, acc, tid);
    store_act(acc, n_b1, bufA, tid, true);
    __syncthreads();
    gemm64<HID>(bufA, BUF_LD, n_w2, w_sm, acc, tid);

    {
        const int tx = tid & 15, ty = tid >> 4;
#pragma unroll
        for (int j = 0; j < 8; j++) {
            int c = tx + 16 * j;
            float bb = n_b2[c];
#pragma unroll
            for (int i = 0; i < 4; i++) {
                int n = n0 + ty * 4 + i;
                if (n < N_NODE)
                    out_h[n * HID + c] = acc[i][j] + bb + h[n * HID + c];
            }
        }
    }
    for (int idx = tid; idx < TN * 12; idx += 256) {
        int r = idx / 12, d = idx % 12;
        int n = n0 + r;
        if (n < N_NODE) {
            float cnt = fmaxf(g_cnt[n], 1.0f);
            out_coord[n * 12 + d] = coord[n * 12 + d] + g_agg[n * 12 + d] / cnt;
        }
    }
}

// ============================================================================
extern "C" void kernel_launch(void* const* d_in, const int* in_sizes, int n_in,
                              void* d_out, int out_size)
{
    const float* h      = (const float*)d_in[0];
    const float* coord  = (const float*)d_in[1];
    const int*   row    = (const int*)d_in[2];
    const int*   col    = (const int*)d_in[3];
    const float* e_w1   = (const float*)d_in[4];
    const float* e_b1   = (const float*)d_in[5];
    const float* e_w2   = (const float*)d_in[6];
    const float* e_b2   = (const float*)d_in[7];
    const float* c_w1   = (const float*)d_in[8];
    const float* c_b1   = (const float*)d_in[9];
    const float* c_wout = (const float*)d_in[10];
    const float* n_w1   = (const float*)d_in[11];
    const float* n_b1   = (const float*)d_in[12];
    const float* n_w2   = (const float*)d_in[13];
    const float* n_b2   = (const float*)d_in[14];

    float* out_h     = (float*)d_out;
    float* out_coord = out_h + N_NODE * HID;

    void *p_sumsq, *p_nagg, *p_agg, *p_cnt;
    cudaGetSymbolAddress(&p_sumsq, g_sumsq);
    cudaGetSymbolAddress(&p_nagg,  g_nagg);
    cudaGetSymbolAddress(&p_agg,   g_agg);
    cudaGetSymbolAddress(&p_cnt,   g_cnt);
    cudaMemsetAsync(p_sumsq, 0, 32 * sizeof(float));
    cudaMemsetAsync(p_nagg,  0, N_NODE * HID * sizeof(float));
    cudaMemsetAsync(p_agg,   0, N_NODE * 12 * sizeof(float));
    cudaMemsetAsync(p_cnt,   0, N_NODE * sizeof(float));

    cudaFuncSetAttribute(edge_kernel, cudaFuncAttributeMaxDynamicSharedMemorySize,
                         EK_SMEM_FL * (int)sizeof(float));
    cudaFuncSetAttribute(node_kernel, cudaFuncAttributeMaxDynamicSharedMemorySize,
                         NK_SMEM_FL * (int)sizeof(float));

    sumsq_kernel<<<256, 256>>>(coord, row, col);
    edge_kernel<<<N_EDGE / TE, 256, EK_SMEM_FL * sizeof(float)>>>(
        h, coord, row, col, e_w1, e_b1, e_w2, e_b2, c_w1, c_b1, c_wout);
    node_kernel<<<(N_NODE + TN - 1) / TN, 256, NK_SMEM_FL * sizeof(float)>>>(
        h, coord, n_w1, n_b1, n_w2, n_b2, out_h, out_coord);
}

// round 3
// speedup vs baseline: 1.3302x; 1.3302x over previous
#include <cuda_runtime.h>
#include <cuda_bf16.h>
#include <math.h>
#include <stdint.h>

#define N_NODE 10000
#define N_EDGE 320000
#define HID    128
#define NC     4

// ---------------- SIMT helpers (node kernel) ----------------
#define TN     64
#define KT     32
#define BUF_LD 132
#define NIN_LD 260

// ---------------- edge kernel geometry ----------------
#define ME      128           // edges per CTA
#define LDA_B   656           // A row stride bytes (328 bf16; K padded to 320)
#define LDB_B   272           // B row stride bytes (136 bf16)
#define BCH_B   17408         // one B chunk: 64 rows * 272 B
#define A_HI    0
#define A_LO    83968         // 128*656
#define B_HI    167936
#define B_LO    185344
#define OF_ROW  202752
#define OF_COL  203264
#define OF_INV  203776
#define OF_BIAS 203904
#define OF_CW   204416
#define OF_CD   206464
#define SMEM_EDGE_BYTES 212608

// ---------------- scratch ----------------
__device__ float g_sumsq[32];
__device__ float g_nagg[N_NODE * HID];
__device__ float g_agg[N_NODE * NC * 3];
__device__ float g_cnt[N_NODE];
// weights: transposed-to-[K x 128], zero-padded, bf16-split, padded-stride images
__device__ __align__(16) unsigned char g_w1t[2 * 5 * BCH_B];   // K=320 (5 chunks)
__device__ __align__(16) unsigned char g_w2t[2 * 2 * BCH_B];   // K=128
__device__ __align__(16) unsigned char g_w3t[2 * 2 * BCH_B];   // K=128

__device__ __forceinline__ float silu_f(float x) { return x / (1.0f + __expf(-x)); }

__device__ __forceinline__ uint32_t smem_to_u32(const void* p) {
    uint32_t a;
    asm("{ .reg .u64 t; cvta.to.shared.u64 t, %1; cvt.u32.u64 %0, t; }" : "=r"(a) : "l"(p));
    return a;
}
__device__ __forceinline__ void ldm_x4(uint32_t (&r)[4], uint32_t addr) {
    asm volatile("ldmatrix.sync.aligned.m8n8.x4.shared.b16 {%0,%1,%2,%3}, [%4];"
                 : "=r"(r[0]), "=r"(r[1]), "=r"(r[2]), "=r"(r[3]) : "r"(addr));
}
__device__ __forceinline__ void ldm_x4_t(uint32_t (&r)[4], uint32_t addr) {
    asm volatile("ldmatrix.sync.aligned.m8n8.x4.trans.shared.b16 {%0,%1,%2,%3}, [%4];"
                 : "=r"(r[0]), "=r"(r[1]), "=r"(r[2]), "=r"(r[3]) : "r"(addr));
}
__device__ __forceinline__ void mma_bf16(float (&d)[4], const uint32_t (&a)[4],
                                         uint32_t b0, uint32_t b1) {
    asm volatile("mma.sync.aligned.m16n8k16.row.col.f32.bf16.bf16.f32 "
                 "{%0,%1,%2,%3}, {%4,%5,%6,%7}, {%8,%9}, {%0,%1,%2,%3};"
                 : "+f"(d[0]), "+f"(d[1]), "+f"(d[2]), "+f"(d[3])
                 : "r"(a[0]), "r"(a[1]), "r"(a[2]), "r"(a[3]), "r"(b0), "r"(b1));
}

__device__ __forceinline__ uint32_t pack2bf(float a, float b) {
    __nv_bfloat162 t = __floats2bfloat162_rn(a, b);
    return *reinterpret_cast<uint32_t*>(&t);
}
__device__ __forceinline__ void split_pair(float a, float b, uint32_t& hp, uint32_t& lp) {
    float ah = __bfloat162float(__float2bfloat16(a));
    float bh = __bfloat162float(__float2bfloat16(b));
    hp = pack2bf(ah, bh);
    lp = pack2bf(a - ah, b - bh);
}
// store 4 consecutive fp32 (col % 4 == 0) into split A (hi/lo), row e
__device__ __forceinline__ void store4A(unsigned char* sm, int e, int col, float4 v) {
    uint32_t h0, l0, h1, l1;
    split_pair(v.x, v.y, h0, l0);
    split_pair(v.z, v.w, h1, l1);
    uint32_t off = (uint32_t)(e * LDA_B + col * 2);
    *(uint2*)(sm + A_HI + off) = make_uint2(h0, h1);
    *(uint2*)(sm + A_LO + off) = make_uint2(l0, l1);
}

// ============================================================================
// Phase A: sums of squares over the edge axis (radial 16 + dist 16)
// ============================================================================
__global__ void sumsq_kernel(const float* __restrict__ coord,
                             const int* __restrict__ row,
                             const int* __restrict__ col)
{
    __shared__ float s_sum[32];
    int tid = threadIdx.x;
    if (tid < 32) s_sum[tid] = 0.0f;
    __syncthreads();
    float p[32];
#pragma unroll
    for (int i = 0; i < 32; i++) p[i] = 0.0f;
    for (int e = blockIdx.x * blockDim.x + tid; e < N_EDGE; e += gridDim.x * blockDim.x) {
        const float* ci = coord + row[e] * 12;
        const float* cj = coord + col[e] * 12;
        float a[12], b[12], d[12];
#pragma unroll
        for (int i = 0; i < 12; i++) { a[i] = ci[i]; b[i] = cj[i]; d[i] = a[i] - b[i]; }
#pragma unroll
        for (int c = 0; c < 4; c++) {
#pragma unroll
            for (int f = 0; f < 4; f++) {
                float r = d[c*3+0]*d[f*3+0] + d[c*3+1]*d[f*3+1] + d[c*3+2]*d[f*3+2];
                float dx = a[c*3+0]-b[f*3+0], dy = a[c*3+1]-b[f*3+1], dz = a[c*3+2]-b[f*3+2];
                float d2 = dx*dx + dy*dy + dz*dz;
                p[c*8 + f]     += r * r;     // dist^2: sqrt then square cancels
                p[c*8 + 4 + f] += d2;
            }
        }
    }
#pragma unroll
    for (int i = 0; i < 32; i++) atomicAdd(&s_sum[i], p[i]);
    __syncthreads();
    if (tid < 32) atomicAdd(&g_sumsq[tid], s_sum[tid]);
}

// ============================================================================
// Weight prep: [K x 128] images, zero-padded K, bf16-split, stride 272 B.
// ============================================================================
__global__ void prep_weights(const float* __restrict__ w1,
                             const float* __restrict__ w2,
                             const float* __restrict__ w3)
{
    int idx = blockIdx.x * blockDim.x + threadIdx.x;
    const float* W; unsigned char* dst; int half, r, K;
    if (idx < 40960)      { W = w1; dst = g_w1t; half = 5*BCH_B; r = idx;          K = 288; }
    else if (idx < 57344) { W = w2; dst = g_w2t; half = 2*BCH_B; r = idx - 40960;  K = 128; }
    else if (idx < 73728) { W = w3; dst = g_w3t; half = 2*BCH_B; r = idx - 57344;  K = 128; }
    else return;
    int c = r >> 13;            // chunk (8192 elems per chunk)
    int rem = r & 8191;
    int kl = rem >> 7, n = rem & 127;
    int kk = c * 64 + kl;
    float v = (kk < K) ? W[kk * 128 + n] : 0.0f;
    float vh = __bfloat162float(__float2bfloat16(v));
    __nv_bfloat16 hb = __float2bfloat16(vh);
    __nv_bfloat16 lb = __float2bfloat16(v - vh);
    *(__nv_bfloat16*)(dst + c * BCH_B + kl * LDB_B + n * 2) = hb;
    *(__nv_bfloat16*)(dst + half + c * BCH_B + kl * LDB_B + n * 2) = lb;
}

// ============================================================================
// warp-tiled split-bf16 GEMM: C[128 x 128] += A[128 x 64*nch] @ W
// warp (wm, wn): rows wm*32..+31, cols wn*64..+63. Ends with __syncthreads().
// ============================================================================
__device__ __forceinline__ void run_gemm_mma(
    unsigned char* sm, uint32_t smem_base, float (&acc)[2][8][4],
    int nchunks, int a_col_base, const unsigned char* __restrict__ wsrc, int half_off,
    int tid, int lane, int r0, int n0)
{
#pragma unroll
    for (int mt = 0; mt < 2; mt++)
#pragma unroll
        for (int nb = 0; nb < 8; nb++)
#pragma unroll
            for (int i = 0; i < 4; i++) acc[mt][nb][i] = 0.0f;

    for (int c = 0; c < nchunks; c++) {
        __syncthreads();
        {
            const float4* sh = (const float4*)(wsrc + c * BCH_B);
            const float4* sl = (const float4*)(wsrc + half_off + c * BCH_B);
            float4* dh = (float4*)(sm + B_HI);
            float4* dl = (float4*)(sm + B_LO);
            for (int i = tid; i < BCH_B / 16; i += 256) { dh[i] = sh[i]; dl[i] = sl[i]; }
        }
        __syncthreads();
#pragma unroll
        for (int ks = 0; ks < 4; ks++) {
            int kcol = a_col_base + c * 64 + ks * 16;
            uint32_t ah[2][4], al[2][4];
            uint32_t a_off = (uint32_t)((r0 + (lane & 15)) * LDA_B + (kcol + (lane >> 4) * 8) * 2);
            ldm_x4(ah[0], smem_base + A_HI + a_off);
            ldm_x4(al[0], smem_base + A_LO + a_off);
            ldm_x4(ah[1], smem_base + A_HI + a_off + 16 * LDA_B);
            ldm_x4(al[1], smem_base + A_LO + a_off + 16 * LDA_B);
            uint32_t bh[4][4], bl[4][4];
            uint32_t b_off = (uint32_t)((ks * 16 + (lane & 15)) * LDB_B + (n0 + (lane >> 4) * 8) * 2);
#pragma unroll
            for (int nt = 0; nt < 4; nt++) {
                ldm_x4_t(bh[nt], smem_base + B_HI + b_off + nt * 32);
                ldm_x4_t(bl[nt], smem_base + B_LO + b_off + nt * 32);
            }
            // term 1: hi * hi
#pragma unroll
            for (int mt = 0; mt < 2; mt++)
#pragma unroll
                for (int nt = 0; nt < 4; nt++) {
                    mma_bf16(acc[mt][2*nt],   ah[mt], bh[nt][0], bh[nt][1]);
                    mma_bf16(acc[mt][2*nt+1], ah[mt], bh[nt][2], bh[nt][3]);
                }
            // term 2: hi * lo
#pragma unroll
            for (int mt = 0; mt < 2; mt++)
#pragma unroll
                for (int nt = 0; nt < 4; nt++) {
                    mma_bf16(acc[mt][2*nt],   ah[mt], bl[nt][0], bl[nt][1]);
                    mma_bf16(acc[mt][2*nt+1], ah[mt], bl[nt][2], bl[nt][3]);
                }
            // term 3: lo * hi
#pragma unroll
            for (int mt = 0; mt < 2; mt++)
#pragma unroll
                for (int nt = 0; nt < 4; nt++) {
                    mma_bf16(acc[mt][2*nt],   al[mt], bh[nt][0], bh[nt][1]);
                    mma_bf16(acc[mt][2*nt+1], al[mt], bh[nt][2], bh[nt][3]);
                }
        }
    }
    __syncthreads();
}

// bias + silu + split-store to A cols [dstbase, dstbase+128); optional nagg red
__device__ __forceinline__ void epi_split_store(
    unsigned char* sm, float (&acc)[2][8][4], const float* __restrict__ SBIAS,
    int dstbase, int lane, int r0, int n0, const int* __restrict__ SROW, bool do_nagg)
{
#pragma unroll
    for (int mt = 0; mt < 2; mt++) {
        int ra = r0 + mt * 16 + (lane >> 2);
        int rb = ra + 8;
#pragma unroll
        for (int nb = 0; nb < 8; nb++) {
            int c = n0 + nb * 8 + (lane & 3) * 2;
            float b0 = SBIAS[c], b1 = SBIAS[c + 1];
            float v0 = silu_f(acc[mt][nb][0] + b0);
            float v1 = silu_f(acc[mt][nb][1] + b1);
            float v2 = silu_f(acc[mt][nb][2] + b0);
            float v3 = silu_f(acc[mt][nb][3] + b1);
            uint32_t h0, l0, h1, l1;
            split_pair(v0, v1, h0, l0);
            split_pair(v2, v3, h1, l1);
            uint32_t oa = (uint32_t)(ra * LDA_B + (dstbase + c) * 2);
            uint32_t ob = (uint32_t)(rb * LDA_B + (dstbase + c) * 2);
            *(uint32_t*)(sm + A_HI + oa) = h0;
            *(uint32_t*)(sm + A_LO + oa) = l0;
            *(uint32_t*)(sm + A_HI + ob) = h1;
            *(uint32_t*)(sm + A_LO + ob) = l1;
            if (do_nagg) {
                float* pa = g_nagg + (size_t)SROW[ra] * HID + c;
                float* pb = g_nagg + (size_t)SROW[rb] * HID + c;
                asm volatile("red.global.add.v2.f32 [%0], {%1,%2};"
                             :: "l"(pa), "f"(v0), "f"(v1) : "memory");
                asm volatile("red.global.add.v2.f32 [%0], {%1,%2};"
                             :: "l"(pb), "f"(v2), "f"(v3) : "memory");
            }
        }
    }
}

// ============================================================================
// Fused edge kernel (mma.sync bf16 3x split): 128 edges / CTA, 256 threads.
// ============================================================================
__global__ void __launch_bounds__(256, 1)
edge_kernel(const float* __restrict__ h, const float* __restrict__ coord,
            const int* __restrict__ row, const int* __restrict__ col,
            const float* __restrict__ e_b1, const float* __restrict__ e_b2,
            const float* __restrict__ c_b1, const float* __restrict__ c_wout)
{
    extern __shared__ unsigned char sm[];
    const int tid  = threadIdx.x;
    const int wid  = tid >> 5;
    const int lane = tid & 31;
    const int e0   = blockIdx.x * ME;
    uint32_t smem_base = smem_to_u32(sm);

    int*   SROW  = (int*)(sm + OF_ROW);
    int*   SCOL  = (int*)(sm + OF_COL);
    float* SINV  = (float*)(sm + OF_INV);
    float* SBIAS = (float*)(sm + OF_BIAS);
    float* SCW   = (float*)(sm + OF_CW);
    float* SCD   = (float*)(sm + OF_CD);

    if (tid < 128) { SROW[tid] = row[e0 + tid]; SCOL[tid] = col[e0 + tid]; }
    if (tid < 32)  SINV[tid] = 1.0f / fmaxf(sqrtf(g_sumsq[tid]), 1e-12f);
    if (tid < 128) ((float4*)SCW)[tid] = ((const float4*)c_wout)[tid];
    __syncthreads();

    // ---- gather h[row]|h[col] into A cols 0..255 (split bf16) ----
#pragma unroll 4
    for (int idx = tid; idx < 128 * 64; idx += 256) {
        int e = idx >> 6, p4 = idx & 63;
        int half = p4 >> 5, q = p4 & 31;
        int node = half ? SCOL[e] : SROW[e];
        float4 v = ((const float4*)(h + node * HID))[q];
        store4A(sm, e, half * 128 + q * 4, v);
    }
    // ---- rad features cols 256..287, zeros 288..319; coord_diff to SCD ----
    if (tid < 128) {
        int e = tid;
        const float* ci = coord + SROW[e] * 12;
        const float* cj = coord + SCOL[e] * 12;
        float a[12], b[12], d[12];
#pragma unroll
        for (int i = 0; i < 12; i++) {
            a[i] = ci[i]; b[i] = cj[i]; d[i] = a[i] - b[i];
            SCD[e * 12 + i] = d[i];
        }
        float radv[32];
#pragma unroll
        for (int c = 0; c < 4; c++) {
#pragma unroll
            for (int f = 0; f < 4; f++) {
                float r = d[c*3+0]*d[f*3+0] + d[c*3+1]*d[f*3+1] + d[c*3+2]*d[f*3+2];
                float dx = a[c*3+0]-b[f*3+0], dy = a[c*3+1]-b[f*3+1], dz = a[c*3+2]-b[f*3+2];
                float d2 = dx*dx + dy*dy + dz*dz;
                radv[c*8 + f]     = r * SINV[c*8 + f];
                radv[c*8 + 4 + f] = sqrtf(d2) * SINV[c*8 + 4 + f];
            }
        }
#pragma unroll
        for (int q = 0; q < 64; q += 4) {
            float4 v = make_float4(q < 32 ? radv[q] : 0.f, q+1 < 32 ? radv[q+1] : 0.f,
                                   q+2 < 32 ? radv[q+2] : 0.f, q+3 < 32 ? radv[q+3] : 0.f);
            store4A(sm, e, 256 + q, v);
        }
    }

    const int wm = wid & 3, wn = wid >> 2;
    const int r0 = wm * 32, n0 = wn * 64;
    float acc[2][8][4];

    // ========== GEMM1: t1 = silu(eh @ W1 + b1) -> A cols 0..127 ==========
    if (tid < 128) SBIAS[tid] = e_b1[tid];
    run_gemm_mma(sm, smem_base, acc, 5, 0, g_w1t, 5 * BCH_B, tid, lane, r0, n0);
    epi_split_store(sm, acc, SBIAS, 0, lane, r0, n0, SROW, false);
    __syncthreads();

    // ========== GEMM2: m = silu(t1 @ W2 + b2) -> A cols 128..255, nagg ====
    if (tid < 128) SBIAS[tid] = e_b2[tid];
    __syncthreads();
    run_gemm_mma(sm, smem_base, acc, 2, 0, g_w2t, 2 * BCH_B, tid, lane, r0, n0);
    epi_split_store(sm, acc, SBIAS, 128, lane, r0, n0, SROW, true);
    __syncthreads();

    // ========== GEMM3: t2 = silu(m @ c_w1 + b) -> fp32 buffer =============
    if (tid < 128) SBIAS[tid] = c_b1[tid];
    __syncthreads();
    run_gemm_mma(sm, smem_base, acc, 2, 128, g_w3t, 2 * BCH_B, tid, lane, r0, n0);
    {
        float* t2f = (float*)(sm + A_LO);   // [128 x 132] fp32, A no longer needed
#pragma unroll
        for (int mt = 0; mt < 2; mt++) {
            int ra = r0 + mt * 16 + (lane >> 2);
            int rb = ra + 8;
#pragma unroll
            for (int nb = 0; nb < 8; nb++) {
                int c = n0 + nb * 8 + (lane & 3) * 2;
                float b0 = SBIAS[c], b1 = SBIAS[c + 1];
                *(float2*)(t2f + ra * 132 + c) =
                    make_float2(silu_f(acc[mt][nb][0] + b0), silu_f(acc[mt][nb][1] + b1));
                *(float2*)(t2f + rb * 132 + c) =
                    make_float2(silu_f(acc[mt][nb][2] + b0), silu_f(acc[mt][nb][3] + b1));
            }
        }
    }
    __syncthreads();

    // ========== w = t2 @ c_wout; coord atomics =============================
    {
        const float* t2f = (const float*)(sm + A_LO);
        for (int u = tid; u < 512; u += 256) {
            int e = u >> 2, c = u & 3;
            const float* tr = t2f + e * 132;
            float w = 0.0f;
#pragma unroll 8
            for (int k = 0; k < 128; k++) w += tr[k] * SCW[k * 4 + c];
            int node = SROW[e];
            const float* cd = SCD + e * 12 + c * 3;
            atomicAdd(&g_agg[node * 12 + c * 3 + 0], cd[0] * w);
            atomicAdd(&g_agg[node * 12 + c * 3 + 1], cd[1] * w);
            atomicAdd(&g_agg[node * 12 + c * 3 + 2], cd[2] * w);
            if (c == 0) atomicAdd(&g_cnt[node], 1.0f);
        }
    }
}

// ============================================================================
// Node MLP + residual + coord epilogue (SIMT fp32; proven in R1)
// ============================================================================
template <int K>
__device__ __forceinline__ void gemm64(const float* __restrict__ A, int lda,
                                       const float* __restrict__ W,
                                       float* __restrict__ w_sm,
                                       float (&acc)[4][8], int tid)
{
    const int tx = tid & 15, ty = tid >> 4;
#pragma unroll
    for (int i = 0; i < 4; i++)
#pragma unroll
        for (int j = 0; j < 8; j++) acc[i][j] = 0.0f;
    const float* a0 = A + (ty * 4 + 0) * lda;
    const float* a1 = A + (ty * 4 + 1) * lda;
    const float* a2 = A + (ty * 4 + 2) * lda;
    const float* a3 = A + (ty * 4 + 3) * lda;
    for (int k0 = 0; k0 < K; k0 += KT) {
#pragma unroll
        for (int i = tid * 4; i < KT * 128; i += 256 * 4)
            *(float4*)(w_sm + i) = *(const float4*)(W + k0 * 128 + i);
        __syncthreads();
#pragma unroll 4
        for (int k = 0; k < KT; k++) {
            float b[8];
#pragma unroll
            for (int j = 0; j < 8; j++) b[j] = w_sm[k * 128 + tx + 16 * j];
            float v0 = a0[k0 + k], v1 = a1[k0 + k], v2 = a2[k0 + k], v3 = a3[k0 + k];
#pragma unroll
            for (int j = 0; j < 8; j++) {
                acc[0][j] += v0 * b[j];
                acc[1][j] += v1 * b[j];
                acc[2][j] += v2 * b[j];
                acc[3][j] += v3 * b[j];
            }
        }
        __syncthreads();
    }
}

#define NK_OFF_W   16640
#define NK_SMEM_FL 20736

__global__ void __launch_bounds__(256, 2)
node_kernel(const float* __restrict__ h, const float* __restrict__ coord,
            const float* __restrict__ n_w1, const float* __restrict__ n_b1,
            const float* __restrict__ n_w2, const float* __restrict__ n_b2,
            float* __restrict__ out_h, float* __restrict__ out_coord)
{
    extern __shared__ float smf[];
    float* nin  = smf;
    float* bufA = smf;
    float* w_sm = smf + NK_OFF_W;
    const int tid = threadIdx.x;
    const int n0  = blockIdx.x * TN;

#pragma unroll
    for (int idx = tid; idx < TN * 64; idx += 256) {
        int r = idx >> 6, q = idx & 63;
        int n = n0 + r;
        int qq = q & 31;
        float4 v = make_float4(0.f, 0.f, 0.f, 0.f);
        if (n < N_NODE)
            v = (q < 32) ? ((const float4*)(h + n * HID))[qq]
                         : *(const float4*)(g_nagg + n * HID + qq * 4);
        *(float4*)(nin + r * NIN_LD + ((q < 32) ? 0 : HID) + qq * 4) = v;
    }
    __syncthreads();

    float acc[4][8];
    gemm64<2 * HID>(nin, NIN_LD, n_w1, w_sm, acc, tid);
    {
        const int tx = tid & 15, ty = tid >> 4;
#pragma unroll
        for (int j = 0; j < 8; j++) {
            int c = tx + 16 * j;
            float bb = n_b1[c];
#pragma unroll
            for (int i = 0; i < 4; i++)
                bufA[(ty * 4 + i) * BUF_LD + c] = silu_f(acc[i][j] + bb);
        }
    }
    __syncthreads();
    gemm64<HID>(bufA, BUF_LD, n_w2, w_sm, acc, tid);

    {
        const int tx = tid & 15, ty = tid >> 4;
#pragma unroll
        for (int j = 0; j < 8; j++) {
            int c = tx + 16 * j;
            float bb = n_b2[c];
#pragma unroll
            for (int i = 0; i < 4; i++) {
                int n = n0 + ty * 4 + i;
                if (n < N_NODE)
                    out_h[n * HID + c] = acc[i][j] + bb + h[n * HID + c];
            }
        }
    }
    for (int idx = tid; idx < TN * 12; idx += 256) {
        int r = idx / 12, d = idx % 12;
        int n = n0 + r;
        if (n < N_NODE) {
            float cnt = fmaxf(g_cnt[n], 1.0f);
            out_coord[n * 12 + d] = coord[n * 12 + d] + g_agg[n * 12 + d] / cnt;
        }
    }
}

// ============================================================================
extern "C" void kernel_launch(void* const* d_in, const int* in_sizes, int n_in,
                              void* d_out, int out_size)
{
    const float* h      = (const float*)d_in[0];
    const float* coord  = (const float*)d_in[1];
    const int*   row    = (const int*)d_in[2];
    const int*   col    = (const int*)d_in[3];
    const float* e_w1   = (const float*)d_in[4];
    const float* e_b1   = (const float*)d_in[5];
    const float* e_w2   = (const float*)d_in[6];
    const float* e_b2   = (const float*)d_in[7];
    const float* c_w1   = (const float*)d_in[8];
    const float* c_b1   = (const float*)d_in[9];
    const float* c_wout = (const float*)d_in[10];
    const float* n_w1   = (const float*)d_in[11];
    const float* n_b1   = (const float*)d_in[12];
    const float* n_w2   = (const float*)d_in[13];
    const float* n_b2   = (const float*)d_in[14];

    float* out_h     = (float*)d_out;
    float* out_coord = out_h + N_NODE * HID;

    void *p_sumsq, *p_nagg, *p_agg, *p_cnt;
    cudaGetSymbolAddress(&p_sumsq, g_sumsq);
    cudaGetSymbolAddress(&p_nagg,  g_nagg);
    cudaGetSymbolAddress(&p_agg,   g_agg);
    cudaGetSymbolAddress(&p_cnt,   g_cnt);
    cudaMemsetAsync(p_sumsq, 0, 32 * sizeof(float));
    cudaMemsetAsync(p_nagg,  0, N_NODE * HID * sizeof(float));
    cudaMemsetAsync(p_agg,   0, N_NODE * 12 * sizeof(float));
    cudaMemsetAsync(p_cnt,   0, N_NODE * sizeof(float));

    cudaFuncSetAttribute(edge_kernel, cudaFuncAttributeMaxDynamicSharedMemorySize,
                         SMEM_EDGE_BYTES);
    cudaFuncSetAttribute(node_kernel, cudaFuncAttributeMaxDynamicSharedMemorySize,
                         NK_SMEM_FL * (int)sizeof(float));

    prep_weights<<<288, 256>>>(e_w1, e_w2, c_w1);
    sumsq_kernel<<<1184, 256>>>(coord, row, col);
    edge_kernel<<<N_EDGE / ME, 256, SMEM_EDGE_BYTES>>>(
        h, coord, row, col, e_b1, e_b2, c_b1, c_wout);
    node_kernel<<<(N_NODE + TN - 1) / TN, 256, NK_SMEM_FL * sizeof(float)>>>(
        h, coord, n_w1, n_b1, n_w2, n_b2, out_h, out_coord);
}

// round 4
// speedup vs baseline: 1.6308x; 1.2260x over previous
#include <cuda_runtime.h>
#include <cuda_bf16.h>
#include <math.h>
#include <stdint.h>

#define N_NODE 10000
#define N_EDGE 320000
#define HID    128
#define NC     4

// ---------------- SIMT helpers (node kernel) ----------------
#define TN     64
#define KT     32
#define BUF_LD 132
#define NIN_LD 260

// ---------------- edge kernel geometry ----------------
#define ME      128           // edges per CTA
#define LDA_B   656           // A row stride bytes (328 bf16; K padded to 320)
#define LDB_B   272           // B row stride bytes (136 bf16)
#define BCH_B   17408         // one B chunk: 64 rows * 272 B
#define A_HI    0
#define A_LO    83968         // 128*656
#define B_HI    167936        // hi+lo contiguous: 34816 B total
#define B_LO    185344
#define OF_ROW  202752
#define OF_COL  203264
#define OF_INV  203776
#define OF_BIAS 203904
#define OF_CW   204416
#define OF_CD   206464
#define SMEM_EDGE_BYTES 212608

#define ETHREADS 512

// ---------------- scratch ----------------
__device__ float g_sumsq[32];
__device__ float g_nagg[N_NODE * HID];
__device__ float g_agg[N_NODE * NC * 3];
__device__ float g_cnt[N_NODE];
__device__ __align__(16) unsigned char g_w1t[2 * 5 * BCH_B];   // K=320 (5 chunks)
__device__ __align__(16) unsigned char g_w2t[2 * 2 * BCH_B];   // K=128
__device__ __align__(16) unsigned char g_w3t[2 * 2 * BCH_B];   // K=128

__device__ __forceinline__ float silu_f(float x) { return x / (1.0f + __expf(-x)); }

__device__ __forceinline__ uint32_t smem_to_u32(const void* p) {
    uint32_t a;
    asm("{ .reg .u64 t; cvta.to.shared.u64 t, %1; cvt.u32.u64 %0, t; }" : "=r"(a) : "l"(p));
    return a;
}
__device__ __forceinline__ void ldm_x4(uint32_t (&r)[4], uint32_t addr) {
    asm volatile("ldmatrix.sync.aligned.m8n8.x4.shared.b16 {%0,%1,%2,%3}, [%4];"
                 : "=r"(r[0]), "=r"(r[1]), "=r"(r[2]), "=r"(r[3]) : "r"(addr));
}
__device__ __forceinline__ void ldm_x4_t(uint32_t (&r)[4], uint32_t addr) {
    asm volatile("ldmatrix.sync.aligned.m8n8.x4.trans.shared.b16 {%0,%1,%2,%3}, [%4];"
                 : "=r"(r[0]), "=r"(r[1]), "=r"(r[2]), "=r"(r[3]) : "r"(addr));
}
__device__ __forceinline__ void mma_bf16(float (&d)[4], const uint32_t (&a)[4],
                                         uint32_t b0, uint32_t b1) {
    asm volatile("mma.sync.aligned.m16n8k16.row.col.f32.bf16.bf16.f32 "
                 "{%0,%1,%2,%3}, {%4,%5,%6,%7}, {%8,%9}, {%0,%1,%2,%3};"
                 : "+f"(d[0]), "+f"(d[1]), "+f"(d[2]), "+f"(d[3])
                 : "r"(a[0]), "r"(a[1]), "r"(a[2]), "r"(a[3]), "r"(b0), "r"(b1));
}

__device__ __forceinline__ uint32_t pack2bf(float a, float b) {
    __nv_bfloat162 t = __floats2bfloat162_rn(a, b);
    return *reinterpret_cast<uint32_t*>(&t);
}
__device__ __forceinline__ void split_pair(float a, float b, uint32_t& hp, uint32_t& lp) {
    float ah = __bfloat162float(__float2bfloat16(a));
    float bh = __bfloat162float(__float2bfloat16(b));
    hp = pack2bf(ah, bh);
    lp = pack2bf(a - ah, b - bh);
}
__device__ __forceinline__ void store4A(unsigned char* sm, int e, int col, float4 v) {
    uint32_t h0, l0, h1, l1;
    split_pair(v.x, v.y, h0, l0);
    split_pair(v.z, v.w, h1, l1);
    uint32_t off = (uint32_t)(e * LDA_B + col * 2);
    *(uint2*)(sm + A_HI + off) = make_uint2(h0, h1);
    *(uint2*)(sm + A_LO + off) = make_uint2(l0, l1);
}

// ============================================================================
// Phase A: sums of squares over the edge axis (radial 16 + dist 16)
// ============================================================================
__global__ void sumsq_kernel(const float* __restrict__ coord,
                             const int* __restrict__ row,
                             const int* __restrict__ col)
{
    __shared__ float s_sum[32];
    int tid = threadIdx.x;
    if (tid < 32) s_sum[tid] = 0.0f;
    __syncthreads();
    float p[32];
#pragma unroll
    for (int i = 0; i < 32; i++) p[i] = 0.0f;
    for (int e = blockIdx.x * blockDim.x + tid; e < N_EDGE; e += gridDim.x * blockDim.x) {
        const float* ci = coord + row[e] * 12;
        const float* cj = coord + col[e] * 12;
        float a[12], b[12], d[12];
#pragma unroll
        for (int i = 0; i < 12; i++) { a[i] = ci[i]; b[i] = cj[i]; d[i] = a[i] - b[i]; }
#pragma unroll
        for (int c = 0; c < 4; c++) {
#pragma unroll
            for (int f = 0; f < 4; f++) {
                float r = d[c*3+0]*d[f*3+0] + d[c*3+1]*d[f*3+1] + d[c*3+2]*d[f*3+2];
                float dx = a[c*3+0]-b[f*3+0], dy = a[c*3+1]-b[f*3+1], dz = a[c*3+2]-b[f*3+2];
                float d2 = dx*dx + dy*dy + dz*dz;
                p[c*8 + f]     += r * r;
                p[c*8 + 4 + f] += d2;
            }
        }
    }
#pragma unroll
    for (int i = 0; i < 32; i++) atomicAdd(&s_sum[i], p[i]);
    __syncthreads();
    if (tid < 32) atomicAdd(&g_sumsq[tid], s_sum[tid]);
}

// ============================================================================
// Weight prep: [K x 128] images, zero-padded K, bf16-split, stride 272 B.
// ============================================================================
__global__ void prep_weights(const float* __restrict__ w1,
                             const float* __restrict__ w2,
                             const float* __restrict__ w3)
{
    int idx = blockIdx.x * blockDim.x + threadIdx.x;
    const float* W; unsigned char* dst; int half, r, K;
    if (idx < 40960)      { W = w1; dst = g_w1t; half = 5*BCH_B; r = idx;          K = 288; }
    else if (idx < 57344) { W = w2; dst = g_w2t; half = 2*BCH_B; r = idx - 40960;  K = 128; }
    else if (idx < 73728) { W = w3; dst = g_w3t; half = 2*BCH_B; r = idx - 57344;  K = 128; }
    else return;
    int c = r >> 13;
    int rem = r & 8191;
    int kl = rem >> 7, n = rem & 127;
    int kk = c * 64 + kl;
    float v = (kk < K) ? W[kk * 128 + n] : 0.0f;
    float vh = __bfloat162float(__float2bfloat16(v));
    __nv_bfloat16 hb = __float2bfloat16(vh);
    __nv_bfloat16 lb = __float2bfloat16(v - vh);
    *(__nv_bfloat16*)(dst + c * BCH_B + kl * LDB_B + n * 2) = hb;
    *(__nv_bfloat16*)(dst + half + c * BCH_B + kl * LDB_B + n * 2) = lb;
}

// ============================================================================
// warp-tiled split-bf16 GEMM with register-staged B prefetch pipeline.
// 16 warps in 4x4 grid: warp tile 32 rows x 32 cols. Ends with __syncthreads.
// ============================================================================
#define NSTG 5   // ceil(2176 / 512)

__device__ __forceinline__ void ld_stage(uint4 (&stg)[NSTG],
                                         const unsigned char* __restrict__ wsrc,
                                         int half_off, int c, int tid)
{
    const uint4* sh = (const uint4*)(wsrc + c * BCH_B);
    const uint4* sl = (const uint4*)(wsrc + half_off + c * BCH_B);
#pragma unroll
    for (int i = 0; i < NSTG; i++) {
        int idx = tid + i * ETHREADS;
        if (idx < 2176)
            stg[i] = (idx < 1088) ? sh[idx] : sl[idx - 1088];
    }
}

__device__ __forceinline__ void run_gemm_mma(
    unsigned char* sm, uint32_t smem_base, float (&acc)[2][4][4],
    int nchunks, int a_col_base, const unsigned char* __restrict__ wsrc, int half_off,
    int tid, int lane, int r0, int n0)
{
#pragma unroll
    for (int mt = 0; mt < 2; mt++)
#pragma unroll
        for (int nb = 0; nb < 4; nb++)
#pragma unroll
            for (int i = 0; i < 4; i++) acc[mt][nb][i] = 0.0f;

    uint4 stg[NSTG];
    ld_stage(stg, wsrc, half_off, 0, tid);

    for (int c = 0; c < nchunks; c++) {
        __syncthreads();                       // previous chunk's MMAs done with B
        {
            uint4* db = (uint4*)(sm + B_HI);   // hi+lo contiguous
#pragma unroll
            for (int i = 0; i < NSTG; i++) {
                int idx = tid + i * ETHREADS;
                if (idx < 2176) db[idx] = stg[i];
            }
        }
        __syncthreads();
        if (c + 1 < nchunks)                   // overlap next chunk's LDGs with MMA
            ld_stage(stg, wsrc, half_off, c + 1, tid);

#pragma unroll
        for (int ks = 0; ks < 4; ks++) {
            int kcol = a_col_base + c * 64 + ks * 16;
            uint32_t ah[2][4], al[2][4];
            uint32_t a_off = (uint32_t)((r0 + (lane & 15)) * LDA_B + (kcol + (lane >> 4) * 8) * 2);
            ldm_x4(ah[0], smem_base + A_HI + a_off);
            ldm_x4(al[0], smem_base + A_LO + a_off);
            ldm_x4(ah[1], smem_base + A_HI + a_off + 16 * LDA_B);
            ldm_x4(al[1], smem_base + A_LO + a_off + 16 * LDA_B);
            uint32_t bh[2][4], bl[2][4];
            uint32_t b_off = (uint32_t)((ks * 16 + (lane & 15)) * LDB_B + (n0 + (lane >> 4) * 8) * 2);
#pragma unroll
            for (int nt = 0; nt < 2; nt++) {
                ldm_x4_t(bh[nt], smem_base + B_HI + b_off + nt * 32);
                ldm_x4_t(bl[nt], smem_base + B_LO + b_off + nt * 32);
            }
#pragma unroll
            for (int mt = 0; mt < 2; mt++)
#pragma unroll
                for (int nt = 0; nt < 2; nt++) {
                    mma_bf16(acc[mt][2*nt],   ah[mt], bh[nt][0], bh[nt][1]);
                    mma_bf16(acc[mt][2*nt+1], ah[mt], bh[nt][2], bh[nt][3]);
                }
#pragma unroll
            for (int mt = 0; mt < 2; mt++)
#pragma unroll
                for (int nt = 0; nt < 2; nt++) {
                    mma_bf16(acc[mt][2*nt],   ah[mt], bl[nt][0], bl[nt][1]);
                    mma_bf16(acc[mt][2*nt+1], ah[mt], bl[nt][2], bl[nt][3]);
                }
#pragma unroll
            for (int mt = 0; mt < 2; mt++)
#pragma unroll
                for (int nt = 0; nt < 2; nt++) {
                    mma_bf16(acc[mt][2*nt],   al[mt], bh[nt][0], bh[nt][1]);
                    mma_bf16(acc[mt][2*nt+1], al[mt], bh[nt][2], bh[nt][3]);
                }
        }
    }
    __syncthreads();
}

// bias + silu + split-store to A cols [dstbase, dstbase+128); optional nagg red
__device__ __forceinline__ void epi_split_store(
    unsigned char* sm, float (&acc)[2][4][4], const float* __restrict__ SBIAS,
    int dstbase, int lane, int r0, int n0, const int* __restrict__ SROW, bool do_nagg)
{
#pragma unroll
    for (int mt = 0; mt < 2; mt++) {
        int ra = r0 + mt * 16 + (lane >> 2);
        int rb = ra + 8;
#pragma unroll
        for (int nb = 0; nb < 4; nb++) {
            int c = n0 + nb * 8 + (lane & 3) * 2;
            float b0 = SBIAS[c], b1 = SBIAS[c + 1];
            float v0 = silu_f(acc[mt][nb][0] + b0);
            float v1 = silu_f(acc[mt][nb][1] + b1);
            float v2 = silu_f(acc[mt][nb][2] + b0);
            float v3 = silu_f(acc[mt][nb][3] + b1);
            uint32_t h0, l0, h1, l1;
            split_pair(v0, v1, h0, l0);
            split_pair(v2, v3, h1, l1);
            uint32_t oa = (uint32_t)(ra * LDA_B + (dstbase + c) * 2);
            uint32_t ob = (uint32_t)(rb * LDA_B + (dstbase + c) * 2);
            *(uint32_t*)(sm + A_HI + oa) = h0;
            *(uint32_t*)(sm + A_LO + oa) = l0;
            *(uint32_t*)(sm + A_HI + ob) = h1;
            *(uint32_t*)(sm + A_LO + ob) = l1;
            if (do_nagg) {
                float* pa = g_nagg + (size_t)SROW[ra] * HID + c;
                float* pb = g_nagg + (size_t)SROW[rb] * HID + c;
                asm volatile("red.global.add.v2.f32 [%0], {%1,%2};"
                             :: "l"(pa), "f"(v0), "f"(v1) : "memory");
                asm volatile("red.global.add.v2.f32 [%0], {%1,%2};"
                             :: "l"(pb), "f"(v2), "f"(v3) : "memory");
            }
        }
    }
}

// ============================================================================
// Fused edge kernel: 128 edges / CTA, 512 threads, 16 warps in 4x4 grid.
// ============================================================================
__global__ void __launch_bounds__(ETHREADS, 1)
edge_kernel(const float* __restrict__ h, const float* __restrict__ coord,
            const int* __restrict__ row, const int* __restrict__ col,
            const float* __restrict__ e_b1, const float* __restrict__ e_b2,
            const float* __restrict__ c_b1, const float* __restrict__ c_wout)
{
    extern __shared__ unsigned char sm[];
    const int tid  = threadIdx.x;
    const int wid  = tid >> 5;
    const int lane = tid & 31;
    const int e0   = blockIdx.x * ME;
    uint32_t smem_base = smem_to_u32(sm);

    int*   SROW  = (int*)(sm + OF_ROW);
    int*   SCOL  = (int*)(sm + OF_COL);
    float* SINV  = (float*)(sm + OF_INV);
    float* SBIAS = (float*)(sm + OF_BIAS);
    float* SCW   = (float*)(sm + OF_CW);
    float* SCD   = (float*)(sm + OF_CD);

    if (tid < 128) { SROW[tid] = row[e0 + tid]; SCOL[tid] = col[e0 + tid]; }
    if (tid < 32)  SINV[tid] = 1.0f / fmaxf(sqrtf(g_sumsq[tid]), 1e-12f);
    if (tid < 128) ((float4*)SCW)[tid] = ((const float4*)c_wout)[tid];
    __syncthreads();

    // ---- gather h[row]|h[col] into A cols 0..255 (split bf16) ----
#pragma unroll 4
    for (int idx = tid; idx < 128 * 64; idx += ETHREADS) {
        int e = idx >> 6, p4 = idx & 63;
        int half = p4 >> 5, q = p4 & 31;
        int node = half ? SCOL[e] : SROW[e];
        float4 v = ((const float4*)(h + node * HID))[q];
        store4A(sm, e, half * 128 + q * 4, v);
    }
    // ---- rad features cols 256..287, zeros 288..319; coord_diff to SCD ----
    if (tid < 128) {
        int e = tid;
        const float* ci = coord + SROW[e] * 12;
        const float* cj = coord + SCOL[e] * 12;
        float a[12], b[12], d[12];
#pragma unroll
        for (int i = 0; i < 12; i++) {
            a[i] = ci[i]; b[i] = cj[i]; d[i] = a[i] - b[i];
            SCD[e * 12 + i] = d[i];
        }
        float radv[32];
#pragma unroll
        for (int c = 0; c < 4; c++) {
#pragma unroll
            for (int f = 0; f < 4; f++) {
                float r = d[c*3+0]*d[f*3+0] + d[c*3+1]*d[f*3+1] + d[c*3+2]*d[f*3+2];
                float dx = a[c*3+0]-b[f*3+0], dy = a[c*3+1]-b[f*3+1], dz = a[c*3+2]-b[f*3+2];
                float d2 = dx*dx + dy*dy + dz*dz;
                radv[c*8 + f]     = r * SINV[c*8 + f];
                radv[c*8 + 4 + f] = sqrtf(d2) * SINV[c*8 + 4 + f];
            }
        }
#pragma unroll
        for (int q = 0; q < 64; q += 4) {
            float4 v = make_float4(q < 32 ? radv[q] : 0.f, q+1 < 32 ? radv[q+1] : 0.f,
                                   q+2 < 32 ? radv[q+2] : 0.f, q+3 < 32 ? radv[q+3] : 0.f);
            store4A(sm, e, 256 + q, v);
        }
    }

    const int wm = wid & 3, wn = wid >> 2;
    const int r0 = wm * 32, n0 = wn * 32;
    float acc[2][4][4];

    // ========== GEMM1: t1 = silu(eh @ W1 + b1) -> A cols 0..127 ==========
    if (tid < 128) SBIAS[tid] = e_b1[tid];
    run_gemm_mma(sm, smem_base, acc, 5, 0, g_w1t, 5 * BCH_B, tid, lane, r0, n0);
    epi_split_store(sm, acc, SBIAS, 0, lane, r0, n0, SROW, false);
    __syncthreads();

    // ========== GEMM2: m = silu(t1 @ W2 + b2) -> A cols 128..255, nagg ====
    if (tid < 128) SBIAS[tid] = e_b2[tid];
    __syncthreads();
    run_gemm_mma(sm, smem_base, acc, 2, 0, g_w2t, 2 * BCH_B, tid, lane, r0, n0);
    epi_split_store(sm, acc, SBIAS, 128, lane, r0, n0, SROW, true);
    __syncthreads();

    // ========== GEMM3: t2 = silu(m @ c_w1 + b) -> fp32 buffer =============
    if (tid < 128) SBIAS[tid] = c_b1[tid];
    __syncthreads();
    run_gemm_mma(sm, smem_base, acc, 2, 128, g_w3t, 2 * BCH_B, tid, lane, r0, n0);
    {
        float* t2f = (float*)(sm + A_LO);   // [128 x 132] fp32 (A no longer needed)
#pragma unroll
        for (int mt = 0; mt < 2; mt++) {
            int ra = r0 + mt * 16 + (lane >> 2);
            int rb = ra + 8;
#pragma unroll
            for (int nb = 0; nb < 4; nb++) {
                int c = n0 + nb * 8 + (lane & 3) * 2;
                float b0 = SBIAS[c], b1 = SBIAS[c + 1];
                *(float2*)(t2f + ra * 132 + c) =
                    make_float2(silu_f(acc[mt][nb][0] + b0), silu_f(acc[mt][nb][1] + b1));
                *(float2*)(t2f + rb * 132 + c) =
                    make_float2(silu_f(acc[mt][nb][2] + b0), silu_f(acc[mt][nb][3] + b1));
            }
        }
    }
    __syncthreads();

    // ========== w = t2 @ c_wout; coord atomics =============================
    if (tid < 512) {
        int e = tid >> 2, c = tid & 3;
        const float* t2f = (const float*)(sm + A_LO);
        const float* tr = t2f + e * 132;
        float w = 0.0f;
#pragma unroll 8
        for (int k = 0; k < 128; k++) w += tr[k] * SCW[k * 4 + c];
        int node = SROW[e];
        const float* cd = SCD + e * 12 + c * 3;
        atomicAdd(&g_agg[node * 12 + c * 3 + 0], cd[0] * w);
        atomicAdd(&g_agg[node * 12 + c * 3 + 1], cd[1] * w);
        atomicAdd(&g_agg[node * 12 + c * 3 + 2], cd[2] * w);
        if (c == 0) atomicAdd(&g_cnt[node], 1.0f);
    }
}

// ============================================================================
// Node MLP + residual + coord epilogue (SIMT fp32)
// ============================================================================
template <int K>
__device__ __forceinline__ void gemm64(const float* __restrict__ A, int lda,
                                       const float* __restrict__ W,
                                       float* __restrict__ w_sm,
                                       float (&acc)[4][8], int tid)
{
    const int tx = tid & 15, ty = tid >> 4;
#pragma unroll
    for (int i = 0; i < 4; i++)
#pragma unroll
        for (int j = 0; j < 8; j++) acc[i][j] = 0.0f;
    const float* a0 = A + (ty * 4 + 0) * lda;
    const float* a1 = A + (ty * 4 + 1) * lda;
    const float* a2 = A + (ty * 4 + 2) * lda;
    const float* a3 = A + (ty * 4 + 3) * lda;
    for (int k0 = 0; k0 < K; k0 += KT) {
#pragma unroll
        for (int i = tid * 4; i < KT * 128; i += 256 * 4)
            *(float4*)(w_sm + i) = *(const float4*)(W + k0 * 128 + i);
        __syncthreads();
#pragma unroll 4
        for (int k = 0; k < KT; k++) {
            float b[8];
#pragma unroll
            for (int j = 0; j < 8; j++) b[j] = w_sm[k * 128 + tx + 16 * j];
            float v0 = a0[k0 + k], v1 = a1[k0 + k], v2 = a2[k0 + k], v3 = a3[k0 + k];
#pragma unroll
            for (int j = 0; j < 8; j++) {
                acc[0][j] += v0 * b[j];
                acc[1][j] += v1 * b[j];
                acc[2][j] += v2 * b[j];
                acc[3][j] += v3 * b[j];
            }
        }
        __syncthreads();
    }
}

#define NK_OFF_W   16640
#define NK_SMEM_FL 20736

__global__ void __launch_bounds__(256, 2)
node_kernel(const float* __restrict__ h, const float* __restrict__ coord,
            const float* __restrict__ n_w1, const float* __restrict__ n_b1,
            const float* __restrict__ n_w2, const float* __restrict__ n_b2,
            float* __restrict__ out_h, float* __restrict__ out_coord)
{
    extern __shared__ float smf[];
    float* nin  = smf;
    float* bufA = smf;
    float* w_sm = smf + NK_OFF_W;
    const int tid = threadIdx.x;
    const int n0  = blockIdx.x * TN;

#pragma unroll
    for (int idx = tid; idx < TN * 64; idx += 256) {
        int r = idx >> 6, q = idx & 63;
        int n = n0 + r;
        int qq = q & 31;
        float4 v = make_float4(0.f, 0.f, 0.f, 0.f);
        if (n < N_NODE)
            v = (q < 32) ? ((const float4*)(h + n * HID))[qq]
                         : *(const float4*)(g_nagg + n * HID + qq * 4);
        *(float4*)(nin + r * NIN_LD + ((q < 32) ? 0 : HID) + qq * 4) = v;
    }
    __syncthreads();

    float acc[4][8];
    gemm64<2 * HID>(nin, NIN_LD, n_w1, w_sm, acc, tid);
    {
        const int tx = tid & 15, ty = tid >> 4;
#pragma unroll
        for (int j = 0; j < 8; j++) {
            int c = tx + 16 * j;
            float bb = n_b1[c];
#pragma unroll
            for (int i = 0; i < 4; i++)
                bufA[(ty * 4 + i) * BUF_LD + c] = silu_f(acc[i][j] + bb);
        }
    }
    __syncthreads();
    gemm64<HID>(bufA, BUF_LD, n_w2, w_sm, acc, tid);

    {
        const int tx = tid & 15, ty = tid >> 4;
#pragma unroll
        for (int j = 0; j < 8; j++) {
            int c = tx + 16 * j;
            float bb = n_b2[c];
#pragma unroll
            for (int i = 0; i < 4; i++) {
                int n = n0 + ty * 4 + i;
                if (n < N_NODE)
                    out_h[n * HID + c] = acc[i][j] + bb + h[n * HID + c];
            }
        }
    }
    for (int idx = tid; idx < TN * 12; idx += 256) {
        int r = idx / 12, d = idx % 12;
        int n = n0 + r;
        if (n < N_NODE) {
            float cnt = fmaxf(g_cnt[n], 1.0f);
            out_coord[n * 12 + d] = coord[n * 12 + d] + g_agg[n * 12 + d] / cnt;
        }
    }
}

// ============================================================================
extern "C" void kernel_launch(void* const* d_in, const int* in_sizes, int n_in,
                              void* d_out, int out_size)
{
    const float* h      = (const float*)d_in[0];
    const float* coord  = (const float*)d_in[1];
    const int*   row    = (const int*)d_in[2];
    const int*   col    = (const int*)d_in[3];
    const float* e_w1   = (const float*)d_in[4];
    const float* e_b1   = (const float*)d_in[5];
    const float* e_w2   = (const float*)d_in[6];
    const float* e_b2   = (const float*)d_in[7];
    const float* c_w1   = (const float*)d_in[8];
    const float* c_b1   = (const float*)d_in[9];
    const float* c_wout = (const float*)d_in[10];
    const float* n_w1   = (const float*)d_in[11];
    const float* n_b1   = (const float*)d_in[12];
    const float* n_w2   = (const float*)d_in[13];
    const float* n_b2   = (const float*)d_in[14];

    float* out_h     = (float*)d_out;
    float* out_coord = out_h + N_NODE * HID;

    void *p_sumsq, *p_nagg, *p_agg, *p_cnt;
    cudaGetSymbolAddress(&p_sumsq, g_sumsq);
    cudaGetSymbolAddress(&p_nagg,  g_nagg);
    cudaGetSymbolAddress(&p_agg,   g_agg);
    cudaGetSymbolAddress(&p_cnt,   g_cnt);
    cudaMemsetAsync(p_sumsq, 0, 32 * sizeof(float));
    cudaMemsetAsync(p_nagg,  0, N_NODE * HID * sizeof(float));
    cudaMemsetAsync(p_agg,   0, N_NODE * 12 * sizeof(float));
    cudaMemsetAsync(p_cnt,   0, N_NODE * sizeof(float));

    cudaFuncSetAttribute(edge_kernel, cudaFuncAttributeMaxDynamicSharedMemorySize,
                         SMEM_EDGE_BYTES);
    cudaFuncSetAttribute(node_kernel, cudaFuncAttributeMaxDynamicSharedMemorySize,
                         NK_SMEM_FL * (int)sizeof(float));

    prep_weights<<<288, 256>>>(e_w1, e_w2, c_w1);
    sumsq_kernel<<<1184, 256>>>(coord, row, col);
    edge_kernel<<<N_EDGE / ME, ETHREADS, SMEM_EDGE_BYTES>>>(
        h, coord, row, col, e_b1, e_b2, c_b1, c_wout);
    node_kernel<<<(N_NODE + TN - 1) / TN, 256, NK_SMEM_FL * sizeof(float)>>>(
        h, coord, n_w1, n_b1, n_w2, n_b2, out_h, out_coord);
}

// round 5
// speedup vs baseline: 1.7784x; 1.0905x over previous
#include <cuda_runtime.h>
#include <cuda_bf16.h>
#include <math.h>
#include <stdint.h>

#define N_NODE 10000
#define N_EDGE 320000
#define HID    128
#define NC     4

// ---------------- SIMT helpers (node kernel) ----------------
#define TN     64
#define KT     32
#define BUF_LD 132
#define NIN_LD 260

// ---------------- edge kernel geometry ----------------
#define ME      64            // edges per CTA
#define ETHREADS 256
#define LDA_B   656           // A row stride bytes (328 bf16; K padded to 320)
#define LDB_B   272           // B row stride bytes (136 bf16)
#define BCH_B   8704          // one B chunk: 32 k-rows * 272 B
#define A_HI    0
#define A_LO    41984         // 64*656
#define B_HI    83968
#define B_LO    92672
#define OF_ROW  101376
#define OF_COL  101632
#define OF_INV  101888
#define OF_BIAS 102016
#define OF_CW   102528
#define OF_CD   104576
#define SMEM_EDGE_BYTES 107648

// ---------------- scratch ----------------
__device__ float g_sumsq[32];
__device__ float g_nagg[N_NODE * HID];
__device__ float g_agg[N_NODE * NC * 3];
__device__ float g_cnt[N_NODE];
// weight images: [K x 128] bf16, row stride 272 B, hi image then lo image
__device__ __align__(16) unsigned char g_w1t[2 * 320 * LDB_B];
__device__ __align__(16) unsigned char g_w2t[2 * 128 * LDB_B];
__device__ __align__(16) unsigned char g_w3t[2 * 128 * LDB_B];

__device__ __forceinline__ float silu_f(float x) {
    return __fdividef(x, 1.0f + __expf(-x));
}

__device__ __forceinline__ uint32_t smem_to_u32(const void* p) {
    uint32_t a;
    asm("{ .reg .u64 t; cvta.to.shared.u64 t, %1; cvt.u32.u64 %0, t; }" : "=r"(a) : "l"(p));
    return a;
}
__device__ __forceinline__ void ldm_x4(uint32_t (&r)[4], uint32_t addr) {
    asm volatile("ldmatrix.sync.aligned.m8n8.x4.shared.b16 {%0,%1,%2,%3}, [%4];"
                 : "=r"(r[0]), "=r"(r[1]), "=r"(r[2]), "=r"(r[3]) : "r"(addr));
}
__device__ __forceinline__ void ldm_x4_t(uint32_t (&r)[4], uint32_t addr) {
    asm volatile("ldmatrix.sync.aligned.m8n8.x4.trans.shared.b16 {%0,%1,%2,%3}, [%4];"
                 : "=r"(r[0]), "=r"(r[1]), "=r"(r[2]), "=r"(r[3]) : "r"(addr));
}
__device__ __forceinline__ void mma_bf16(float (&d)[4], const uint32_t (&a)[4],
                                         uint32_t b0, uint32_t b1) {
    asm volatile("mma.sync.aligned.m16n8k16.row.col.f32.bf16.bf16.f32 "
                 "{%0,%1,%2,%3}, {%4,%5,%6,%7}, {%8,%9}, {%0,%1,%2,%3};"
                 : "+f"(d[0]), "+f"(d[1]), "+f"(d[2]), "+f"(d[3])
                 : "r"(a[0]), "r"(a[1]), "r"(a[2]), "r"(a[3]), "r"(b0), "r"(b1));
}

__device__ __forceinline__ uint32_t pack2bf(float a, float b) {
    __nv_bfloat162 t = __floats2bfloat162_rn(a, b);
    return *reinterpret_cast<uint32_t*>(&t);
}
__device__ __forceinline__ void split_pair(float a, float b, uint32_t& hp, uint32_t& lp) {
    float ah = __bfloat162float(__float2bfloat16(a));
    float bh = __bfloat162float(__float2bfloat16(b));
    hp = pack2bf(ah, bh);
    lp = pack2bf(a - ah, b - bh);
}
__device__ __forceinline__ void store4A(unsigned char* sm, int e, int col, float4 v) {
    uint32_t h0, l0, h1, l1;
    split_pair(v.x, v.y, h0, l0);
    split_pair(v.z, v.w, h1, l1);
    uint32_t off = (uint32_t)(e * LDA_B + col * 2);
    *(uint2*)(sm + A_HI + off) = make_uint2(h0, h1);
    *(uint2*)(sm + A_LO + off) = make_uint2(l0, l1);
}

// ============================================================================
// Phase A: sums of squares over the edge axis (radial 16 + dist 16)
// ============================================================================
__global__ void sumsq_kernel(const float* __restrict__ coord,
                             const int* __restrict__ row,
                             const int* __restrict__ col)
{
    __shared__ float s_sum[32];
    int tid = threadIdx.x;
    if (tid < 32) s_sum[tid] = 0.0f;
    __syncthreads();
    float p[32];
#pragma unroll
    for (int i = 0; i < 32; i++) p[i] = 0.0f;
    for (int e = blockIdx.x * blockDim.x + tid; e < N_EDGE; e += gridDim.x * blockDim.x) {
        const float* ci = coord + row[e] * 12;
        const float* cj = coord + col[e] * 12;
        float a[12], b[12], d[12];
#pragma unroll
        for (int i = 0; i < 12; i++) { a[i] = ci[i]; b[i] = cj[i]; d[i] = a[i] - b[i]; }
#pragma unroll
        for (int c = 0; c < 4; c++) {
#pragma unroll
            for (int f = 0; f < 4; f++) {
                float r = d[c*3+0]*d[f*3+0] + d[c*3+1]*d[f*3+1] + d[c*3+2]*d[f*3+2];
                float dx = a[c*3+0]-b[f*3+0], dy = a[c*3+1]-b[f*3+1], dz = a[c*3+2]-b[f*3+2];
                float d2 = dx*dx + dy*dy + dz*dz;
                p[c*8 + f]     += r * r;
                p[c*8 + 4 + f] += d2;
            }
        }
    }
#pragma unroll
    for (int i = 0; i < 32; i++) atomicAdd(&s_sum[i], p[i]);
    __syncthreads();
    if (tid < 32) atomicAdd(&g_sumsq[tid], s_sum[tid]);
}

// ============================================================================
// Weight prep: [K x 128] images, zero-padded K, bf16-split, row stride 272 B.
// ============================================================================
__global__ void prep_weights(const float* __restrict__ w1,
                             const float* __restrict__ w2,
                             const float* __restrict__ w3)
{
    int idx = blockIdx.x * blockDim.x + threadIdx.x;
    const float* W; unsigned char* dst; int half, r, K;
    if (idx < 40960)      { W = w1; dst = g_w1t; half = 320*LDB_B; r = idx;          K = 288; }
    else if (idx < 57344) { W = w2; dst = g_w2t; half = 128*LDB_B; r = idx - 40960;  K = 128; }
    else if (idx < 73728) { W = w3; dst = g_w3t; half = 128*LDB_B; r = idx - 57344;  K = 128; }
    else return;
    int kk = r >> 7, n = r & 127;
    float v = (kk < K) ? W[kk * 128 + n] : 0.0f;
    float vh = __bfloat162float(__float2bfloat16(v));
    __nv_bfloat16 hb = __float2bfloat16(vh);
    __nv_bfloat16 lb = __float2bfloat16(v - vh);
    *(__nv_bfloat16*)(dst + kk * LDB_B + n * 2) = hb;
    *(__nv_bfloat16*)(dst + half + kk * LDB_B + n * 2) = lb;
}

// ============================================================================
// warp-tiled split-bf16 GEMM with register-staged B prefetch.
// 8 warps in 2x4 grid: warp tile 32 rows x 32 cols. B chunk = 32 k-rows.
// ============================================================================
#define NSTG 5   // ceil(1088 / 256)

__device__ __forceinline__ void ld_stage(uint4 (&stg)[NSTG],
                                         const unsigned char* __restrict__ wsrc,
                                         int half_off, int c, int tid)
{
    const uint4* sh = (const uint4*)(wsrc + c * BCH_B);
    const uint4* sl = (const uint4*)(wsrc + half_off + c * BCH_B);
#pragma unroll
    for (int i = 0; i < NSTG; i++) {
        int idx = tid + i * ETHREADS;
        if (idx < 1088)
            stg[i] = (idx < 544) ? sh[idx] : sl[idx - 544];
    }
}

__device__ __forceinline__ void run_gemm_mma(
    unsigned char* sm, uint32_t smem_base, float (&acc)[2][4][4],
    int nchunks, int a_col_base, const unsigned char* __restrict__ wsrc, int half_off,
    int tid, int lane, int r0, int n0)
{
#pragma unroll
    for (int mt = 0; mt < 2; mt++)
#pragma unroll
        for (int nb = 0; nb < 4; nb++)
#pragma unroll
            for (int i = 0; i < 4; i++) acc[mt][nb][i] = 0.0f;

    uint4 stg[NSTG];
    ld_stage(stg, wsrc, half_off, 0, tid);

    for (int c = 0; c < nchunks; c++) {
        __syncthreads();                       // previous chunk's MMAs done with B
        {
            uint4* dh = (uint4*)(sm + B_HI);
            uint4* dl = (uint4*)(sm + B_LO);
#pragma unroll
            for (int i = 0; i < NSTG; i++) {
                int idx = tid + i * ETHREADS;
                if (idx < 1088) {
                    if (idx < 544) dh[idx] = stg[i];
                    else           dl[idx - 544] = stg[i];
                }
            }
        }
        __syncthreads();
        if (c + 1 < nchunks)                   // overlap next chunk's LDGs with MMA
            ld_stage(stg, wsrc, half_off, c + 1, tid);

#pragma unroll
        for (int ks = 0; ks < 2; ks++) {
            int kcol = a_col_base + c * 32 + ks * 16;
            uint32_t ah[2][4], al[2][4];
            uint32_t a_off = (uint32_t)((r0 + (lane & 15)) * LDA_B + (kcol + (lane >> 4) * 8) * 2);
            ldm_x4(ah[0], smem_base + A_HI + a_off);
            ldm_x4(al[0], smem_base + A_LO + a_off);
            ldm_x4(ah[1], smem_base + A_HI + a_off + 16 * LDA_B);
            ldm_x4(al[1], smem_base + A_LO + a_off + 16 * LDA_B);
            uint32_t bh[2][4], bl[2][4];
            uint32_t b_off = (uint32_t)((ks * 16 + (lane & 15)) * LDB_B + (n0 + (lane >> 4) * 8) * 2);
#pragma unroll
            for (int nt = 0; nt < 2; nt++) {
                ldm_x4_t(bh[nt], smem_base + B_HI + b_off + nt * 32);
                ldm_x4_t(bl[nt], smem_base + B_LO + b_off + nt * 32);
            }
#pragma unroll
            for (int mt = 0; mt < 2; mt++)
#pragma unroll
                for (int nt = 0; nt < 2; nt++) {
                    mma_bf16(acc[mt][2*nt],   ah[mt], bh[nt][0], bh[nt][1]);
                    mma_bf16(acc[mt][2*nt+1], ah[mt], bh[nt][2], bh[nt][3]);
                }
#pragma unroll
            for (int mt = 0; mt < 2; mt++)
#pragma unroll
                for (int nt = 0; nt < 2; nt++) {
                    mma_bf16(acc[mt][2*nt],   ah[mt], bl[nt][0], bl[nt][1]);
                    mma_bf16(acc[mt][2*nt+1], ah[mt], bl[nt][2], bl[nt][3]);
                }
#pragma unroll
            for (int mt = 0; mt < 2; mt++)
#pragma unroll
                for (int nt = 0; nt < 2; nt++) {
                    mma_bf16(acc[mt][2*nt],   al[mt], bh[nt][0], bh[nt][1]);
                    mma_bf16(acc[mt][2*nt+1], al[mt], bh[nt][2], bh[nt][3]);
                }
        }
    }
    __syncthreads();
}

// bias + silu + split-store to A cols [dstbase, dstbase+128); optional nagg red
__device__ __forceinline__ void epi_split_store(
    unsigned char* sm, float (&acc)[2][4][4], const float* __restrict__ SBIAS,
    int dstbase, int lane, int r0, int n0, const int* __restrict__ SROW, bool do_nagg)
{
#pragma unroll
    for (int mt = 0; mt < 2; mt++) {
        int ra = r0 + mt * 16 + (lane >> 2);
        int rb = ra + 8;
#pragma unroll
        for (int nb = 0; nb < 4; nb++) {
            int c = n0 + nb * 8 + (lane & 3) * 2;
            float b0 = SBIAS[c], b1 = SBIAS[c + 1];
            float v0 = silu_f(acc[mt][nb][0] + b0);
            float v1 = silu_f(acc[mt][nb][1] + b1);
            float v2 = silu_f(acc[mt][nb][2] + b0);
            float v3 = silu_f(acc[mt][nb][3] + b1);
            uint32_t h0, l0, h1, l1;
            split_pair(v0, v1, h0, l0);
            split_pair(v2, v3, h1, l1);
            uint32_t oa = (uint32_t)(ra * LDA_B + (dstbase + c) * 2);
            uint32_t ob = (uint32_t)(rb * LDA_B + (dstbase + c) * 2);
            *(uint32_t*)(sm + A_HI + oa) = h0;
            *(uint32_t*)(sm + A_LO + oa) = l0;
            *(uint32_t*)(sm + A_HI + ob) = h1;
            *(uint32_t*)(sm + A_LO + ob) = l1;
            if (do_nagg) {
                float* pa = g_nagg + (size_t)SROW[ra] * HID + c;
                float* pb = g_nagg + (size_t)SROW[rb] * HID + c;
                asm volatile("red.global.add.v2.f32 [%0], {%1,%2};"
                             :: "l"(pa), "f"(v0), "f"(v1) : "memory");
                asm volatile("red.global.add.v2.f32 [%0], {%1,%2};"
                             :: "l"(pb), "f"(v2), "f"(v3) : "memory");
            }
        }
    }
}

// ============================================================================
// Fused edge kernel: 64 edges / CTA, 256 threads, 8 warps in 2x4 grid,
// occupancy 2 CTAs/SM.
// ============================================================================
__global__ void __launch_bounds__(ETHREADS, 2)
edge_kernel(const float* __restrict__ h, const float* __restrict__ coord,
            const int* __restrict__ row, const int* __restrict__ col,
            const float* __restrict__ e_b1, const float* __restrict__ e_b2,
            const float* __restrict__ c_b1, const float* __restrict__ c_wout)
{
    extern __shared__ unsigned char sm[];
    const int tid  = threadIdx.x;
    const int wid  = tid >> 5;
    const int lane = tid & 31;
    const int e0   = blockIdx.x * ME;
    uint32_t smem_base = smem_to_u32(sm);

    int*   SROW  = (int*)(sm + OF_ROW);
    int*   SCOL  = (int*)(sm + OF_COL);
    float* SINV  = (float*)(sm + OF_INV);
    float* SBIAS = (float*)(sm + OF_BIAS);
    float* SCW   = (float*)(sm + OF_CW);
    float* SCD   = (float*)(sm + OF_CD);

    if (tid < ME)  { SROW[tid] = row[e0 + tid]; SCOL[tid] = col[e0 + tid]; }
    if (tid < 32)  SINV[tid] = 1.0f / fmaxf(sqrtf(g_sumsq[tid]), 1e-12f);
    if (tid < 128) ((float4*)SCW)[tid] = ((const float4*)c_wout)[tid];
    __syncthreads();

    // ---- gather h[row]|h[col] into A cols 0..255 (split bf16) ----
#pragma unroll 4
    for (int idx = tid; idx < ME * 64; idx += ETHREADS) {
        int e = idx >> 6, p4 = idx & 63;
        int half = p4 >> 5, q = p4 & 31;
        int node = half ? SCOL[e] : SROW[e];
        float4 v = ((const float4*)(h + node * HID))[q];
        store4A(sm, e, half * 128 + q * 4, v);
    }
    // ---- rad features cols 256..287, zeros 288..319; coord_diff to SCD ----
    if (tid < ME) {
        int e = tid;
        const float* ci = coord + SROW[e] * 12;
        const float* cj = coord + SCOL[e] * 12;
        float a[12], b[12], d[12];
#pragma unroll
        for (int i = 0; i < 12; i++) {
            a[i] = ci[i]; b[i] = cj[i]; d[i] = a[i] - b[i];
            SCD[e * 12 + i] = d[i];
        }
        float radv[32];
#pragma unroll
        for (int c = 0; c < 4; c++) {
#pragma unroll
            for (int f = 0; f < 4; f++) {
                float r = d[c*3+0]*d[f*3+0] + d[c*3+1]*d[f*3+1] + d[c*3+2]*d[f*3+2];
                float dx = a[c*3+0]-b[f*3+0], dy = a[c*3+1]-b[f*3+1], dz = a[c*3+2]-b[f*3+2];
                float d2 = dx*dx + dy*dy + dz*dz;
                radv[c*8 + f]     = r * SINV[c*8 + f];
                radv[c*8 + 4 + f] = sqrtf(d2) * SINV[c*8 + 4 + f];
            }
        }
#pragma unroll
        for (int q = 0; q < 64; q += 4) {
            float4 v = make_float4(q < 32 ? radv[q] : 0.f, q+1 < 32 ? radv[q+1] : 0.f,
                                   q+2 < 32 ? radv[q+2] : 0.f, q+3 < 32 ? radv[q+3] : 0.f);
            store4A(sm, e, 256 + q, v);
        }
    }

    const int wm = wid & 1, wn = wid >> 1;
    const int r0 = wm * 32, n0 = wn * 32;
    float acc[2][4][4];

    // ========== GEMM1: t1 = silu(eh @ W1 + b1) -> A cols 0..127 ==========
    if (tid < 128) SBIAS[tid] = e_b1[tid];
    run_gemm_mma(sm, smem_base, acc, 10, 0, g_w1t, 320 * LDB_B, tid, lane, r0, n0);
    epi_split_store(sm, acc, SBIAS, 0, lane, r0, n0, SROW, false);
    __syncthreads();

    // ========== GEMM2: m = silu(t1 @ W2 + b2) -> A cols 128..255, nagg ====
    if (tid < 128) SBIAS[tid] = e_b2[tid];
    __syncthreads();
    run_gemm_mma(sm, smem_base, acc, 4, 0, g_w2t, 128 * LDB_B, tid, lane, r0, n0);
    epi_split_store(sm, acc, SBIAS, 128, lane, r0, n0, SROW, true);
    __syncthreads();

    // ========== GEMM3: t2 = silu(m @ c_w1 + b) -> fp32 buffer =============
    if (tid < 128) SBIAS[tid] = c_b1[tid];
    __syncthreads();
    run_gemm_mma(sm, smem_base, acc, 4, 128, g_w3t, 128 * LDB_B, tid, lane, r0, n0);
    {
        float* t2f = (float*)(sm + A_LO);   // [64 x 132] fp32 (A_LO no longer needed)
#pragma unroll
        for (int mt = 0; mt < 2; mt++) {
            int ra = r0 + mt * 16 + (lane >> 2);
            int rb = ra + 8;
#pragma unroll
            for (int nb = 0; nb < 4; nb++) {
                int c = n0 + nb * 8 + (lane & 3) * 2;
                float b0 = SBIAS[c], b1 = SBIAS[c + 1];
                *(float2*)(t2f + ra * 132 + c) =
                    make_float2(silu_f(acc[mt][nb][0] + b0), silu_f(acc[mt][nb][1] + b1));
                *(float2*)(t2f + rb * 132 + c) =
                    make_float2(silu_f(acc[mt][nb][2] + b0), silu_f(acc[mt][nb][3] + b1));
            }
        }
    }
    __syncthreads();

    // ========== w = t2 @ c_wout; coord atomics =============================
    {
        int e = tid >> 2, c = tid & 3;
        const float* t2f = (const float*)(sm + A_LO);
        const float* tr = t2f + e * 132;
        float w = 0.0f;
#pragma unroll 8
        for (int k = 0; k < 128; k++) w += tr[k] * SCW[k * 4 + c];
        int node = SROW[e];
        const float* cd = SCD + e * 12 + c * 3;
        atomicAdd(&g_agg[node * 12 + c * 3 + 0], cd[0] * w);
        atomicAdd(&g_agg[node * 12 + c * 3 + 1], cd[1] * w);
        atomicAdd(&g_agg[node * 12 + c * 3 + 2], cd[2] * w);
        if (c == 0) atomicAdd(&g_cnt[node], 1.0f);
    }
}

// ============================================================================
// Node MLP + residual + coord epilogue (SIMT fp32)
// ============================================================================
template <int K>
__device__ __forceinline__ void gemm64(const float* __restrict__ A, int lda,
                                       const float* __restrict__ W,
                                       float* __restrict__ w_sm,
                                       float (&acc)[4][8], int tid)
{
    const int tx = tid & 15, ty = tid >> 4;
#pragma unroll
    for (int i = 0; i < 4; i++)
#pragma unroll
        for (int j = 0; j < 8; j++) acc[i][j] = 0.0f;
    const float* a0 = A + (ty * 4 + 0) * lda;
    const float* a1 = A + (ty * 4 + 1) * lda;
    const float* a2 = A + (ty * 4 + 2) * lda;
    const float* a3 = A + (ty * 4 + 3) * lda;
    for (int k0 = 0; k0 < K; k0 += KT) {
#pragma unroll
        for (int i = tid * 4; i < KT * 128; i += 256 * 4)
            *(float4*)(w_sm + i) = *(const float4*)(W + k0 * 128 + i);
        __syncthreads();
#pragma unroll 4
        for (int k = 0; k < KT; k++) {
            float b[8];
#pragma unroll
            for (int j = 0; j < 8; j++) b[j] = w_sm[k * 128 + tx + 16 * j];
            float v0 = a0[k0 + k], v1 = a1[k0 + k], v2 = a2[k0 + k], v3 = a3[k0 + k];
#pragma unroll
            for (int j = 0; j < 8; j++) {
                acc[0][j] += v0 * b[j];
                acc[1][j] += v1 * b[j];
                acc[2][j] += v2 * b[j];
                acc[3][j] += v3 * b[j];
            }
        }
        __syncthreads();
    }
}

#define NK_OFF_W   16640
#define NK_SMEM_FL 20736

__global__ void __launch_bounds__(256, 2)
node_kernel(const float* __restrict__ h, const float* __restrict__ coord,
            const float* __restrict__ n_w1, const float* __restrict__ n_b1,
            const float* __restrict__ n_w2, const float* __restrict__ n_b2,
            float* __restrict__ out_h, float* __restrict__ out_coord)
{
    extern __shared__ float smf[];
    float* nin  = smf;
    float* bufA = smf;
    float* w_sm = smf + NK_OFF_W;
    const int tid = threadIdx.x;
    const int n0  = blockIdx.x * TN;

#pragma unroll
    for (int idx = tid; idx < TN * 64; idx += 256) {
        int r = idx >> 6, q = idx & 63;
        int n = n0 + r;
        int qq = q & 31;
        float4 v = make_float4(0.f, 0.f, 0.f, 0.f);
        if (n < N_NODE)
            v = (q < 32) ? ((const float4*)(h + n * HID))[qq]
                         : *(const float4*)(g_nagg + n * HID + qq * 4);
        *(float4*)(nin + r * NIN_LD + ((q < 32) ? 0 : HID) + qq * 4) = v;
    }
    __syncthreads();

    float acc[4][8];
    gemm64<2 * HID>(nin, NIN_LD, n_w1, w_sm, acc, tid);
    {
        const int tx = tid & 15, ty = tid >> 4;
#pragma unroll
        for (int j = 0; j < 8; j++) {
            int c = tx + 16 * j;
            float bb = n_b1[c];
#pragma unroll
            for (int i = 0; i < 4; i++)
                bufA[(ty * 4 + i) * BUF_LD + c] = silu_f(acc[i][j] + bb);
        }
    }
    __syncthreads();
    gemm64<HID>(bufA, BUF_LD, n_w2, w_sm, acc, tid);

    {
        const int tx = tid & 15, ty = tid >> 4;
#pragma unroll
        for (int j = 0; j < 8; j++) {
            int c = tx + 16 * j;
            float bb = n_b2[c];
#pragma unroll
            for (int i = 0; i < 4; i++) {
                int n = n0 + ty * 4 + i;
                if (n < N_NODE)
                    out_h[n * HID + c] = acc[i][j] + bb + h[n * HID + c];
            }
        }
    }
    for (int idx = tid; idx < TN * 12; idx += 256) {
        int r = idx / 12, d = idx % 12;
        int n = n0 + r;
        if (n < N_NODE) {
            float cnt = fmaxf(g_cnt[n], 1.0f);
            out_coord[n * 12 + d] = coord[n * 12 + d] + g_agg[n * 12 + d] / cnt;
        }
    }
}

// ============================================================================
extern "C" void kernel_launch(void* const* d_in, const int* in_sizes, int n_in,
                              void* d_out, int out_size)
{
    const float* h      = (const float*)d_in[0];
    const float* coord  = (const float*)d_in[1];
    const int*   row    = (const int*)d_in[2];
    const int*   col    = (const int*)d_in[3];
    const float* e_w1   = (const float*)d_in[4];
    const float* e_b1   = (const float*)d_in[5];
    const float* e_w2   = (const float*)d_in[6];
    const float* e_b2   = (const float*)d_in[7];
    const float* c_w1   = (const float*)d_in[8];
    const float* c_b1   = (const float*)d_in[9];
    const float* c_wout = (const float*)d_in[10];
    const float* n_w1   = (const float*)d_in[11];
    const float* n_b1   = (const float*)d_in[12];
    const float* n_w2   = (const float*)d_in[13];
    const float* n_b2   = (const float*)d_in[14];

    float* out_h     = (float*)d_out;
    float* out_coord = out_h + N_NODE * HID;

    void *p_sumsq, *p_nagg, *p_agg, *p_cnt;
    cudaGetSymbolAddress(&p_sumsq, g_sumsq);
    cudaGetSymbolAddress(&p_nagg,  g_nagg);
    cudaGetSymbolAddress(&p_agg,   g_agg);
    cudaGetSymbolAddress(&p_cnt,   g_cnt);
    cudaMemsetAsync(p_sumsq, 0, 32 * sizeof(float));
    cudaMemsetAsync(p_nagg,  0, N_NODE * HID * sizeof(float));
    cudaMemsetAsync(p_agg,   0, N_NODE * 12 * sizeof(float));
    cudaMemsetAsync(p_cnt,   0, N_NODE * sizeof(float));

    cudaFuncSetAttribute(edge_kernel, cudaFuncAttributeMaxDynamicSharedMemorySize,
                         SMEM_EDGE_BYTES);
    cudaFuncSetAttribute(node_kernel, cudaFuncAttributeMaxDynamicSharedMemorySize,
                         NK_SMEM_FL * (int)sizeof(float));

    prep_weights<<<288, 256>>>(e_w1, e_w2, c_w1);
    sumsq_kernel<<<1184, 256>>>(coord, row, col);
    edge_kernel<<<N_EDGE / ME, ETHREADS, SMEM_EDGE_BYTES>>>(
        h, coord, row, col, e_b1, e_b2, c_b1, c_wout);
    node_kernel<<<(N_NODE + TN - 1) / TN, 256, NK_SMEM_FL * sizeof(float)>>>(
        h, coord, n_w1, n_b1, n_w2, n_b2, out_h, out_coord);
}

// round 6
// speedup vs baseline: 2.1200x; 1.1921x over previous
#include <cuda_runtime.h>
#include <cuda_fp16.h>
#include <math.h>
#include <stdint.h>

#define N_NODE 10000
#define N_EDGE 320000
#define HID    128
#define NC     4

// ---------------- SIMT helpers (node kernel) ----------------
#define TN     64
#define KT     32
#define BUF_LD 132
#define NIN_LD 260

// ---------------- edge kernel geometry ----------------
#define ME      64            // edges per CTA
#define ETHREADS 256
#define LDA_B   656           // A row stride bytes (328 fp16; K padded to 320)
#define LDB_B   272           // B row stride bytes (136 fp16)
#define BCH_B   17408         // one B chunk: 64 k-rows * 272 B (hi only)
#define A_HI    0
#define A_LO    41984         // 64*656
#define B_HI    83968         // 17408 B
#define OF_ROW  101376
#define OF_COL  101632
#define OF_INV  101888
#define OF_BIAS 102016
#define OF_CW   102528
#define OF_CD   104576
#define SMEM_EDGE_BYTES 107648

// ---------------- scratch ----------------
__device__ float g_sumsq[32];
__device__ float g_nagg[N_NODE * HID];
__device__ float g_agg[N_NODE * NC * 3];
__device__ float g_cnt[N_NODE];
// weight images: [K x 128] fp16 (single, rounded), row stride 272 B
__device__ __align__(16) unsigned char g_w1t[320 * LDB_B];
__device__ __align__(16) unsigned char g_w2t[128 * LDB_B];
__device__ __align__(16) unsigned char g_w3t[128 * LDB_B];

__device__ __forceinline__ float silu_f(float x) {
    return __fdividef(x, 1.0f + __expf(-x));
}

__device__ __forceinline__ uint32_t smem_to_u32(const void* p) {
    uint32_t a;
    asm("{ .reg .u64 t; cvta.to.shared.u64 t, %1; cvt.u32.u64 %0, t; }" : "=r"(a) : "l"(p));
    return a;
}
__device__ __forceinline__ void ldm_x4(uint32_t (&r)[4], uint32_t addr) {
    asm volatile("ldmatrix.sync.aligned.m8n8.x4.shared.b16 {%0,%1,%2,%3}, [%4];"
                 : "=r"(r[0]), "=r"(r[1]), "=r"(r[2]), "=r"(r[3]) : "r"(addr));
}
__device__ __forceinline__ void ldm_x4_t(uint32_t (&r)[4], uint32_t addr) {
    asm volatile("ldmatrix.sync.aligned.m8n8.x4.trans.shared.b16 {%0,%1,%2,%3}, [%4];"
                 : "=r"(r[0]), "=r"(r[1]), "=r"(r[2]), "=r"(r[3]) : "r"(addr));
}
__device__ __forceinline__ void mma_f16(float (&d)[4], const uint32_t (&a)[4],
                                        uint32_t b0, uint32_t b1) {
    asm volatile("mma.sync.aligned.m16n8k16.row.col.f32.f16.f16.f32 "
                 "{%0,%1,%2,%3}, {%4,%5,%6,%7}, {%8,%9}, {%0,%1,%2,%3};"
                 : "+f"(d[0]), "+f"(d[1]), "+f"(d[2]), "+f"(d[3])
                 : "r"(a[0]), "r"(a[1]), "r"(a[2]), "r"(a[3]), "r"(b0), "r"(b1));
}

__device__ __forceinline__ uint32_t pack2h(float a, float b) {
    __half2 t = __floats2half2_rn(a, b);
    return *reinterpret_cast<uint32_t*>(&t);
}
// fp16 split: hi = rn(x), lo = rn(x - float(hi))
__device__ __forceinline__ void split_pair(float a, float b, uint32_t& hp, uint32_t& lp) {
    __half ah = __float2half_rn(a);
    __half bh = __float2half_rn(b);
    float ar = __half2float(ah), br = __half2float(bh);
    __half2 hv = __halves2half2(ah, bh);
    hp = *reinterpret_cast<uint32_t*>(&hv);
    lp = pack2h(a - ar, b - br);
}
__device__ __forceinline__ void store4A(unsigned char* sm, int e, int col, float4 v) {
    uint32_t h0, l0, h1, l1;
    split_pair(v.x, v.y, h0, l0);
    split_pair(v.z, v.w, h1, l1);
    uint32_t off = (uint32_t)(e * LDA_B + col * 2);
    *(uint2*)(sm + A_HI + off) = make_uint2(h0, h1);
    *(uint2*)(sm + A_LO + off) = make_uint2(l0, l1);
}

// ============================================================================
// Phase A: sums of squares over the edge axis (radial 16 + dist 16)
// ============================================================================
__global__ void sumsq_kernel(const float* __restrict__ coord,
                             const int* __restrict__ row,
                             const int* __restrict__ col)
{
    __shared__ float s_sum[32];
    int tid = threadIdx.x;
    if (tid < 32) s_sum[tid] = 0.0f;
    __syncthreads();
    float p[32];
#pragma unroll
    for (int i = 0; i < 32; i++) p[i] = 0.0f;
    for (int e = blockIdx.x * blockDim.x + tid; e < N_EDGE; e += gridDim.x * blockDim.x) {
        const float* ci = coord + row[e] * 12;
        const float* cj = coord + col[e] * 12;
        float a[12], b[12], d[12];
#pragma unroll
        for (int i = 0; i < 12; i++) { a[i] = ci[i]; b[i] = cj[i]; d[i] = a[i] - b[i]; }
#pragma unroll
        for (int c = 0; c < 4; c++) {
#pragma unroll
            for (int f = 0; f < 4; f++) {
                float r = d[c*3+0]*d[f*3+0] + d[c*3+1]*d[f*3+1] + d[c*3+2]*d[f*3+2];
                float dx = a[c*3+0]-b[f*3+0], dy = a[c*3+1]-b[f*3+1], dz = a[c*3+2]-b[f*3+2];
                float d2 = dx*dx + dy*dy + dz*dz;
                p[c*8 + f]     += r * r;
                p[c*8 + 4 + f] += d2;
            }
        }
    }
#pragma unroll
    for (int i = 0; i < 32; i++) atomicAdd(&s_sum[i], p[i]);
    __syncthreads();
    if (tid < 32) atomicAdd(&g_sumsq[tid], s_sum[tid]);
}

// ============================================================================
// Weight prep: [K x 128] fp16 images, zero-padded K, row stride 272 B.
// ============================================================================
__global__ void prep_weights(const float* __restrict__ w1,
                             const float* __restrict__ w2,
                             const float* __restrict__ w3)
{
    int idx = blockIdx.x * blockDim.x + threadIdx.x;
    const float* W; unsigned char* dst; int r, K;
    if (idx < 40960)      { W = w1; dst = g_w1t; r = idx;          K = 288; }
    else if (idx < 57344) { W = w2; dst = g_w2t; r = idx - 40960;  K = 128; }
    else if (idx < 73728) { W = w3; dst = g_w3t; r = idx - 57344;  K = 128; }
    else return;
    int kk = r >> 7, n = r & 127;
    float v = (kk < K) ? W[kk * 128 + n] : 0.0f;
    *(__half*)(dst + kk * LDB_B + n * 2) = __float2half_rn(v);
}

// ============================================================================
// warp-tiled 2-term fp16 GEMM with register-staged B prefetch.
// 8 warps in 2x4 grid: warp tile 32 rows x 32 cols. B chunk = 64 k-rows.
// ============================================================================
#define NSTG 5   // ceil(1088 / 256)

__device__ __forceinline__ void ld_stage(uint4 (&stg)[NSTG],
                                         const unsigned char* __restrict__ wsrc,
                                         int c, int tid)
{
    const uint4* s = (const uint4*)(wsrc + c * BCH_B);
#pragma unroll
    for (int i = 0; i < NSTG; i++) {
        int idx = tid + i * ETHREADS;
        if (idx < 1088) stg[i] = s[idx];
    }
}

__device__ __forceinline__ void run_gemm_mma(
    unsigned char* sm, uint32_t smem_base, float (&acc)[2][4][4],
    int nchunks, int a_col_base, const unsigned char* __restrict__ wsrc,
    int tid, int lane, int r0, int n0)
{
#pragma unroll
    for (int mt = 0; mt < 2; mt++)
#pragma unroll
        for (int nb = 0; nb < 4; nb++)
#pragma unroll
            for (int i = 0; i < 4; i++) acc[mt][nb][i] = 0.0f;

    uint4 stg[NSTG];
    ld_stage(stg, wsrc, 0, tid);

    for (int c = 0; c < nchunks; c++) {
        __syncthreads();                       // previous chunk's MMAs done with B
        {
            uint4* db = (uint4*)(sm + B_HI);
#pragma unroll
            for (int i = 0; i < NSTG; i++) {
                int idx = tid + i * ETHREADS;
                if (idx < 1088) db[idx] = stg[i];
            }
        }
        __syncthreads();
        if (c + 1 < nchunks)                   // overlap next chunk's LDGs with MMA
            ld_stage(stg, wsrc, c + 1, tid);

#pragma unroll
        for (int ks = 0; ks < 4; ks++) {
            int kcol = a_col_base + c * 64 + ks * 16;
            uint32_t ah[2][4], al[2][4];
            uint32_t a_off = (uint32_t)((r0 + (lane & 15)) * LDA_B + (kcol + (lane >> 4) * 8) * 2);
            ldm_x4(ah[0], smem_base + A_HI + a_off);
            ldm_x4(al[0], smem_base + A_LO + a_off);
            ldm_x4(ah[1], smem_base + A_HI + a_off + 16 * LDA_B);
            ldm_x4(al[1], smem_base + A_LO + a_off + 16 * LDA_B);
            uint32_t bh[2][4];
            uint32_t b_off = (uint32_t)((ks * 16 + (lane & 15)) * LDB_B + (n0 + (lane >> 4) * 8) * 2);
#pragma unroll
            for (int nt = 0; nt < 2; nt++)
                ldm_x4_t(bh[nt], smem_base + B_HI + b_off + nt * 32);
            // term 1: hi * hi
#pragma unroll
            for (int mt = 0; mt < 2; mt++)
#pragma unroll
                for (int nt = 0; nt < 2; nt++) {
                    mma_f16(acc[mt][2*nt],   ah[mt], bh[nt][0], bh[nt][1]);
                    mma_f16(acc[mt][2*nt+1], ah[mt], bh[nt][2], bh[nt][3]);
                }
            // term 2: lo * hi  (corrects A's fp16 rounding)
#pragma unroll
            for (int mt = 0; mt < 2; mt++)
#pragma unroll
                for (int nt = 0; nt < 2; nt++) {
                    mma_f16(acc[mt][2*nt],   al[mt], bh[nt][0], bh[nt][1]);
                    mma_f16(acc[mt][2*nt+1], al[mt], bh[nt][2], bh[nt][3]);
                }
        }
    }
    __syncthreads();
}

// bias + silu + split-store to A cols [dstbase, dstbase+128); optional nagg red
__device__ __forceinline__ void epi_split_store(
    unsigned char* sm, float (&acc)[2][4][4], const float* __restrict__ SBIAS,
    int dstbase, int lane, int r0, int n0, const int* __restrict__ SROW, bool do_nagg)
{
#pragma unroll
    for (int mt = 0; mt < 2; mt++) {
        int ra = r0 + mt * 16 + (lane >> 2);
        int rb = ra + 8;
#pragma unroll
        for (int nb = 0; nb < 4; nb++) {
            int c = n0 + nb * 8 + (lane & 3) * 2;
            float b0 = SBIAS[c], b1 = SBIAS[c + 1];
            float v0 = silu_f(acc[mt][nb][0] + b0);
            float v1 = silu_f(acc[mt][nb][1] + b1);
            float v2 = silu_f(acc[mt][nb][2] + b0);
            float v3 = silu_f(acc[mt][nb][3] + b1);
            uint32_t h0, l0, h1, l1;
            split_pair(v0, v1, h0, l0);
            split_pair(v2, v3, h1, l1);
            uint32_t oa = (uint32_t)(ra * LDA_B + (dstbase + c) * 2);
            uint32_t ob = (uint32_t)(rb * LDA_B + (dstbase + c) * 2);
            *(uint32_t*)(sm + A_HI + oa) = h0;
            *(uint32_t*)(sm + A_LO + oa) = l0;
            *(uint32_t*)(sm + A_HI + ob) = h1;
            *(uint32_t*)(sm + A_LO + ob) = l1;
            if (do_nagg) {
                float* pa = g_nagg + (size_t)SROW[ra] * HID + c;
                float* pb = g_nagg + (size_t)SROW[rb] * HID + c;
                asm volatile("red.global.add.v2.f32 [%0], {%1,%2};"
                             :: "l"(pa), "f"(v0), "f"(v1) : "memory");
                asm volatile("red.global.add.v2.f32 [%0], {%1,%2};"
                             :: "l"(pb), "f"(v2), "f"(v3) : "memory");
            }
        }
    }
}

// ============================================================================
// Fused edge kernel: 64 edges / CTA, 256 threads, 8 warps in 2x4 grid,
// occupancy 2 CTAs/SM.
// ============================================================================
__global__ void __launch_bounds__(ETHREADS, 2)
edge_kernel(const float* __restrict__ h, const float* __restrict__ coord,
            const int* __restrict__ row, const int* __restrict__ col,
            const float* __restrict__ e_b1, const float* __restrict__ e_b2,
            const float* __restrict__ c_b1, const float* __restrict__ c_wout)
{
    extern __shared__ unsigned char sm[];
    const int tid  = threadIdx.x;
    const int wid  = tid >> 5;
    const int lane = tid & 31;
    const int e0   = blockIdx.x * ME;
    uint32_t smem_base = smem_to_u32(sm);

    int*   SROW  = (int*)(sm + OF_ROW);
    int*   SCOL  = (int*)(sm + OF_COL);
    float* SINV  = (float*)(sm + OF_INV);
    float* SBIAS = (float*)(sm + OF_BIAS);
    float* SCW   = (float*)(sm + OF_CW);
    float* SCD   = (float*)(sm + OF_CD);

    if (tid < ME)  { SROW[tid] = row[e0 + tid]; SCOL[tid] = col[e0 + tid]; }
    if (tid < 32)  SINV[tid] = 1.0f / fmaxf(sqrtf(g_sumsq[tid]), 1e-12f);
    if (tid < 128) ((float4*)SCW)[tid] = ((const float4*)c_wout)[tid];
    __syncthreads();

    // ---- gather h[row]|h[col] into A cols 0..255 (split fp16) ----
#pragma unroll 4
    for (int idx = tid; idx < ME * 64; idx += ETHREADS) {
        int e = idx >> 6, p4 = idx & 63;
        int half = p4 >> 5, q = p4 & 31;
        int node = half ? SCOL[e] : SROW[e];
        float4 v = ((const float4*)(h + node * HID))[q];
        store4A(sm, e, half * 128 + q * 4, v);
    }
    // ---- rad features cols 256..287, zeros 288..319; coord_diff to SCD ----
    if (tid < ME) {
        int e = tid;
        const float* ci = coord + SROW[e] * 12;
        const float* cj = coord + SCOL[e] * 12;
        float a[12], b[12], d[12];
#pragma unroll
        for (int i = 0; i < 12; i++) {
            a[i] = ci[i]; b[i] = cj[i]; d[i] = a[i] - b[i];
            SCD[e * 12 + i] = d[i];
        }
        float radv[32];
#pragma unroll
        for (int c = 0; c < 4; c++) {
#pragma unroll
            for (int f = 0; f < 4; f++) {
                float r = d[c*3+0]*d[f*3+0] + d[c*3+1]*d[f*3+1] + d[c*3+2]*d[f*3+2];
                float dx = a[c*3+0]-b[f*3+0], dy = a[c*3+1]-b[f*3+1], dz = a[c*3+2]-b[f*3+2];
                float d2 = dx*dx + dy*dy + dz*dz;
                radv[c*8 + f]     = r * SINV[c*8 + f];
                radv[c*8 + 4 + f] = sqrtf(d2) * SINV[c*8 + 4 + f];
            }
        }
#pragma unroll
        for (int q = 0; q < 64; q += 4) {
            float4 v = make_float4(q < 32 ? radv[q] : 0.f, q+1 < 32 ? radv[q+1] : 0.f,
                                   q+2 < 32 ? radv[q+2] : 0.f, q+3 < 32 ? radv[q+3] : 0.f);
            store4A(sm, e, 256 + q, v);
        }
    }

    const int wm = wid & 1, wn = wid >> 1;
    const int r0 = wm * 32, n0 = wn * 32;
    float acc[2][4][4];

    // ========== GEMM1: t1 = silu(eh @ W1 + b1) -> A cols 0..127 ==========
    if (tid < 128) SBIAS[tid] = e_b1[tid];
    run_gemm_mma(sm, smem_base, acc, 5, 0, g_w1t, tid, lane, r0, n0);
    epi_split_store(sm, acc, SBIAS, 0, lane, r0, n0, SROW, false);
    __syncthreads();

    // ========== GEMM2: m = silu(t1 @ W2 + b2) -> A cols 128..255, nagg ====
    if (tid < 128) SBIAS[tid] = e_b2[tid];
    __syncthreads();
    run_gemm_mma(sm, smem_base, acc, 2, 0, g_w2t, tid, lane, r0, n0);
    epi_split_store(sm, acc, SBIAS, 128, lane, r0, n0, SROW, true);
    __syncthreads();

    // ========== GEMM3: t2 = silu(m @ c_w1 + b) -> fp32 buffer =============
    if (tid < 128) SBIAS[tid] = c_b1[tid];
    __syncthreads();
    run_gemm_mma(sm, smem_base, acc, 2, 128, g_w3t, tid, lane, r0, n0);
    {
        float* t2f = (float*)(sm + A_LO);   // [64 x 132] fp32 (A_LO no longer needed)
#pragma unroll
        for (int mt = 0; mt < 2; mt++) {
            int ra = r0 + mt * 16 + (lane >> 2);
            int rb = ra + 8;
#pragma unroll
            for (int nb = 0; nb < 4; nb++) {
                int c = n0 + nb * 8 + (lane & 3) * 2;
                float b0 = SBIAS[c], b1 = SBIAS[c + 1];
                *(float2*)(t2f + ra * 132 + c) =
                    make_float2(silu_f(acc[mt][nb][0] + b0), silu_f(acc[mt][nb][1] + b1));
                *(float2*)(t2f + rb * 132 + c) =
                    make_float2(silu_f(acc[mt][nb][2] + b0), silu_f(acc[mt][nb][3] + b1));
            }
        }
    }
    __syncthreads();

    // ========== w = t2 @ c_wout; coord atomics =============================
    {
        int e = tid >> 2, c = tid & 3;
        const float* t2f = (const float*)(sm + A_LO);
        const float* tr = t2f + e * 132;
        float w = 0.0f;
#pragma unroll 8
        for (int k = 0; k < 128; k++) w += tr[k] * SCW[k * 4 + c];
        int node = SROW[e];
        const float* cd = SCD + e * 12 + c * 3;
        atomicAdd(&g_agg[node * 12 + c * 3 + 0], cd[0] * w);
        atomicAdd(&g_agg[node * 12 + c * 3 + 1], cd[1] * w);
        atomicAdd(&g_agg[node * 12 + c * 3 + 2], cd[2] * w);
        if (c == 0) atomicAdd(&g_cnt[node], 1.0f);
    }
}

// ============================================================================
// Node MLP + residual + coord epilogue (SIMT fp32)
// ============================================================================
template <int K>
__device__ __forceinline__ void gemm64(const float* __restrict__ A, int lda,
                                       const float* __restrict__ W,
                                       float* __restrict__ w_sm,
                                       float (&acc)[4][8], int tid)
{
    const int tx = tid & 15, ty = tid >> 4;
#pragma unroll
    for (int i = 0; i < 4; i++)
#pragma unroll
        for (int j = 0; j < 8; j++) acc[i][j] = 0.0f;
    const float* a0 = A + (ty * 4 + 0) * lda;
    const float* a1 = A + (ty * 4 + 1) * lda;
    const float* a2 = A + (ty * 4 + 2) * lda;
    const float* a3 = A + (ty * 4 + 3) * lda;
    for (int k0 = 0; k0 < K; k0 += KT) {
#pragma unroll
        for (int i = tid * 4; i < KT * 128; i += 256 * 4)
            *(float4*)(w_sm + i) = *(const float4*)(W + k0 * 128 + i);
        __syncthreads();
#pragma unroll 4
        for (int k = 0; k < KT; k++) {
            float b[8];
#pragma unroll
            for (int j = 0; j < 8; j++) b[j] = w_sm[k * 128 + tx + 16 * j];
            float v0 = a0[k0 + k], v1 = a1[k0 + k], v2 = a2[k0 + k], v3 = a3[k0 + k];
#pragma unroll
            for (int j = 0; j < 8; j++) {
                acc[0][j] += v0 * b[j];
                acc[1][j] += v1 * b[j];
                acc[2][j] += v2 * b[j];
                acc[3][j] += v3 * b[j];
            }
        }
        __syncthreads();
    }
}

#define NK_OFF_W   16640
#define NK_SMEM_FL 20736

__global__ void __launch_bounds__(256, 2)
node_kernel(const float* __restrict__ h, const float* __restrict__ coord,
            const float* __restrict__ n_w1, const float* __restrict__ n_b1,
            const float* __restrict__ n_w2, const float* __restrict__ n_b2,
            float* __restrict__ out_h, float* __restrict__ out_coord)
{
    extern __shared__ float smf[];
    float* nin  = smf;
    float* bufA = smf;
    float* w_sm = smf + NK_OFF_W;
    const int tid = threadIdx.x;
    const int n0  = blockIdx.x * TN;

#pragma unroll
    for (int idx = tid; idx < TN * 64; idx += 256) {
        int r = idx >> 6, q = idx & 63;
        int n = n0 + r;
        int qq = q & 31;
        float4 v = make_float4(0.f, 0.f, 0.f, 0.f);
        if (n < N_NODE)
            v = (q < 32) ? ((const float4*)(h + n * HID))[qq]
                         : *(const float4*)(g_nagg + n * HID + qq * 4);
        *(float4*)(nin + r * NIN_LD + ((q < 32) ? 0 : HID) + qq * 4) = v;
    }
    __syncthreads();

    float acc[4][8];
    gemm64<2 * HID>(nin, NIN_LD, n_w1, w_sm, acc, tid);
    {
        const int tx = tid & 15, ty = tid >> 4;
#pragma unroll
        for (int j = 0; j < 8; j++) {
            int c = tx + 16 * j;
            float bb = n_b1[c];
#pragma unroll
            for (int i = 0; i < 4; i++)
                bufA[(ty * 4 + i) * BUF_LD + c] = silu_f(acc[i][j] + bb);
        }
    }
    __syncthreads();
    gemm64<HID>(bufA, BUF_LD, n_w2, w_sm, acc, tid);

    {
        const int tx = tid & 15, ty = tid >> 4;
#pragma unroll
        for (int j = 0; j < 8; j++) {
            int c = tx + 16 * j;
            float bb = n_b2[c];
#pragma unroll
            for (int i = 0; i < 4; i++) {
                int n = n0 + ty * 4 + i;
                if (n < N_NODE)
                    out_h[n * HID + c] = acc[i][j] + bb + h[n * HID + c];
            }
        }
    }
    for (int idx = tid; idx < TN * 12; idx += 256) {
        int r = idx / 12, d = idx % 12;
        int n = n0 + r;
        if (n < N_NODE) {
            float cnt = fmaxf(g_cnt[n], 1.0f);
            out_coord[n * 12 + d] = coord[n * 12 + d] + g_agg[n * 12 + d] / cnt;
        }
    }
}

// ============================================================================
extern "C" void kernel_launch(void* const* d_in, const int* in_sizes, int n_in,
                              void* d_out, int out_size)
{
    const float* h      = (const float*)d_in[0];
    const float* coord  = (const float*)d_in[1];
    const int*   row    = (const int*)d_in[2];
    const int*   col    = (const int*)d_in[3];
    const float* e_w1   = (const float*)d_in[4];
    const float* e_b1   = (const float*)d_in[5];
    const float* e_w2   = (const float*)d_in[6];
    const float* e_b2   = (const float*)d_in[7];
    const float* c_w1   = (const float*)d_in[8];
    const float* c_b1   = (const float*)d_in[9];
    const float* c_wout = (const float*)d_in[10];
    const float* n_w1   = (const float*)d_in[11];
    const float* n_b1   = (const float*)d_in[12];
    const float* n_w2   = (const float*)d_in[13];
    const float* n_b2   = (const float*)d_in[14];

    float* out_h     = (float*)d_out;
    float* out_coord = out_h + N_NODE * HID;

    void *p_sumsq, *p_nagg, *p_agg, *p_cnt;
    cudaGetSymbolAddress(&p_sumsq, g_sumsq);
    cudaGetSymbolAddress(&p_nagg,  g_nagg);
    cudaGetSymbolAddress(&p_agg,   g_agg);
    cudaGetSymbolAddress(&p_cnt,   g_cnt);
    cudaMemsetAsync(p_sumsq, 0, 32 * sizeof(float));
    cudaMemsetAsync(p_nagg,  0, N_NODE * HID * sizeof(float));
    cudaMemsetAsync(p_agg,   0, N_NODE * 12 * sizeof(float));
    cudaMemsetAsync(p_cnt,   0, N_NODE * sizeof(float));

    cudaFuncSetAttribute(edge_kernel, cudaFuncAttributeMaxDynamicSharedMemorySize,
                         SMEM_EDGE_BYTES);
    cudaFuncSetAttribute(node_kernel, cudaFuncAttributeMaxDynamicSharedMemorySize,
                         NK_SMEM_FL * (int)sizeof(float));

    prep_weights<<<288, 256>>>(e_w1, e_w2, c_w1);
    sumsq_kernel<<<1184, 256>>>(coord, row, col);
    edge_kernel<<<N_EDGE / ME, ETHREADS, SMEM_EDGE_BYTES>>>(
        h, coord, row, col, e_b1, e_b2, c_b1, c_wout);
    node_kernel<<<(N_NODE + TN - 1) / TN, 256, NK_SMEM_FL * sizeof(float)>>>(
        h, coord, n_w1, n_b1, n_w2, n_b2, out_h, out_coord);
}

// round 7
// speedup vs baseline: 2.4632x; 1.1619x over previous
#include <cuda_runtime.h>
#include <cuda_fp16.h>
#include <math.h>
#include <stdint.h>

#define N_NODE 10000
#define N_EDGE 320000
#define HID    128
#define NC     4

// ---------------- SIMT helpers (node kernel) ----------------
#define TN     64
#define KT     32
#define BUF_LD 132
#define NIN_LD 260

// ---------------- edge kernel geometry ----------------
#define ME      64            // edges per CTA
#define ETHREADS 256
#define LDA_B   656           // A row stride bytes (328 fp16; K padded to 320)
#define LDB_B   272           // B row stride bytes (136 fp16)
#define BCH_B   17408         // one B chunk: 64 k-rows * 272 B
#define A_OFF   0             // single fp16 A image: 64*656 = 41984 B
#define B_OFF   41984
#define OF_ROW  59392
#define OF_COL  59648
#define OF_INV  59904
#define OF_BIAS 60032
#define OF_CW   60544
#define OF_CD   62592
#define SMEM_EDGE_BYTES 65664

// ---------------- scratch ----------------
__device__ float g_sumsq[32];
__device__ float g_nagg[N_NODE * HID];
__device__ float g_agg[N_NODE * NC * 3];
__device__ float g_cnt[N_NODE];
// weight images: [K x 128] fp16, row stride 272 B
__device__ __align__(16) unsigned char g_w1t[320 * LDB_B];
__device__ __align__(16) unsigned char g_w2t[128 * LDB_B];
__device__ __align__(16) unsigned char g_w3t[128 * LDB_B];

__device__ __forceinline__ float silu_f(float x) {
    return __fdividef(x, 1.0f + __expf(-x));
}

__device__ __forceinline__ uint32_t smem_to_u32(const void* p) {
    uint32_t a;
    asm("{ .reg .u64 t; cvta.to.shared.u64 t, %1; cvt.u32.u64 %0, t; }" : "=r"(a) : "l"(p));
    return a;
}
__device__ __forceinline__ void ldm_x4(uint32_t (&r)[4], uint32_t addr) {
    asm volatile("ldmatrix.sync.aligned.m8n8.x4.shared.b16 {%0,%1,%2,%3}, [%4];"
                 : "=r"(r[0]), "=r"(r[1]), "=r"(r[2]), "=r"(r[3]) : "r"(addr));
}
__device__ __forceinline__ void ldm_x4_t(uint32_t (&r)[4], uint32_t addr) {
    asm volatile("ldmatrix.sync.aligned.m8n8.x4.trans.shared.b16 {%0,%1,%2,%3}, [%4];"
                 : "=r"(r[0]), "=r"(r[1]), "=r"(r[2]), "=r"(r[3]) : "r"(addr));
}
__device__ __forceinline__ void mma_f16(float (&d)[4], const uint32_t (&a)[4],
                                        uint32_t b0, uint32_t b1) {
    asm volatile("mma.sync.aligned.m16n8k16.row.col.f32.f16.f16.f32 "
                 "{%0,%1,%2,%3}, {%4,%5,%6,%7}, {%8,%9}, {%0,%1,%2,%3};"
                 : "+f"(d[0]), "+f"(d[1]), "+f"(d[2]), "+f"(d[3])
                 : "r"(a[0]), "r"(a[1]), "r"(a[2]), "r"(a[3]), "r"(b0), "r"(b1));
}

__device__ __forceinline__ uint32_t pack2h(float a, float b) {
    __half2 t = __floats2half2_rn(a, b);
    return *reinterpret_cast<uint32_t*>(&t);
}
// store 4 consecutive fp32 (col % 4 == 0) as fp16 into A, row e
__device__ __forceinline__ void store4A(unsigned char* sm, int e, int col, float4 v) {
    uint32_t off = (uint32_t)(e * LDA_B + col * 2);
    *(uint2*)(sm + A_OFF + off) = make_uint2(pack2h(v.x, v.y), pack2h(v.z, v.w));
}

// ============================================================================
// Phase A: sums of squares over the edge axis (radial 16 + dist 16)
// ============================================================================
__global__ void sumsq_kernel(const float* __restrict__ coord,
                             const int* __restrict__ row,
                             const int* __restrict__ col)
{
    __shared__ float s_sum[32];
    int tid = threadIdx.x;
    if (tid < 32) s_sum[tid] = 0.0f;
    __syncthreads();
    float p[32];
#pragma unroll
    for (int i = 0; i < 32; i++) p[i] = 0.0f;
    for (int e = blockIdx.x * blockDim.x + tid; e < N_EDGE; e += gridDim.x * blockDim.x) {
        const float* ci = coord + row[e] * 12;
        const float* cj = coord + col[e] * 12;
        float a[12], b[12], d[12];
#pragma unroll
        for (int i = 0; i < 12; i++) { a[i] = ci[i]; b[i] = cj[i]; d[i] = a[i] - b[i]; }
#pragma unroll
        for (int c = 0; c < 4; c++) {
#pragma unroll
            for (int f = 0; f < 4; f++) {
                float r = d[c*3+0]*d[f*3+0] + d[c*3+1]*d[f*3+1] + d[c*3+2]*d[f*3+2];
                float dx = a[c*3+0]-b[f*3+0], dy = a[c*3+1]-b[f*3+1], dz = a[c*3+2]-b[f*3+2];
                float d2 = dx*dx + dy*dy + dz*dz;
                p[c*8 + f]     += r * r;
                p[c*8 + 4 + f] += d2;
            }
        }
    }
#pragma unroll
    for (int i = 0; i < 32; i++) atomicAdd(&s_sum[i], p[i]);
    __syncthreads();
    if (tid < 32) atomicAdd(&g_sumsq[tid], s_sum[tid]);
}

// ============================================================================
// Weight prep: [K x 128] fp16 images, zero-padded K, row stride 272 B.
// ============================================================================
__global__ void prep_weights(const float* __restrict__ w1,
                             const float* __restrict__ w2,
                             const float* __restrict__ w3)
{
    int idx = blockIdx.x * blockDim.x + threadIdx.x;
    const float* W; unsigned char* dst; int r, K;
    if (idx < 40960)      { W = w1; dst = g_w1t; r = idx;          K = 288; }
    else if (idx < 57344) { W = w2; dst = g_w2t; r = idx - 40960;  K = 128; }
    else if (idx < 73728) { W = w3; dst = g_w3t; r = idx - 57344;  K = 128; }
    else return;
    int kk = r >> 7, n = r & 127;
    float v = (kk < K) ? W[kk * 128 + n] : 0.0f;
    *(__half*)(dst + kk * LDB_B + n * 2) = __float2half_rn(v);
}

// ============================================================================
// warp-tiled fp16 GEMM with register-staged B prefetch.
// 8 warps in 2x4 grid: warp tile 32 rows x 32 cols. B chunk = 64 k-rows.
// ============================================================================
#define NSTG 5   // ceil(1088 / 256)

__device__ __forceinline__ void ld_stage(uint4 (&stg)[NSTG],
                                         const unsigned char* __restrict__ wsrc,
                                         int c, int tid)
{
    const uint4* s = (const uint4*)(wsrc + c * BCH_B);
#pragma unroll
    for (int i = 0; i < NSTG; i++) {
        int idx = tid + i * ETHREADS;
        if (idx < 1088) stg[i] = s[idx];
    }
}

__device__ __forceinline__ void run_gemm_mma(
    unsigned char* sm, uint32_t smem_base, float (&acc)[2][4][4],
    int nchunks, int a_col_base, const unsigned char* __restrict__ wsrc,
    int tid, int lane, int r0, int n0)
{
#pragma unroll
    for (int mt = 0; mt < 2; mt++)
#pragma unroll
        for (int nb = 0; nb < 4; nb++)
#pragma unroll
            for (int i = 0; i < 4; i++) acc[mt][nb][i] = 0.0f;

    uint4 stg[NSTG];
    ld_stage(stg, wsrc, 0, tid);

    for (int c = 0; c < nchunks; c++) {
        __syncthreads();                       // previous chunk's MMAs done with B
        {
            uint4* db = (uint4*)(sm + B_OFF);
#pragma unroll
            for (int i = 0; i < NSTG; i++) {
                int idx = tid + i * ETHREADS;
                if (idx < 1088) db[idx] = stg[i];
            }
        }
        __syncthreads();
        if (c + 1 < nchunks)                   // overlap next chunk's LDGs with MMA
            ld_stage(stg, wsrc, c + 1, tid);

#pragma unroll
        for (int ks = 0; ks < 4; ks++) {
            int kcol = a_col_base + c * 64 + ks * 16;
            uint32_t ah[2][4];
            uint32_t a_off = (uint32_t)((r0 + (lane & 15)) * LDA_B + (kcol + (lane >> 4) * 8) * 2);
            ldm_x4(ah[0], smem_base + A_OFF + a_off);
            ldm_x4(ah[1], smem_base + A_OFF + a_off + 16 * LDA_B);
            uint32_t bh[2][4];
            uint32_t b_off = (uint32_t)((ks * 16 + (lane & 15)) * LDB_B + (n0 + (lane >> 4) * 8) * 2);
#pragma unroll
            for (int nt = 0; nt < 2; nt++)
                ldm_x4_t(bh[nt], smem_base + B_OFF + b_off + nt * 32);
#pragma unroll
            for (int mt = 0; mt < 2; mt++)
#pragma unroll
                for (int nt = 0; nt < 2; nt++) {
                    mma_f16(acc[mt][2*nt],   ah[mt], bh[nt][0], bh[nt][1]);
                    mma_f16(acc[mt][2*nt+1], ah[mt], bh[nt][2], bh[nt][3]);
                }
        }
    }
    __syncthreads();
}

// bias + silu + fp16-store to A cols [dstbase, dstbase+128); optional nagg red
__device__ __forceinline__ void epi_store(
    unsigned char* sm, float (&acc)[2][4][4], const float* __restrict__ SBIAS,
    int dstbase, int lane, int r0, int n0, const int* __restrict__ SROW, bool do_nagg)
{
#pragma unroll
    for (int mt = 0; mt < 2; mt++) {
        int ra = r0 + mt * 16 + (lane >> 2);
        int rb = ra + 8;
#pragma unroll
        for (int nb = 0; nb < 4; nb++) {
            int c = n0 + nb * 8 + (lane & 3) * 2;
            float b0 = SBIAS[c], b1 = SBIAS[c + 1];
            float v0 = silu_f(acc[mt][nb][0] + b0);
            float v1 = silu_f(acc[mt][nb][1] + b1);
            float v2 = silu_f(acc[mt][nb][2] + b0);
            float v3 = silu_f(acc[mt][nb][3] + b1);
            uint32_t oa = (uint32_t)(ra * LDA_B + (dstbase + c) * 2);
            uint32_t ob = (uint32_t)(rb * LDA_B + (dstbase + c) * 2);
            *(uint32_t*)(sm + A_OFF + oa) = pack2h(v0, v1);
            *(uint32_t*)(sm + A_OFF + ob) = pack2h(v2, v3);
            if (do_nagg) {
                float* pa = g_nagg + (size_t)SROW[ra] * HID + c;
                float* pb = g_nagg + (size_t)SROW[rb] * HID + c;
                asm volatile("red.global.add.v2.f32 [%0], {%1,%2};"
                             :: "l"(pa), "f"(v0), "f"(v1) : "memory");
                asm volatile("red.global.add.v2.f32 [%0], {%1,%2};"
                             :: "l"(pb), "f"(v2), "f"(v3) : "memory");
            }
        }
    }
}

// ============================================================================
// Fused edge kernel: 64 edges / CTA, 256 threads, 8 warps in 2x4 grid,
// occupancy 3 CTAs/SM.
// ============================================================================
__global__ void __launch_bounds__(ETHREADS, 3)
edge_kernel(const float* __restrict__ h, const float* __restrict__ coord,
            const int* __restrict__ row, const int* __restrict__ col,
            const float* __restrict__ e_b1, const float* __restrict__ e_b2,
            const float* __restrict__ c_b1, const float* __restrict__ c_wout)
{
    extern __shared__ unsigned char sm[];
    const int tid  = threadIdx.x;
    const int wid  = tid >> 5;
    const int lane = tid & 31;
    const int e0   = blockIdx.x * ME;
    uint32_t smem_base = smem_to_u32(sm);

    int*   SROW  = (int*)(sm + OF_ROW);
    int*   SCOL  = (int*)(sm + OF_COL);
    float* SINV  = (float*)(sm + OF_INV);
    float* SBIAS = (float*)(sm + OF_BIAS);
    float* SCW   = (float*)(sm + OF_CW);
    float* SCD   = (float*)(sm + OF_CD);

    if (tid < ME)  { SROW[tid] = row[e0 + tid]; SCOL[tid] = col[e0 + tid]; }
    if (tid < 32)  SINV[tid] = 1.0f / fmaxf(sqrtf(g_sumsq[tid]), 1e-12f);
    if (tid < 128) ((float4*)SCW)[tid] = ((const float4*)c_wout)[tid];
    __syncthreads();

    // ---- gather h[row]|h[col] into A cols 0..255 (fp16) ----
#pragma unroll 4
    for (int idx = tid; idx < ME * 64; idx += ETHREADS) {
        int e = idx >> 6, p4 = idx & 63;
        int half = p4 >> 5, q = p4 & 31;
        int node = half ? SCOL[e] : SROW[e];
        float4 v = ((const float4*)(h + node * HID))[q];
        store4A(sm, e, half * 128 + q * 4, v);
    }
    // ---- rad features cols 256..287, zeros 288..319; coord_diff to SCD ----
    if (tid < ME) {
        int e = tid;
        const float* ci = coord + SROW[e] * 12;
        const float* cj = coord + SCOL[e] * 12;
        float a[12], b[12], d[12];
#pragma unroll
        for (int i = 0; i < 12; i++) {
            a[i] = ci[i]; b[i] = cj[i]; d[i] = a[i] - b[i];
            SCD[e * 12 + i] = d[i];
        }
        float radv[32];
#pragma unroll
        for (int c = 0; c < 4; c++) {
#pragma unroll
            for (int f = 0; f < 4; f++) {
                float r = d[c*3+0]*d[f*3+0] + d[c*3+1]*d[f*3+1] + d[c*3+2]*d[f*3+2];
                float dx = a[c*3+0]-b[f*3+0], dy = a[c*3+1]-b[f*3+1], dz = a[c*3+2]-b[f*3+2];
                float d2 = dx*dx + dy*dy + dz*dz;
                radv[c*8 + f]     = r * SINV[c*8 + f];
                radv[c*8 + 4 + f] = sqrtf(d2) * SINV[c*8 + 4 + f];
            }
        }
#pragma unroll
        for (int q = 0; q < 64; q += 4) {
            float4 v = make_float4(q < 32 ? radv[q] : 0.f, q+1 < 32 ? radv[q+1] : 0.f,
                                   q+2 < 32 ? radv[q+2] : 0.f, q+3 < 32 ? radv[q+3] : 0.f);
            store4A(sm, e, 256 + q, v);
        }
    }

    const int wm = wid & 1, wn = wid >> 1;
    const int r0 = wm * 32, n0 = wn * 32;
    float acc[2][4][4];

    // ========== GEMM1: t1 = silu(eh @ W1 + b1) -> A cols 0..127 ==========
    if (tid < 128) SBIAS[tid] = e_b1[tid];
    run_gemm_mma(sm, smem_base, acc, 5, 0, g_w1t, tid, lane, r0, n0);
    epi_store(sm, acc, SBIAS, 0, lane, r0, n0, SROW, false);
    __syncthreads();

    // ========== GEMM2: m = silu(t1 @ W2 + b2) -> A cols 128..255, nagg ====
    if (tid < 128) SBIAS[tid] = e_b2[tid];
    __syncthreads();
    run_gemm_mma(sm, smem_base, acc, 2, 0, g_w2t, tid, lane, r0, n0);
    epi_store(sm, acc, SBIAS, 128, lane, r0, n0, SROW, true);
    __syncthreads();

    // ========== GEMM3: t2 = silu(m @ c_w1 + b) -> fp32 buffer =============
    if (tid < 128) SBIAS[tid] = c_b1[tid];
    __syncthreads();
    run_gemm_mma(sm, smem_base, acc, 2, 128, g_w3t, tid, lane, r0, n0);
    {
        float* t2f = (float*)(sm + A_OFF);  // [64 x 132] fp32; A done after GEMM3
#pragma unroll
        for (int mt = 0; mt < 2; mt++) {
            int ra = r0 + mt * 16 + (lane >> 2);
            int rb = ra + 8;
#pragma unroll
            for (int nb = 0; nb < 4; nb++) {
                int c = n0 + nb * 8 + (lane & 3) * 2;
                float b0 = SBIAS[c], b1 = SBIAS[c + 1];
                *(float2*)(t2f + ra * 132 + c) =
                    make_float2(silu_f(acc[mt][nb][0] + b0), silu_f(acc[mt][nb][1] + b1));
                *(float2*)(t2f + rb * 132 + c) =
                    make_float2(silu_f(acc[mt][nb][2] + b0), silu_f(acc[mt][nb][3] + b1));
            }
        }
    }
    __syncthreads();

    // ========== w = t2 @ c_wout; coord atomics =============================
    {
        int e = tid >> 2, c = tid & 3;
        const float* t2f = (const float*)(sm + A_OFF);
        const float* tr = t2f + e * 132;
        float w = 0.0f;
#pragma unroll 8
        for (int k = 0; k < 128; k++) w += tr[k] * SCW[k * 4 + c];
        int node = SROW[e];
        const float* cd = SCD + e * 12 + c * 3;
        atomicAdd(&g_agg[node * 12 + c * 3 + 0], cd[0] * w);
        atomicAdd(&g_agg[node * 12 + c * 3 + 1], cd[1] * w);
        atomicAdd(&g_agg[node * 12 + c * 3 + 2], cd[2] * w);
        if (c == 0) atomicAdd(&g_cnt[node], 1.0f);
    }
}

// ============================================================================
// Node MLP + residual + coord epilogue (SIMT fp32)
// ============================================================================
template <int K>
__device__ __forceinline__ void gemm64(const float* __restrict__ A, int lda,
                                       const float* __restrict__ W,
                                       float* __restrict__ w_sm,
                                       float (&acc)[4][8], int tid)
{
    const int tx = tid & 15, ty = tid >> 4;
#pragma unroll
    for (int i = 0; i < 4; i++)
#pragma unroll
        for (int j = 0; j < 8; j++) acc[i][j] = 0.0f;
    const float* a0 = A + (ty * 4 + 0) * lda;
    const float* a1 = A + (ty * 4 + 1) * lda;
    const float* a2 = A + (ty * 4 + 2) * lda;
    const float* a3 = A + (ty * 4 + 3) * lda;
    for (int k0 = 0; k0 < K; k0 += KT) {
#pragma unroll
        for (int i = tid * 4; i < KT * 128; i += 256 * 4)
            *(float4*)(w_sm + i) = *(const float4*)(W + k0 * 128 + i);
        __syncthreads();
#pragma unroll 4
        for (int k = 0; k < KT; k++) {
            float b[8];
#pragma unroll
            for (int j = 0; j < 8; j++) b[j] = w_sm[k * 128 + tx + 16 * j];
            float v0 = a0[k0 + k], v1 = a1[k0 + k], v2 = a2[k0 + k], v3 = a3[k0 + k];
#pragma unroll
            for (int j = 0; j < 8; j++) {
                acc[0][j] += v0 * b[j];
                acc[1][j] += v1 * b[j];
                acc[2][j] += v2 * b[j];
                acc[3][j] += v3 * b[j];
            }
        }
        __syncthreads();
    }
}

#define NK_OFF_W   16640
#define NK_SMEM_FL 20736

__global__ void __launch_bounds__(256, 2)
node_kernel(const float* __restrict__ h, const float* __restrict__ coord,
            const float* __restrict__ n_w1, const float* __restrict__ n_b1,
            const float* __restrict__ n_w2, const float* __restrict__ n_b2,
            float* __restrict__ out_h, float* __restrict__ out_coord)
{
    extern __shared__ float smf[];
    float* nin  = smf;
    float* bufA = smf;
    float* w_sm = smf + NK_OFF_W;
    const int tid = threadIdx.x;
    const int n0  = blockIdx.x * TN;

#pragma unroll
    for (int idx = tid; idx < TN * 64; idx += 256) {
        int r = idx >> 6, q = idx & 63;
        int n = n0 + r;
        int qq = q & 31;
        float4 v = make_float4(0.f, 0.f, 0.f, 0.f);
        if (n < N_NODE)
            v = (q < 32) ? ((const float4*)(h + n * HID))[qq]
                         : *(const float4*)(g_nagg + n * HID + qq * 4);
        *(float4*)(nin + r * NIN_LD + ((q < 32) ? 0 : HID) + qq * 4) = v;
    }
    __syncthreads();

    float acc[4][8];
    gemm64<2 * HID>(nin, NIN_LD, n_w1, w_sm, acc, tid);
    {
        const int tx = tid & 15, ty = tid >> 4;
#pragma unroll
        for (int j = 0; j < 8; j++) {
            int c = tx + 16 * j;
            float bb = n_b1[c];
#pragma unroll
            for (int i = 0; i < 4; i++)
                bufA[(ty * 4 + i) * BUF_LD + c] = silu_f(acc[i][j] + bb);
        }
    }
    __syncthreads();
    gemm64<HID>(bufA, BUF_LD, n_w2, w_sm, acc, tid);

    {
        const int tx = tid & 15, ty = tid >> 4;
#pragma unroll
        for (int j = 0; j < 8; j++) {
            int c = tx + 16 * j;
            float bb = n_b2[c];
#pragma unroll
            for (int i = 0; i < 4; i++) {
                int n = n0 + ty * 4 + i;
                if (n < N_NODE)
                    out_h[n * HID + c] = acc[i][j] + bb + h[n * HID + c];
            }
        }
    }
    for (int idx = tid; idx < TN * 12; idx += 256) {
        int r = idx / 12, d = idx % 12;
        int n = n0 + r;
        if (n < N_NODE) {
            float cnt = fmaxf(g_cnt[n], 1.0f);
            out_coord[n * 12 + d] = coord[n * 12 + d] + g_agg[n * 12 + d] / cnt;
        }
    }
}

// ============================================================================
extern "C" void kernel_launch(void* const* d_in, const int* in_sizes, int n_in,
                              void* d_out, int out_size)
{
    const float* h      = (const float*)d_in[0];
    const float* coord  = (const float*)d_in[1];
    const int*   row    = (const int*)d_in[2];
    const int*   col    = (const int*)d_in[3];
    const float* e_w1   = (const float*)d_in[4];
    const float* e_b1   = (const float*)d_in[5];
    const float* e_w2   = (const float*)d_in[6];
    const float* e_b2   = (const float*)d_in[7];
    const float* c_w1   = (const float*)d_in[8];
    const float* c_b1   = (const float*)d_in[9];
    const float* c_wout = (const float*)d_in[10];
    const float* n_w1   = (const float*)d_in[11];
    const float* n_b1   = (const float*)d_in[12];
    const float* n_w2   = (const float*)d_in[13];
    const float* n_b2   = (const float*)d_in[14];

    float* out_h     = (float*)d_out;
    float* out_coord = out_h + N_NODE * HID;

    void *p_sumsq, *p_nagg, *p_agg, *p_cnt;
    cudaGetSymbolAddress(&p_sumsq, g_sumsq);
    cudaGetSymbolAddress(&p_nagg,  g_nagg);
    cudaGetSymbolAddress(&p_agg,   g_agg);
    cudaGetSymbolAddress(&p_cnt,   g_cnt);
    cudaMemsetAsync(p_sumsq, 0, 32 * sizeof(float));
    cudaMemsetAsync(p_nagg,  0, N_NODE * HID * sizeof(float));
    cudaMemsetAsync(p_agg,   0, N_NODE * 12 * sizeof(float));
    cudaMemsetAsync(p_cnt,   0, N_NODE * sizeof(float));

    cudaFuncSetAttribute(edge_kernel, cudaFuncAttributeMaxDynamicSharedMemorySize,
                         SMEM_EDGE_BYTES);
    cudaFuncSetAttribute(node_kernel, cudaFuncAttributeMaxDynamicSharedMemorySize,
                         NK_SMEM_FL * (int)sizeof(float));

    prep_weights<<<288, 256>>>(e_w1, e_w2, c_w1);
    sumsq_kernel<<<1184, 256>>>(coord, row, col);
    edge_kernel<<<N_EDGE / ME, ETHREADS, SMEM_EDGE_BYTES>>>(
        h, coord, row, col, e_b1, e_b2, c_b1, c_wout);
    node_kernel<<<(N_NODE + TN - 1) / TN, 256, NK_SMEM_FL * sizeof(float)>>>(
        h, coord, n_w1, n_b1, n_w2, n_b2, out_h, out_coord);
}

// round 8
// speedup vs baseline: 2.5230x; 1.0243x over previous
#include <cuda_runtime.h>
#include <cuda_fp16.h>
#include <math.h>
#include <stdint.h>

#define N_NODE 10000
#define N_EDGE 320000
#define HID    128
#define NC     4

// ---------------- SIMT helpers (node kernel) ----------------
#define TN     32
#define KT     32
#define BUF_LD 132
#define NIN_LD 260

// ---------------- edge kernel geometry ----------------
#define ME      64            // edges per CTA
#define ETHREADS 256
#define LDA_B   656           // A row stride bytes (328 fp16 capacity; K=288 used)
#define LDB_B   272           // B row stride bytes (136 fp16)
#define A_OFF   0             // fp16 A image: 64*656 = 41984 B
#define B_OFF   41984         // B chunk: up to 64 k-rows * 272 B = 17408
#define OF_ROW  59392
#define OF_COL  59648
#define OF_INV  59904
#define OF_BIAS 60032
#define OF_CW   60544         // transposed c_wout: 4 x 136 fp32 = 2176 B
#define OF_CD   62720         // coord_diff: 64*12*4 = 3072 B
#define SMEM_EDGE_BYTES 65792

// ---------------- scratch ----------------
__device__ float g_sumsq[32];
__device__ float g_nagg[N_NODE * HID];
__device__ float g_agg[N_NODE * NC * 3];
__device__ float g_cnt[N_NODE];
// weight images: [K x 128] fp16, row stride 272 B
__device__ __align__(16) unsigned char g_w1t[288 * LDB_B];
__device__ __align__(16) unsigned char g_w2t[128 * LDB_B];
__device__ __align__(16) unsigned char g_w3t[128 * LDB_B];

__device__ __forceinline__ float silu_f(float x) {
    return __fdividef(x, 1.0f + __expf(-x));
}

__device__ __forceinline__ uint32_t smem_to_u32(const void* p) {
    uint32_t a;
    asm("{ .reg .u64 t; cvta.to.shared.u64 t, %1; cvt.u32.u64 %0, t; }" : "=r"(a) : "l"(p));
    return a;
}
__device__ __forceinline__ void ldm_x4(uint32_t (&r)[4], uint32_t addr) {
    asm volatile("ldmatrix.sync.aligned.m8n8.x4.shared.b16 {%0,%1,%2,%3}, [%4];"
                 : "=r"(r[0]), "=r"(r[1]), "=r"(r[2]), "=r"(r[3]) : "r"(addr));
}
__device__ __forceinline__ void ldm_x4_t(uint32_t (&r)[4], uint32_t addr) {
    asm volatile("ldmatrix.sync.aligned.m8n8.x4.trans.shared.b16 {%0,%1,%2,%3}, [%4];"
                 : "=r"(r[0]), "=r"(r[1]), "=r"(r[2]), "=r"(r[3]) : "r"(addr));
}
__device__ __forceinline__ void mma_f16(float (&d)[4], const uint32_t (&a)[4],
                                        uint32_t b0, uint32_t b1) {
    asm volatile("mma.sync.aligned.m16n8k16.row.col.f32.f16.f16.f32 "
                 "{%0,%1,%2,%3}, {%4,%5,%6,%7}, {%8,%9}, {%0,%1,%2,%3};"
                 : "+f"(d[0]), "+f"(d[1]), "+f"(d[2]), "+f"(d[3])
                 : "r"(a[0]), "r"(a[1]), "r"(a[2]), "r"(a[3]), "r"(b0), "r"(b1));
}

__device__ __forceinline__ uint32_t pack2h(float a, float b) {
    __half2 t = __floats2half2_rn(a, b);
    return *reinterpret_cast<uint32_t*>(&t);
}
__device__ __forceinline__ void store4A(unsigned char* sm, int e, int col, float4 v) {
    uint32_t off = (uint32_t)(e * LDA_B + col * 2);
    *(uint2*)(sm + A_OFF + off) = make_uint2(pack2h(v.x, v.y), pack2h(v.z, v.w));
}

// ============================================================================
// Phase A: sums of squares over the edge axis (float4 gathers)
// ============================================================================
__global__ void sumsq_kernel(const float* __restrict__ coord,
                             const int* __restrict__ row,
                             const int* __restrict__ col)
{
    __shared__ float s_sum[32];
    int tid = threadIdx.x;
    if (tid < 32) s_sum[tid] = 0.0f;
    __syncthreads();
    float p[32];
#pragma unroll
    for (int i = 0; i < 32; i++) p[i] = 0.0f;
    for (int e = blockIdx.x * blockDim.x + tid; e < N_EDGE; e += gridDim.x * blockDim.x) {
        const float4* c4i = (const float4*)(coord + row[e] * 12);
        const float4* c4j = (const float4*)(coord + col[e] * 12);
        float4 i0 = c4i[0], i1 = c4i[1], i2 = c4i[2];
        float4 j0 = c4j[0], j1 = c4j[1], j2 = c4j[2];
        float a[12] = {i0.x,i0.y,i0.z,i0.w,i1.x,i1.y,i1.z,i1.w,i2.x,i2.y,i2.z,i2.w};
        float b[12] = {j0.x,j0.y,j0.z,j0.w,j1.x,j1.y,j1.z,j1.w,j2.x,j2.y,j2.z,j2.w};
        float d[12];
#pragma unroll
        for (int i = 0; i < 12; i++) d[i] = a[i] - b[i];
#pragma unroll
        for (int c = 0; c < 4; c++) {
#pragma unroll
            for (int f = 0; f < 4; f++) {
                float r = d[c*3+0]*d[f*3+0] + d[c*3+1]*d[f*3+1] + d[c*3+2]*d[f*3+2];
                float dx = a[c*3+0]-b[f*3+0], dy = a[c*3+1]-b[f*3+1], dz = a[c*3+2]-b[f*3+2];
                float d2 = dx*dx + dy*dy + dz*dz;
                p[c*8 + f]     += r * r;
                p[c*8 + 4 + f] += d2;
            }
        }
    }
#pragma unroll
    for (int i = 0; i < 32; i++) atomicAdd(&s_sum[i], p[i]);
    __syncthreads();
    if (tid < 32) atomicAdd(&g_sumsq[tid], s_sum[tid]);
}

// ============================================================================
// Weight prep: [K x 128] fp16 images, row stride 272 B.
// ============================================================================
__global__ void prep_weights(const float* __restrict__ w1,
                             const float* __restrict__ w2,
                             const float* __restrict__ w3)
{
    int idx = blockIdx.x * blockDim.x + threadIdx.x;
    const float* W; unsigned char* dst; int r;
    if (idx < 36864)      { W = w1; dst = g_w1t; r = idx; }
    else if (idx < 53248) { W = w2; dst = g_w2t; r = idx - 36864; }
    else if (idx < 69632) { W = w3; dst = g_w3t; r = idx - 53248; }
    else return;
    int kk = r >> 7, n = r & 127;
    *(__half*)(dst + kk * LDB_B + n * 2) = __float2half_rn(W[kk * 128 + n]);
}

// ============================================================================
// warp-tiled fp16 GEMM, register-staged B prefetch, variable tail chunk.
// 8 warps in 2x4 grid: warp tile 32 rows x 32 cols. Chunks of 64 k-rows
// (last chunk may be 32).
// ============================================================================
#define NSTG 5   // ceil(1088 / 256)

__device__ __forceinline__ void ld_stageN(uint4 (&stg)[NSTG],
                                          const unsigned char* __restrict__ wsrc,
                                          int byteoff, int n4, int tid)
{
    const uint4* s = (const uint4*)(wsrc + byteoff);
#pragma unroll
    for (int i = 0; i < NSTG; i++) {
        int idx = tid + i * ETHREADS;
        if (idx < n4) stg[i] = s[idx];
    }
}

template <int KTOT>
__device__ __forceinline__ void run_gemm_mma(
    unsigned char* sm, uint32_t smem_base, float (&acc)[2][4][4],
    int a_col_base, const unsigned char* __restrict__ wsrc,
    int tid, int lane, int r0, int n0)
{
#pragma unroll
    for (int mt = 0; mt < 2; mt++)
#pragma unroll
        for (int nb = 0; nb < 4; nb++)
#pragma unroll
            for (int i = 0; i < 4; i++) acc[mt][nb][i] = 0.0f;

    uint4 stg[NSTG];
    constexpr int R0 = (KTOT < 64) ? KTOT : 64;
    ld_stageN(stg, wsrc, 0, R0 * 17, tid);

#pragma unroll
    for (int k0 = 0; k0 < KTOT; k0 += 64) {
        const int rows = (KTOT - k0 < 64) ? (KTOT - k0) : 64;
        const int cn4 = rows * 17;
        __syncthreads();                       // previous chunk's MMAs done with B
        {
            uint4* db = (uint4*)(sm + B_OFF);
#pragma unroll
            for (int i = 0; i < NSTG; i++) {
                int idx = tid + i * ETHREADS;
                if (idx < cn4) db[idx] = stg[i];
            }
        }
        __syncthreads();
        if (k0 + 64 < KTOT) {                  // overlap next chunk's LDGs with MMA
            const int nrows = (KTOT - k0 - 64 < 64) ? (KTOT - k0 - 64) : 64;
            ld_stageN(stg, wsrc, (k0 + 64) * LDB_B, nrows * 17, tid);
        }
        const int nks = rows >> 4;
#pragma unroll
        for (int ks = 0; ks < 4; ks++) {
            if (ks >= nks) break;
            int kcol = a_col_base + k0 + ks * 16;
            uint32_t ah[2][4];
            uint32_t a_off = (uint32_t)((r0 + (lane & 15)) * LDA_B + (kcol + (lane >> 4) * 8) * 2);
            ldm_x4(ah[0], smem_base + A_OFF + a_off);
            ldm_x4(ah[1], smem_base + A_OFF + a_off + 16 * LDA_B);
            uint32_t bh[2][4];
            uint32_t b_off = (uint32_t)((ks * 16 + (lane & 15)) * LDB_B + (n0 + (lane >> 4) * 8) * 2);
#pragma unroll
            for (int nt = 0; nt < 2; nt++)
                ldm_x4_t(bh[nt], smem_base + B_OFF + b_off + nt * 32);
#pragma unroll
            for (int mt = 0; mt < 2; mt++)
#pragma unroll
                for (int nt = 0; nt < 2; nt++) {
                    mma_f16(acc[mt][2*nt],   ah[mt], bh[nt][0], bh[nt][1]);
                    mma_f16(acc[mt][2*nt+1], ah[mt], bh[nt][2], bh[nt][3]);
                }
        }
    }
    __syncthreads();
}

// bias + silu + fp16-store to A cols [dstbase, dstbase+128); optional nagg red
__device__ __forceinline__ void epi_store(
    unsigned char* sm, float (&acc)[2][4][4], const float* __restrict__ SBIAS,
    int dstbase, int lane, int r0, int n0, const int* __restrict__ SROW, bool do_nagg)
{
#pragma unroll
    for (int mt = 0; mt < 2; mt++) {
        int ra = r0 + mt * 16 + (lane >> 2);
        int rb = ra + 8;
#pragma unroll
        for (int nb = 0; nb < 4; nb++) {
            int c = n0 + nb * 8 + (lane & 3) * 2;
            float b0 = SBIAS[c], b1 = SBIAS[c + 1];
            float v0 = silu_f(acc[mt][nb][0] + b0);
            float v1 = silu_f(acc[mt][nb][1] + b1);
            float v2 = silu_f(acc[mt][nb][2] + b0);
            float v3 = silu_f(acc[mt][nb][3] + b1);
            uint32_t oa = (uint32_t)(ra * LDA_B + (dstbase + c) * 2);
            uint32_t ob = (uint32_t)(rb * LDA_B + (dstbase + c) * 2);
            *(uint32_t*)(sm + A_OFF + oa) = pack2h(v0, v1);
            *(uint32_t*)(sm + A_OFF + ob) = pack2h(v2, v3);
            if (do_nagg) {
                float* pa = g_nagg + (size_t)SROW[ra] * HID + c;
                float* pb = g_nagg + (size_t)SROW[rb] * HID + c;
                asm volatile("red.global.add.v2.f32 [%0], {%1,%2};"
                             :: "l"(pa), "f"(v0), "f"(v1) : "memory");
                asm volatile("red.global.add.v2.f32 [%0], {%1,%2};"
                             :: "l"(pb), "f"(v2), "f"(v3) : "memory");
            }
        }
    }
}

// ============================================================================
// Fused edge kernel: 64 edges / CTA, 256 threads, 8 warps, 3 CTAs/SM.
// ============================================================================
__global__ void __launch_bounds__(ETHREADS, 3)
edge_kernel(const float* __restrict__ h, const float* __restrict__ coord,
            const int* __restrict__ row, const int* __restrict__ col,
            const float* __restrict__ e_b1, const float* __restrict__ e_b2,
            const float* __restrict__ c_b1, const float* __restrict__ c_wout)
{
    extern __shared__ unsigned char sm[];
    const int tid  = threadIdx.x;
    const int wid  = tid >> 5;
    const int lane = tid & 31;
    const int e0   = blockIdx.x * ME;
    uint32_t smem_base = smem_to_u32(sm);

    int*   SROW  = (int*)(sm + OF_ROW);
    int*   SCOL  = (int*)(sm + OF_COL);
    float* SINV  = (float*)(sm + OF_INV);
    float* SBIAS = (float*)(sm + OF_BIAS);
    float* SCWT  = (float*)(sm + OF_CW);    // [4][136] transposed c_wout
    float* SCD   = (float*)(sm + OF_CD);

    if (tid < ME)  { SROW[tid] = row[e0 + tid]; SCOL[tid] = col[e0 + tid]; }
    if (tid < 32)  SINV[tid] = 1.0f / fmaxf(sqrtf(g_sumsq[tid]), 1e-12f);
    {   // transpose c_wout [128][4] -> SCWT [4][136]
        int k = tid >> 1, half = tid & 1;     // 2 floats per thread
        float2 v = ((const float2*)c_wout)[tid];
        SCWT[(half * 2 + 0) * 136 + k] = v.x;
        SCWT[(half * 2 + 1) * 136 + k] = v.y;
    }
    __syncthreads();

    // ---- gather h[row]|h[col] into A cols 0..255 (fp16) ----
#pragma unroll 4
    for (int idx = tid; idx < ME * 64; idx += ETHREADS) {
        int e = idx >> 6, p4 = idx & 63;
        int half = p4 >> 5, q = p4 & 31;
        int node = half ? SCOL[e] : SROW[e];
        float4 v = ((const float4*)(h + node * HID))[q];
        store4A(sm, e, half * 128 + q * 4, v);
    }
    // ---- rad features cols 256..287; coord_diff to SCD ----
    if (tid < ME) {
        int e = tid;
        const float4* c4i = (const float4*)(coord + SROW[e] * 12);
        const float4* c4j = (const float4*)(coord + SCOL[e] * 12);
        float4 i0 = c4i[0], i1 = c4i[1], i2 = c4i[2];
        float4 j0 = c4j[0], j1 = c4j[1], j2 = c4j[2];
        float a[12] = {i0.x,i0.y,i0.z,i0.w,i1.x,i1.y,i1.z,i1.w,i2.x,i2.y,i2.z,i2.w};
        float b[12] = {j0.x,j0.y,j0.z,j0.w,j1.x,j1.y,j1.z,j1.w,j2.x,j2.y,j2.z,j2.w};
        float d[12];
#pragma unroll
        for (int i = 0; i < 12; i++) { d[i] = a[i] - b[i]; SCD[e * 12 + i] = d[i]; }
        float radv[32];
#pragma unroll
        for (int c = 0; c < 4; c++) {
#pragma unroll
            for (int f = 0; f < 4; f++) {
                float r = d[c*3+0]*d[f*3+0] + d[c*3+1]*d[f*3+1] + d[c*3+2]*d[f*3+2];
                float dx = a[c*3+0]-b[f*3+0], dy = a[c*3+1]-b[f*3+1], dz = a[c*3+2]-b[f*3+2];
                float d2 = dx*dx + dy*dy + dz*dz;
                radv[c*8 + f]     = r * SINV[c*8 + f];
                radv[c*8 + 4 + f] = sqrtf(d2) * SINV[c*8 + 4 + f];
            }
        }
#pragma unroll
        for (int q = 0; q < 32; q += 4)
            store4A(sm, e, 256 + q, make_float4(radv[q], radv[q+1], radv[q+2], radv[q+3]));
    }

    const int wm = wid & 1, wn = wid >> 1;
    const int r0 = wm * 32, n0 = wn * 32;
    float acc[2][4][4];

    // ========== GEMM1: t1 = silu(eh @ W1 + b1) -> A cols 0..127 (K=288) ===
    if (tid < 128) SBIAS[tid] = e_b1[tid];
    run_gemm_mma<288>(sm, smem_base, acc, 0, g_w1t, tid, lane, r0, n0);
    epi_store(sm, acc, SBIAS, 0, lane, r0, n0, SROW, false);
    __syncthreads();

    // ========== GEMM2: m = silu(t1 @ W2 + b2) -> A cols 128..255, nagg ====
    if (tid < 128) SBIAS[tid] = e_b2[tid];
    __syncthreads();
    run_gemm_mma<128>(sm, smem_base, acc, 0, g_w2t, tid, lane, r0, n0);
    epi_store(sm, acc, SBIAS, 128, lane, r0, n0, SROW, true);
    __syncthreads();

    // ========== GEMM3: t2 = silu(m @ c_w1 + b) -> fp32 buffer =============
    if (tid < 128) SBIAS[tid] = c_b1[tid];
    __syncthreads();
    run_gemm_mma<128>(sm, smem_base, acc, 128, g_w3t, tid, lane, r0, n0);
    {
        float* t2f = (float*)(sm + A_OFF);  // [64 x 132] fp32; A done after GEMM3
#pragma unroll
        for (int mt = 0; mt < 2; mt++) {
            int ra = r0 + mt * 16 + (lane >> 2);
            int rb = ra + 8;
#pragma unroll
            for (int nb = 0; nb < 4; nb++) {
                int c = n0 + nb * 8 + (lane & 3) * 2;
                float b0 = SBIAS[c], b1 = SBIAS[c + 1];
                *(float2*)(t2f + ra * 132 + c) =
                    make_float2(silu_f(acc[mt][nb][0] + b0), silu_f(acc[mt][nb][1] + b1));
                *(float2*)(t2f + rb * 132 + c) =
                    make_float2(silu_f(acc[mt][nb][2] + b0), silu_f(acc[mt][nb][3] + b1));
            }
        }
    }
    __syncthreads();

    // ========== w = t2 @ c_wout (float4 dot); coord atomics ===============
    {
        int e = tid >> 2, c = tid & 3;
        const float4* tr4 = (const float4*)((const float*)(sm + A_OFF) + e * 132);
        const float4* cw4 = (const float4*)(SCWT + c * 136);
        float w = 0.0f;
#pragma unroll
        for (int i = 0; i < 32; i++) {
            float4 t = tr4[i], u = cw4[i];
            w += t.x * u.x + t.y * u.y + t.z * u.z + t.w * u.w;
        }
        int node = SROW[e];
        const float* cd = SCD + e * 12 + c * 3;
        atomicAdd(&g_agg[node * 12 + c * 3 + 0], cd[0] * w);
        atomicAdd(&g_agg[node * 12 + c * 3 + 1], cd[1] * w);
        atomicAdd(&g_agg[node * 12 + c * 3 + 2], cd[2] * w);
        if (c == 0) atomicAdd(&g_cnt[node], 1.0f);
    }
}

// ============================================================================
// Node MLP + residual + coord epilogue (SIMT fp32, TN=32, ~2 CTAs/SM wave)
// ============================================================================
template <int K>
__device__ __forceinline__ void gemm32(const float* __restrict__ A, int lda,
                                       const float* __restrict__ W,
                                       float* __restrict__ w_sm,
                                       float (&acc)[2][8], int tid)
{
    const int tx = tid & 15, ty = tid >> 4;
#pragma unroll
    for (int i = 0; i < 2; i++)
#pragma unroll
        for (int j = 0; j < 8; j++) acc[i][j] = 0.0f;
    const float* a0 = A + (ty * 2 + 0) * lda;
    const float* a1 = A + (ty * 2 + 1) * lda;
    for (int k0 = 0; k0 < K; k0 += KT) {
#pragma unroll
        for (int i = tid * 4; i < KT * 128; i += 256 * 4)
            *(float4*)(w_sm + i) = *(const float4*)(W + k0 * 128 + i);
        __syncthreads();
#pragma unroll 4
        for (int k = 0; k < KT; k++) {
            float b[8];
#pragma unroll
            for (int j = 0; j < 8; j++) b[j] = w_sm[k * 128 + tx + 16 * j];
            float v0 = a0[k0 + k], v1 = a1[k0 + k];
#pragma unroll
            for (int j = 0; j < 8; j++) {
                acc[0][j] += v0 * b[j];
                acc[1][j] += v1 * b[j];
            }
        }
        __syncthreads();
    }
}

#define NK_OFF_W   (TN * NIN_LD)        // 8320 floats
#define NK_SMEM_FL (NK_OFF_W + KT * 128)  // 12416 floats = 49664 B

__global__ void __launch_bounds__(256, 4)
node_kernel(const float* __restrict__ h, const float* __restrict__ coord,
            const float* __restrict__ n_w1, const float* __restrict__ n_b1,
            const float* __restrict__ n_w2, const float* __restrict__ n_b2,
            float* __restrict__ out_h, float* __restrict__ out_coord)
{
    extern __shared__ float smf[];
    float* nin  = smf;
    float* bufA = smf;
    float* w_sm = smf + NK_OFF_W;
    const int tid = threadIdx.x;
    const int n0  = blockIdx.x * TN;

#pragma unroll
    for (int idx = tid; idx < TN * 64; idx += 256) {
        int r = idx >> 6, q = idx & 63;
        int n = n0 + r;
        int qq = q & 31;
        float4 v = make_float4(0.f, 0.f, 0.f, 0.f);
        if (n < N_NODE)
            v = (q < 32) ? ((const float4*)(h + n * HID))[qq]
                         : *(const float4*)(g_nagg + n * HID + qq * 4);
        *(float4*)(nin + r * NIN_LD + ((q < 32) ? 0 : HID) + qq * 4) = v;
    }
    __syncthreads();

    float acc[2][8];
    gemm32<2 * HID>(nin, NIN_LD, n_w1, w_sm, acc, tid);
    {
        const int tx = tid & 15, ty = tid >> 4;
#pragma unroll
        for (int j = 0; j < 8; j++) {
            int c = tx + 16 * j;
            float bb = n_b1[c];
#pragma unroll
            for (int i = 0; i < 2; i++)
                bufA[(ty * 2 + i) * BUF_LD + c] = silu_f(acc[i][j] + bb);
        }
    }
    __syncthreads();
    gemm32<HID>(bufA, BUF_LD, n_w2, w_sm, acc, tid);

    {
        const int tx = tid & 15, ty = tid >> 4;
#pragma unroll
        for (int j = 0; j < 8; j++) {
            int c = tx + 16 * j;
            float bb = n_b2[c];
#pragma unroll
            for (int i = 0; i < 2; i++) {
                int n = n0 + ty * 2 + i;
                if (n < N_NODE)
                    out_h[n * HID + c] = acc[i][j] + bb + h[n * HID + c];
            }
        }
    }
    for (int idx = tid; idx < TN * 12; idx += 256) {
        int r = idx / 12, d = idx % 12;
        int n = n0 + r;
        if (n < N_NODE) {
            float cnt = fmaxf(g_cnt[n], 1.0f);
            out_coord[n * 12 + d] = coord[n * 12 + d] + g_agg[n * 12 + d] / cnt;
        }
    }
}

// ============================================================================
extern "C" void kernel_launch(void* const* d_in, const int* in_sizes, int n_in,
                              void* d_out, int out_size)
{
    const float* h      = (const float*)d_in[0];
    const float* coord  = (const float*)d_in[1];
    const int*   row    = (const int*)d_in[2];
    const int*   col    = (const int*)d_in[3];
    const float* e_w1   = (const float*)d_in[4];
    const float* e_b1   = (const float*)d_in[5];
    const float* e_w2   = (const float*)d_in[6];
    const float* e_b2   = (const float*)d_in[7];
    const float* c_w1   = (const float*)d_in[8];
    const float* c_b1   = (const float*)d_in[9];
    const float* c_wout = (const float*)d_in[10];
    const float* n_w1   = (const float*)d_in[11];
    const float* n_b1   = (const float*)d_in[12];
    const float* n_w2   = (const float*)d_in[13];
    const float* n_b2   = (const float*)d_in[14];

    float* out_h     = (float*)d_out;
    float* out_coord = out_h + N_NODE * HID;

    void *p_sumsq, *p_nagg, *p_agg, *p_cnt;
    cudaGetSymbolAddress(&p_sumsq, g_sumsq);
    cudaGetSymbolAddress(&p_nagg,  g_nagg);
    cudaGetSymbolAddress(&p_agg,   g_agg);
    cudaGetSymbolAddress(&p_cnt,   g_cnt);
    cudaMemsetAsync(p_sumsq, 0, 32 * sizeof(float));
    cudaMemsetAsync(p_nagg,  0, N_NODE * HID * sizeof(float));
    cudaMemsetAsync(p_agg,   0, N_NODE * 12 * sizeof(float));
    cudaMemsetAsync(p_cnt,   0, N_NODE * sizeof(float));

    cudaFuncSetAttribute(edge_kernel, cudaFuncAttributeMaxDynamicSharedMemorySize,
                         SMEM_EDGE_BYTES);
    cudaFuncSetAttribute(node_kernel, cudaFuncAttributeMaxDynamicSharedMemorySize,
                         NK_SMEM_FL * (int)sizeof(float));

    prep_weights<<<272, 256>>>(e_w1, e_w2, c_w1);
    sumsq_kernel<<<1184, 256>>>(coord, row, col);
    edge_kernel<<<N_EDGE / ME, ETHREADS, SMEM_EDGE_BYTES>>>(
        h, coord, row, col, e_b1, e_b2, c_b1, c_wout);
    node_kernel<<<(N_NODE + TN - 1) / TN, 256, NK_SMEM_FL * sizeof(float)>>>(
        h, coord, n_w1, n_b1, n_w2, n_b2, out_h, out_coord);
}

// round 10
// speedup vs baseline: 2.7031x; 1.0714x over previous
#include <cuda_runtime.h>
#include <cuda_fp16.h>
#include <math.h>
#include <stdint.h>

#define N_NODE 10000
#define N_EDGE 320000
#define HID    128
#define NC     4

// ---------------- edge/node MMA kernel geometry ----------------
#define ME      64            // rows (edges/nodes) per CTA
#define ETHREADS 256
#define LDA_B   656           // A row stride bytes (328 fp16 capacity)
#define LDB_B   272           // B row stride bytes (136 fp16)
#define A_OFF   0             // fp16 A image: 64*656 = 41984 B
#define B_OFF   41984         // B chunk: up to 64 k-rows * 272 B = 17408
#define OF_ROW  59392
#define OF_COL  59648
#define OF_INV  59904
#define OF_BIAS 60032
#define OF_CW   60544         // transposed c_wout: 4 x 136 fp32 = 2176 B
#define OF_CD   62720         // coord_diff: 64*12*4 = 3072 B
#define SMEM_EDGE_BYTES 65792
#define SMEM_NODE_BYTES 60544 // A + B + bias

// ---------------- scratch ----------------
__device__ float g_sumsq[32];
__device__ float g_nagg[N_NODE * HID];
__device__ float g_agg[N_NODE * NC * 3];
__device__ float g_cnt[N_NODE];
// weight images: [K x 128] fp16, row stride 272 B
__device__ __align__(16) unsigned char g_w1t[288 * LDB_B];
__device__ __align__(16) unsigned char g_w2t[128 * LDB_B];
__device__ __align__(16) unsigned char g_w3t[128 * LDB_B];
__device__ __align__(16) unsigned char g_nw1t[256 * LDB_B];
__device__ __align__(16) unsigned char g_nw2t[128 * LDB_B];

__device__ __forceinline__ float silu_f(float x) {
    return __fdividef(x, 1.0f + __expf(-x));
}

__device__ __forceinline__ uint32_t smem_to_u32(const void* p) {
    uint32_t a;
    asm("{ .reg .u64 t; cvta.to.shared.u64 t, %1; cvt.u32.u64 %0, t; }" : "=r"(a) : "l"(p));
    return a;
}
__device__ __forceinline__ void ldm_x4(uint32_t (&r)[4], uint32_t addr) {
    asm volatile("ldmatrix.sync.aligned.m8n8.x4.shared.b16 {%0,%1,%2,%3}, [%4];"
                 : "=r"(r[0]), "=r"(r[1]), "=r"(r[2]), "=r"(r[3]) : "r"(addr));
}
__device__ __forceinline__ void ldm_x4_t(uint32_t (&r)[4], uint32_t addr) {
    asm volatile("ldmatrix.sync.aligned.m8n8.x4.trans.shared.b16 {%0,%1,%2,%3}, [%4];"
                 : "=r"(r[0]), "=r"(r[1]), "=r"(r[2]), "=r"(r[3]) : "r"(addr));
}
__device__ __forceinline__ void mma_f16(float (&d)[4], const uint32_t (&a)[4],
                                        uint32_t b0, uint32_t b1) {
    asm volatile("mma.sync.aligned.m16n8k16.row.col.f32.f16.f16.f32 "
                 "{%0,%1,%2,%3}, {%4,%5,%6,%7}, {%8,%9}, {%0,%1,%2,%3};"
                 : "+f"(d[0]), "+f"(d[1]), "+f"(d[2]), "+f"(d[3])
                 : "r"(a[0]), "r"(a[1]), "r"(a[2]), "r"(a[3]), "r"(b0), "r"(b1));
}

__device__ __forceinline__ uint32_t pack2h(float a, float b) {
    __half2 t = __floats2half2_rn(a, b);
    return *reinterpret_cast<uint32_t*>(&t);
}
__device__ __forceinline__ void store4A(unsigned char* sm, int e, int col, float4 v) {
    uint32_t off = (uint32_t)(e * LDA_B + col * 2);
    *(uint2*)(sm + A_OFF + off) = make_uint2(pack2h(v.x, v.y), pack2h(v.z, v.w));
}

// ============================================================================
// Fused prep (weights -> fp16 images) + sumsq (L2-norm sums over edges).
// Blocks [0, PREP_BLOCKS) do prep; the rest do sumsq.
// ============================================================================
#define PREP_BLOCKS  464   // 118784 elems / 256
#define SUMSQ_BLOCKS 1184

__global__ void prep_sumsq_kernel(const float* __restrict__ w1,
                                  const float* __restrict__ w2,
                                  const float* __restrict__ w3,
                                  const float* __restrict__ nw1,
                                  const float* __restrict__ nw2,
                                  const float* __restrict__ coord,
                                  const int* __restrict__ row,
                                  const int* __restrict__ col)
{
    int tid = threadIdx.x;
    if (blockIdx.x < PREP_BLOCKS) {
        int idx = blockIdx.x * 256 + tid;
        const float* W; unsigned char* dst; int r;
        if (idx < 36864)       { W = w1;  dst = g_w1t;  r = idx; }
        else if (idx < 53248)  { W = w2;  dst = g_w2t;  r = idx - 36864; }
        else if (idx < 69632)  { W = w3;  dst = g_w3t;  r = idx - 53248; }
        else if (idx < 102400) { W = nw1; dst = g_nw1t; r = idx - 69632; }
        else if (idx < 118784) { W = nw2; dst = g_nw2t; r = idx - 102400; }
        else return;
        int kk = r >> 7, n = r & 127;
        *(__half*)(dst + kk * LDB_B + n * 2) = __float2half_rn(W[kk * 128 + n]);
        return;
    }
    // ---- sumsq ----
    __shared__ float s_sum[32];
    if (tid < 32) s_sum[tid] = 0.0f;
    __syncthreads();
    float p[32];
#pragma unroll
    for (int i = 0; i < 32; i++) p[i] = 0.0f;
    int bid = blockIdx.x - PREP_BLOCKS;
    for (int e = bid * 256 + tid; e < N_EDGE; e += SUMSQ_BLOCKS * 256) {
        const float4* c4i = (const float4*)(coord + row[e] * 12);
        const float4* c4j = (const float4*)(coord + col[e] * 12);
        float4 i0 = c4i[0], i1 = c4i[1], i2 = c4i[2];
        float4 j0 = c4j[0], j1 = c4j[1], j2 = c4j[2];
        float a[12] = {i0.x,i0.y,i0.z,i0.w,i1.x,i1.y,i1.z,i1.w,i2.x,i2.y,i2.z,i2.w};
        float b[12] = {j0.x,j0.y,j0.z,j0.w,j1.x,j1.y,j1.z,j1.w,j2.x,j2.y,j2.z,j2.w};
        float d[12];
#pragma unroll
        for (int i = 0; i < 12; i++) d[i] = a[i] - b[i];
#pragma unroll
        for (int c = 0; c < 4; c++) {
#pragma unroll
            for (int f = 0; f < 4; f++) {
                float r = d[c*3+0]*d[f*3+0] + d[c*3+1]*d[f*3+1] + d[c*3+2]*d[f*3+2];
                float dx = a[c*3+0]-b[f*3+0], dy = a[c*3+1]-b[f*3+1], dz = a[c*3+2]-b[f*3+2];
                float d2 = dx*dx + dy*dy + dz*dz;
                p[c*8 + f]     += r * r;
                p[c*8 + 4 + f] += d2;
            }
        }
    }
#pragma unroll
    for (int i = 0; i < 32; i++) atomicAdd(&s_sum[i], p[i]);
    __syncthreads();
    if (tid < 32) atomicAdd(&g_sumsq[tid], s_sum[tid]);
}

// ============================================================================
// warp-tiled fp16 GEMM, register-staged B prefetch, variable tail chunk.
// 8 warps in 2x4 grid: warp tile 32 rows x 32 cols.
// ============================================================================
#define NSTG 5   // ceil(1088 / 256)

__device__ __forceinline__ void ld_stageN(uint4 (&stg)[NSTG],
                                          const unsigned char* __restrict__ wsrc,
                                          int byteoff, int n4, int tid)
{
    const uint4* s = (const uint4*)(wsrc + byteoff);
#pragma unroll
    for (int i = 0; i < NSTG; i++) {
        int idx = tid + i * ETHREADS;
        if (idx < n4) stg[i] = s[idx];
    }
}

template <int KTOT>
__device__ __forceinline__ void run_gemm_mma(
    unsigned char* sm, uint32_t smem_base, float (&acc)[2][4][4],
    int a_col_base, const unsigned char* __restrict__ wsrc,
    int tid, int lane, int r0, int n0)
{
#pragma unroll
    for (int mt = 0; mt < 2; mt++)
#pragma unroll
        for (int nb = 0; nb < 4; nb++)
#pragma unroll
            for (int i = 0; i < 4; i++) acc[mt][nb][i] = 0.0f;

    uint4 stg[NSTG];
    constexpr int R0 = (KTOT < 64) ? KTOT : 64;
    ld_stageN(stg, wsrc, 0, R0 * 17, tid);

#pragma unroll
    for (int k0 = 0; k0 < KTOT; k0 += 64) {
        const int rows = (KTOT - k0 < 64) ? (KTOT - k0) : 64;
        const int cn4 = rows * 17;
        __syncthreads();                       // previous chunk's MMAs done with B
        {
            uint4* db = (uint4*)(sm + B_OFF);
#pragma unroll
            for (int i = 0; i < NSTG; i++) {
                int idx = tid + i * ETHREADS;
                if (idx < cn4) db[idx] = stg[i];
            }
        }
        __syncthreads();
        if (k0 + 64 < KTOT) {                  // overlap next chunk's LDGs with MMA
            const int nrows = (KTOT - k0 - 64 < 64) ? (KTOT - k0 - 64) : 64;
            ld_stageN(stg, wsrc, (k0 + 64) * LDB_B, nrows * 17, tid);
        }
        const int nks = rows >> 4;
#pragma unroll
        for (int ks = 0; ks < 4; ks++) {
            if (ks >= nks) break;
            int kcol = a_col_base + k0 + ks * 16;
            uint32_t ah[2][4];
            uint32_t a_off = (uint32_t)((r0 + (lane & 15)) * LDA_B + (kcol + (lane >> 4) * 8) * 2);
            ldm_x4(ah[0], smem_base + A_OFF + a_off);
            ldm_x4(ah[1], smem_base + A_OFF + a_off + 16 * LDA_B);
            uint32_t bh[2][4];
            uint32_t b_off = (uint32_t)((ks * 16 + (lane & 15)) * LDB_B + (n0 + (lane >> 4) * 8) * 2);
#pragma unroll
            for (int nt = 0; nt < 2; nt++)
                ldm_x4_t(bh[nt], smem_base + B_OFF + b_off + nt * 32);
#pragma unroll
            for (int mt = 0; mt < 2; mt++)
#pragma unroll
                for (int nt = 0; nt < 2; nt++) {
                    mma_f16(acc[mt][2*nt],   ah[mt], bh[nt][0], bh[nt][1]);
                    mma_f16(acc[mt][2*nt+1], ah[mt], bh[nt][2], bh[nt][3]);
                }
        }
    }
    __syncthreads();
}

// bias + silu + fp16-store to A cols [dstbase, dstbase+128); optional nagg red
__device__ __forceinline__ void epi_store(
    unsigned char* sm, float (&acc)[2][4][4], const float* __restrict__ SBIAS,
    int dstbase, int lane, int r0, int n0, const int* __restrict__ SROW, bool do_nagg)
{
#pragma unroll
    for (int mt = 0; mt < 2; mt++) {
        int ra = r0 + mt * 16 + (lane >> 2);
        int rb = ra + 8;
#pragma unroll
        for (int nb = 0; nb < 4; nb++) {
            int c = n0 + nb * 8 + (lane & 3) * 2;
            float b0 = SBIAS[c], b1 = SBIAS[c + 1];
            float v0 = silu_f(acc[mt][nb][0] + b0);
            float v1 = silu_f(acc[mt][nb][1] + b1);
            float v2 = silu_f(acc[mt][nb][2] + b0);
            float v3 = silu_f(acc[mt][nb][3] + b1);
            uint32_t oa = (uint32_t)(ra * LDA_B + (dstbase + c) * 2);
            uint32_t ob = (uint32_t)(rb * LDA_B + (dstbase + c) * 2);
            *(uint32_t*)(sm + A_OFF + oa) = pack2h(v0, v1);
            *(uint32_t*)(sm + A_OFF + ob) = pack2h(v2, v3);
            if (do_nagg) {
                float* pa = g_nagg + (size_t)SROW[ra] * HID + c;
                float* pb = g_nagg + (size_t)SROW[rb] * HID + c;
                asm volatile("red.global.add.v2.f32 [%0], {%1,%2};"
                             :: "l"(pa), "f"(v0), "f"(v1) : "memory");
                asm volatile("red.global.add.v2.f32 [%0], {%1,%2};"
                             :: "l"(pb), "f"(v2), "f"(v3) : "memory");
            }
        }
    }
}

// ============================================================================
// Fused edge kernel: 64 edges / CTA, 256 threads, 8 warps, 3 CTAs/SM.
// ============================================================================
__global__ void __launch_bounds__(ETHREADS, 3)
edge_kernel(const float* __restrict__ h, const float* __restrict__ coord,
            const int* __restrict__ row, const int* __restrict__ col,
            const float* __restrict__ e_b1, const float* __restrict__ e_b2,
            const float* __restrict__ c_b1, const float* __restrict__ c_wout)
{
    extern __shared__ unsigned char sm[];
    const int tid  = threadIdx.x;
    const int wid  = tid >> 5;
    const int lane = tid & 31;
    const int e0   = blockIdx.x * ME;
    uint32_t smem_base = smem_to_u32(sm);

    int*   SROW  = (int*)(sm + OF_ROW);
    int*   SCOL  = (int*)(sm + OF_COL);
    float* SINV  = (float*)(sm + OF_INV);
    float* SBIAS = (float*)(sm + OF_BIAS);
    float* SCWT  = (float*)(sm + OF_CW);    // [4][136] transposed c_wout
    float* SCD   = (float*)(sm + OF_CD);

    if (tid < ME)  { SROW[tid] = row[e0 + tid]; SCOL[tid] = col[e0 + tid]; }
    if (tid < 32)  SINV[tid] = 1.0f / fmaxf(sqrtf(g_sumsq[tid]), 1e-12f);
    {   // transpose c_wout [128][4] -> SCWT [4][136]
        int k = tid >> 1, half = tid & 1;
        float2 v = ((const float2*)c_wout)[tid];
        SCWT[(half * 2 + 0) * 136 + k] = v.x;
        SCWT[(half * 2 + 1) * 136 + k] = v.y;
    }
    __syncthreads();

    // ---- gather h[row]|h[col] into A cols 0..255 (fp16) ----
#pragma unroll 4
    for (int idx = tid; idx < ME * 64; idx += ETHREADS) {
        int e = idx >> 6, p4 = idx & 63;
        int half = p4 >> 5, q = p4 & 31;
        int node = half ? SCOL[e] : SROW[e];
        float4 v = ((const float4*)(h + node * HID))[q];
        store4A(sm, e, half * 128 + q * 4, v);
    }
    // ---- rad features cols 256..287; coord_diff to SCD ----
    if (tid < ME) {
        int e = tid;
        const float4* c4i = (const float4*)(coord + SROW[e] * 12);
        const float4* c4j = (const float4*)(coord + SCOL[e] * 12);
        float4 i0 = c4i[0], i1 = c4i[1], i2 = c4i[2];
        float4 j0 = c4j[0], j1 = c4j[1], j2 = c4j[2];
        float a[12] = {i0.x,i0.y,i0.z,i0.w,i1.x,i1.y,i1.z,i1.w,i2.x,i2.y,i2.z,i2.w};
        float b[12] = {j0.x,j0.y,j0.z,j0.w,j1.x,j1.y,j1.z,j1.w,j2.x,j2.y,j2.z,j2.w};
        float d[12];
#pragma unroll
        for (int i = 0; i < 12; i++) { d[i] = a[i] - b[i]; SCD[e * 12 + i] = d[i]; }
        float radv[32];
#pragma unroll
        for (int c = 0; c < 4; c++) {
#pragma unroll
            for (int f = 0; f < 4; f++) {
                float r = d[c*3+0]*d[f*3+0] + d[c*3+1]*d[f*3+1] + d[c*3+2]*d[f*3+2];
                float dx = a[c*3+0]-b[f*3+0], dy = a[c*3+1]-b[f*3+1], dz = a[c*3+2]-b[f*3+2];
                float d2 = dx*dx + dy*dy + dz*dz;
                radv[c*8 + f]     = r * SINV[c*8 + f];
                radv[c*8 + 4 + f] = sqrtf(d2) * SINV[c*8 + 4 + f];
            }
        }
#pragma unroll
        for (int q = 0; q < 32; q += 4)
            store4A(sm, e, 256 + q, make_float4(radv[q], radv[q+1], radv[q+2], radv[q+3]));
    }

    const int wm = wid & 1, wn = wid >> 1;
    const int r0 = wm * 32, n0 = wn * 32;
    float acc[2][4][4];

    // ========== GEMM1: t1 = silu(eh @ W1 + b1) -> A cols 0..127 (K=288) ===
    if (tid < 128) SBIAS[tid] = e_b1[tid];
    run_gemm_mma<288>(sm, smem_base, acc, 0, g_w1t, tid, lane, r0, n0);
    epi_store(sm, acc, SBIAS, 0, lane, r0, n0, SROW, false);
    __syncthreads();

    // ========== GEMM2: m = silu(t1 @ W2 + b2) -> A cols 128..255, nagg ====
    if (tid < 128) SBIAS[tid] = e_b2[tid];
    __syncthreads();
    run_gemm_mma<128>(sm, smem_base, acc, 0, g_w2t, tid, lane, r0, n0);
    epi_store(sm, acc, SBIAS, 128, lane, r0, n0, SROW, true);
    __syncthreads();

    // ========== GEMM3: t2 = silu(m @ c_w1 + b) -> fp32 buffer =============
    if (tid < 128) SBIAS[tid] = c_b1[tid];
    __syncthreads();
    run_gemm_mma<128>(sm, smem_base, acc, 128, g_w3t, tid, lane, r0, n0);
    {
        float* t2f = (float*)(sm + A_OFF);  // [64 x 132] fp32; A done after GEMM3
#pragma unroll
        for (int mt = 0; mt < 2; mt++) {
            int ra = r0 + mt * 16 + (lane >> 2);
            int rb = ra + 8;
#pragma unroll
            for (int nb = 0; nb < 4; nb++) {
                int c = n0 + nb * 8 + (lane & 3) * 2;
                float b0 = SBIAS[c], b1 = SBIAS[c + 1];
                *(float2*)(t2f + ra * 132 + c) =
                    make_float2(silu_f(acc[mt][nb][0] + b0), silu_f(acc[mt][nb][1] + b1));
                *(float2*)(t2f + rb * 132 + c) =
                    make_float2(silu_f(acc[mt][nb][2] + b0), silu_f(acc[mt][nb][3] + b1));
            }
        }
    }
    __syncthreads();

    // ========== w = t2 @ c_wout (float4 dot); coord atomics ===============
    {
        int e = tid >> 2, c = tid & 3;
        const float4* tr4 = (const float4*)((const float*)(sm + A_OFF) + e * 132);
        const float4* cw4 = (const float4*)(SCWT + c * 136);
        float w = 0.0f;
#pragma unroll
        for (int i = 0; i < 32; i++) {
            float4 t = tr4[i], u = cw4[i];
            w += t.x * u.x + t.y * u.y + t.z * u.z + t.w * u.w;
        }
        int node = SROW[e];
        const float* cd = SCD + e * 12 + c * 3;
        atomicAdd(&g_agg[node * 12 + c * 3 + 0], cd[0] * w);
        atomicAdd(&g_agg[node * 12 + c * 3 + 1], cd[1] * w);
        atomicAdd(&g_agg[node * 12 + c * 3 + 2], cd[2] * w);
        if (c == 0) atomicAdd(&g_cnt[node], 1.0f);
    }
}

// ============================================================================
// Node MLP via fp16 MMA: 64 nodes / CTA, same GEMM machinery.
// GEMM1: nin=[h|nagg] (K=256) -> silu -> A cols 0..127
// GEMM2: K=128 -> +b2 +h residual -> out_h ; then coord epilogue.
// ============================================================================
__global__ void __launch_bounds__(ETHREADS, 3)
node_kernel(const float* __restrict__ h, const float* __restrict__ coord,
            const float* __restrict__ n_b1, const float* __restrict__ n_b2,
            float* __restrict__ out_h, float* __restrict__ out_coord)
{
    extern __shared__ unsigned char sm[];
    const int tid  = threadIdx.x;
    const int wid  = tid >> 5;
    const int lane = tid & 31;
    const int nb0  = blockIdx.x * ME;
    uint32_t smem_base = smem_to_u32(sm);
    float* SBIAS = (float*)(sm + OF_ROW);   // reuse offset region (512 B)

    // ---- gather h[n] | nagg[n] into A cols 0..255 (fp16) ----
#pragma unroll 4
    for (int idx = tid; idx < ME * 64; idx += ETHREADS) {
        int r = idx >> 6, p4 = idx & 63;
        int half = p4 >> 5, q = p4 & 31;
        int n = nb0 + r;
        float4 v = make_float4(0.f, 0.f, 0.f, 0.f);
        if (n < N_NODE)
            v = half ? ((const float4*)(g_nagg + n * HID))[q]
                     : ((const float4*)(h + n * HID))[q];
        store4A(sm, r, half * 128 + q * 4, v);
    }

    const int wm = wid & 1, wn = wid >> 1;
    const int r0 = wm * 32, n0 = wn * 32;
    float acc[2][4][4];

    // ========== GEMM1: t = silu(nin @ nW1 + b1) -> A cols 0..127 ==========
    if (tid < 128) SBIAS[tid] = n_b1[tid];
    run_gemm_mma<256>(sm, smem_base, acc, 0, g_nw1t, tid, lane, r0, n0);
    epi_store(sm, acc, SBIAS, 0, lane, r0, n0, (const int*)nullptr, false);
    __syncthreads();

    // ========== GEMM2: hn = t @ nW2 + b2 ; out_h = h + hn =================
    if (tid < 128) SBIAS[tid] = n_b2[tid];
    __syncthreads();
    run_gemm_mma<128>(sm, smem_base, acc, 0, g_nw2t, tid, lane, r0, n0);
    {
#pragma unroll
        for (int mt = 0; mt < 2; mt++) {
            int ra = r0 + mt * 16 + (lane >> 2);
            int rb = ra + 8;
            int na = nb0 + ra, nbv = nb0 + rb;
#pragma unroll
            for (int nb = 0; nb < 4; nb++) {
                int c = n0 + nb * 8 + (lane & 3) * 2;
                float b0 = SBIAS[c], b1 = SBIAS[c + 1];
                if (na < N_NODE) {
                    float2 hv = *(const float2*)(h + na * HID + c);
                    *(float2*)(out_h + na * HID + c) =
                        make_float2(acc[mt][nb][0] + b0 + hv.x,
                                    acc[mt][nb][1] + b1 + hv.y);
                }
                if (nbv < N_NODE) {
                    float2 hv = *(const float2*)(h + nbv * HID + c);
                    *(float2*)(out_h + nbv * HID + c) =
                        make_float2(acc[mt][nb][2] + b0 + hv.x,
                                    acc[mt][nb][3] + b1 + hv.y);
                }
            }
        }
    }
    // ---- coord epilogue ----
    for (int idx = tid; idx < ME * 12; idx += ETHREADS) {
        int r = idx / 12, d = idx % 12;
        int n = nb0 + r;
        if (n < N_NODE) {
            float cnt = fmaxf(g_cnt[n], 1.0f);
            out_coord[n * 12 + d] = coord[n * 12 + d] + g_agg[n * 12 + d] / cnt;
        }
    }
}

// ============================================================================
extern "C" void kernel_launch(void* const* d_in, const int* in_sizes, int n_in,
                              void* d_out, int out_size)
{
    const float* h      = (const float*)d_in[0];
    const float* coord  = (const float*)d_in[1];
    const int*   row    = (const int*)d_in[2];
    const int*   col    = (const int*)d_in[3];
    const float* e_w1   = (const float*)d_in[4];
    const float* e_b1   = (const float*)d_in[5];
    const float* e_w2   = (const float*)d_in[6];
    const float* e_b2   = (const float*)d_in[7];
    const float* c_w1   = (const float*)d_in[8];
    const float* c_b1   = (const float*)d_in[9];
    const float* c_wout = (const float*)d_in[10];
    const float* n_w1   = (const float*)d_in[11];
    const float* n_b1   = (const float*)d_in[12];
    const float* n_w2   = (const float*)d_in[13];
    const float* n_b2   = (const float*)d_in[14];

    float* out_h     = (float*)d_out;
    float* out_coord = out_h + N_NODE * HID;

    void *p_sumsq, *p_nagg, *p_agg, *p_cnt;
    cudaGetSymbolAddress(&p_sumsq, g_sumsq);
    cudaGetSymbolAddress(&p_nagg,  g_nagg);
    cudaGetSymbolAddress(&p_agg,   g_agg);
    cudaGetSymbolAddress(&p_cnt,   g_cnt);
    cudaMemsetAsync(p_sumsq, 0, 32 * sizeof(float));
    cudaMemsetAsync(p_nagg,  0, N_NODE * HID * sizeof(float));
    cudaMemsetAsync(p_agg,   0, N_NODE * 12 * sizeof(float));
    cudaMemsetAsync(p_cnt,   0, N_NODE * sizeof(float));

    cudaFuncSetAttribute(edge_kernel, cudaFuncAttributeMaxDynamicSharedMemorySize,
                         SMEM_EDGE_BYTES);
    cudaFuncSetAttribute(node_kernel, cudaFuncAttributeMaxDynamicSharedMemorySize,
                         SMEM_NODE_BYTES);

    prep_sumsq_kernel<<<PREP_BLOCKS + SUMSQ_BLOCKS, 256>>>(
        e_w1, e_w2, c_w1, n_w1, n_w2, coord, row, col);
    edge_kernel<<<N_EDGE / ME, ETHREADS, SMEM_EDGE_BYTES>>>(
        h, coord, row, col, e_b1, e_b2, c_b1, c_wout);
    node_kernel<<<(N_NODE + ME - 1) / ME, ETHREADS, SMEM_NODE_BYTES>>>(
        h, coord, n_b1, n_b2, out_h, out_coord);
}

// round 11
// speedup vs baseline: 2.7630x; 1.0222x over previous
#include <cuda_runtime.h>
#include <cuda_fp16.h>
#include <math.h>
#include <stdint.h>

#define N_NODE 10000
#define N_EDGE 320000
#define HID    128
#define NC     4

// ---------------- edge kernel geometry (ME=128, occ 2) ----------------
#define ME      128           // edges per CTA
#define ETHREADS 256
#define LDA_B   656           // A row stride bytes
#define LDB_B   272           // B row stride bytes (136 fp16)
#define A_OFF   0             // fp16 A image: 128*656 = 83968 B
#define B_OFF   83968         // B chunk: up to 64 k-rows * 272 B = 17408
#define OF_ROW  101376
#define OF_COL  101888
#define OF_INV  102400
#define OF_BIAS 102528
#define OF_CW   103040        // transposed c_wout: 4 x 136 fp32 = 2176 B
#define OF_CD   105216        // coord_diff: 128*12*4 = 6144 B
#define SMEM_EDGE_BYTES 111360

// ---------------- node kernel geometry (64 rows/CTA, occ 3) ----------------
#define MN      64
#define NA_OFF  0             // 64*656 = 41984
#define NB_OFF  41984
#define NOF_BIAS 59392
#define SMEM_NODE_BYTES 60544

// ---------------- scratch ----------------
__device__ float g_sumsq[32];
__device__ float g_nagg[N_NODE * HID];
__device__ float g_agg[N_NODE * NC * 3];
__device__ float g_cnt[N_NODE];
// weight images: [K x 128] fp16, row stride 272 B
__device__ __align__(16) unsigned char g_w1t[288 * LDB_B];
__device__ __align__(16) unsigned char g_w2t[128 * LDB_B];
__device__ __align__(16) unsigned char g_w3t[128 * LDB_B];
__device__ __align__(16) unsigned char g_nw1t[256 * LDB_B];
__device__ __align__(16) unsigned char g_nw2t[128 * LDB_B];

__device__ __forceinline__ float silu_f(float x) {
    return __fdividef(x, 1.0f + __expf(-x));
}

__device__ __forceinline__ uint32_t smem_to_u32(const void* p) {
    uint32_t a;
    asm("{ .reg .u64 t; cvta.to.shared.u64 t, %1; cvt.u32.u64 %0, t; }" : "=r"(a) : "l"(p));
    return a;
}
__device__ __forceinline__ void ldm_x4(uint32_t (&r)[4], uint32_t addr) {
    asm volatile("ldmatrix.sync.aligned.m8n8.x4.shared.b16 {%0,%1,%2,%3}, [%4];"
                 : "=r"(r[0]), "=r"(r[1]), "=r"(r[2]), "=r"(r[3]) : "r"(addr));
}
__device__ __forceinline__ void ldm_x4_t(uint32_t (&r)[4], uint32_t addr) {
    asm volatile("ldmatrix.sync.aligned.m8n8.x4.trans.shared.b16 {%0,%1,%2,%3}, [%4];"
                 : "=r"(r[0]), "=r"(r[1]), "=r"(r[2]), "=r"(r[3]) : "r"(addr));
}
__device__ __forceinline__ void mma_f16(float (&d)[4], const uint32_t (&a)[4],
                                        uint32_t b0, uint32_t b1) {
    asm volatile("mma.sync.aligned.m16n8k16.row.col.f32.f16.f16.f32 "
                 "{%0,%1,%2,%3}, {%4,%5,%6,%7}, {%8,%9}, {%0,%1,%2,%3};"
                 : "+f"(d[0]), "+f"(d[1]), "+f"(d[2]), "+f"(d[3])
                 : "r"(a[0]), "r"(a[1]), "r"(a[2]), "r"(a[3]), "r"(b0), "r"(b1));
}

__device__ __forceinline__ uint32_t pack2h(float a, float b) {
    __half2 t = __floats2half2_rn(a, b);
    return *reinterpret_cast<uint32_t*>(&t);
}
__device__ __forceinline__ void store4A(unsigned char* sm, int e, int col, float4 v) {
    uint32_t off = (uint32_t)(e * LDA_B + col * 2);
    *(uint2*)(sm + off) = make_uint2(pack2h(v.x, v.y), pack2h(v.z, v.w));
}

// ============================================================================
// Fused prep (weights -> fp16 images) + sumsq (L2-norm sums over edges).
// ============================================================================
#define PREP_BLOCKS  464
#define SUMSQ_BLOCKS 1184

__global__ void prep_sumsq_kernel(const float* __restrict__ w1,
                                  const float* __restrict__ w2,
                                  const float* __restrict__ w3,
                                  const float* __restrict__ nw1,
                                  const float* __restrict__ nw2,
                                  const float* __restrict__ coord,
                                  const int* __restrict__ row,
                                  const int* __restrict__ col)
{
    int tid = threadIdx.x;
    if (blockIdx.x < PREP_BLOCKS) {
        int idx = blockIdx.x * 256 + tid;
        const float* W; unsigned char* dst; int r;
        if (idx < 36864)       { W = w1;  dst = g_w1t;  r = idx; }
        else if (idx < 53248)  { W = w2;  dst = g_w2t;  r = idx - 36864; }
        else if (idx < 69632)  { W = w3;  dst = g_w3t;  r = idx - 53248; }
        else if (idx < 102400) { W = nw1; dst = g_nw1t; r = idx - 69632; }
        else if (idx < 118784) { W = nw2; dst = g_nw2t; r = idx - 102400; }
        else return;
        int kk = r >> 7, n = r & 127;
        *(__half*)(dst + kk * LDB_B + n * 2) = __float2half_rn(W[kk * 128 + n]);
        return;
    }
    __shared__ float s_sum[32];
    if (tid < 32) s_sum[tid] = 0.0f;
    __syncthreads();
    float p[32];
#pragma unroll
    for (int i = 0; i < 32; i++) p[i] = 0.0f;
    int bid = blockIdx.x - PREP_BLOCKS;
    for (int e = bid * 256 + tid; e < N_EDGE; e += SUMSQ_BLOCKS * 256) {
        const float4* c4i = (const float4*)(coord + row[e] * 12);
        const float4* c4j = (const float4*)(coord + col[e] * 12);
        float4 i0 = c4i[0], i1 = c4i[1], i2 = c4i[2];
        float4 j0 = c4j[0], j1 = c4j[1], j2 = c4j[2];
        float a[12] = {i0.x,i0.y,i0.z,i0.w,i1.x,i1.y,i1.z,i1.w,i2.x,i2.y,i2.z,i2.w};
        float b[12] = {j0.x,j0.y,j0.z,j0.w,j1.x,j1.y,j1.z,j1.w,j2.x,j2.y,j2.z,j2.w};
        float d[12];
#pragma unroll
        for (int i = 0; i < 12; i++) d[i] = a[i] - b[i];
#pragma unroll
        for (int c = 0; c < 4; c++) {
#pragma unroll
            for (int f = 0; f < 4; f++) {
                float r = d[c*3+0]*d[f*3+0] + d[c*3+1]*d[f*3+1] + d[c*3+2]*d[f*3+2];
                float dx = a[c*3+0]-b[f*3+0], dy = a[c*3+1]-b[f*3+1], dz = a[c*3+2]-b[f*3+2];
                float d2 = dx*dx + dy*dy + dz*dz;
                p[c*8 + f]     += r * r;
                p[c*8 + 4 + f] += d2;
            }
        }
    }
#pragma unroll
    for (int i = 0; i < 32; i++) atomicAdd(&s_sum[i], p[i]);
    __syncthreads();
    if (tid < 32) atomicAdd(&g_sumsq[tid], s_sum[tid]);
}

// ============================================================================
// Shared staging helpers
// ============================================================================
#define NSTG 5   // ceil(1088 / 256)

__device__ __forceinline__ void ld_stageN(uint4 (&stg)[NSTG],
                                          const unsigned char* __restrict__ wsrc,
                                          int byteoff, int n4, int tid)
{
    const uint4* s = (const uint4*)(wsrc + byteoff);
#pragma unroll
    for (int i = 0; i < NSTG; i++) {
        int idx = tid + i * ETHREADS;
        if (idx < n4) stg[i] = s[idx];
    }
}

// ============================================================================
// EDGE GEMM: 8 warps in 4x2 grid, warp tile 32 rows x 64 cols, acc[2][8][4].
// ============================================================================
template <int KTOT>
__device__ __forceinline__ void run_gemm_e(
    unsigned char* sm, uint32_t smem_base, float (&acc)[2][8][4],
    int a_col_base, const unsigned char* __restrict__ wsrc,
    int tid, int lane, int r0, int n0)
{
#pragma unroll
    for (int mt = 0; mt < 2; mt++)
#pragma unroll
        for (int nb = 0; nb < 8; nb++)
#pragma unroll
            for (int i = 0; i < 4; i++) acc[mt][nb][i] = 0.0f;

    uint4 stg[NSTG];
    constexpr int R0 = (KTOT < 64) ? KTOT : 64;
    ld_stageN(stg, wsrc, 0, R0 * 17, tid);

#pragma unroll
    for (int k0 = 0; k0 < KTOT; k0 += 64) {
        const int rows = (KTOT - k0 < 64) ? (KTOT - k0) : 64;
        const int cn4 = rows * 17;
        __syncthreads();
        {
            uint4* db = (uint4*)(sm + B_OFF);
#pragma unroll
            for (int i = 0; i < NSTG; i++) {
                int idx = tid + i * ETHREADS;
                if (idx < cn4) db[idx] = stg[i];
            }
        }
        __syncthreads();
        if (k0 + 64 < KTOT) {
            const int nrows = (KTOT - k0 - 64 < 64) ? (KTOT - k0 - 64) : 64;
            ld_stageN(stg, wsrc, (k0 + 64) * LDB_B, nrows * 17, tid);
        }
        const int nks = rows >> 4;
#pragma unroll
        for (int ks = 0; ks < 4; ks++) {
            if (ks >= nks) break;
            int kcol = a_col_base + k0 + ks * 16;
            uint32_t ah[2][4];
            uint32_t a_off = (uint32_t)((r0 + (lane & 15)) * LDA_B + (kcol + (lane >> 4) * 8) * 2);
            ldm_x4(ah[0], smem_base + A_OFF + a_off);
            ldm_x4(ah[1], smem_base + A_OFF + a_off + 16 * LDA_B);
            uint32_t bh[4][4];
            uint32_t b_off = (uint32_t)((ks * 16 + (lane & 15)) * LDB_B + (n0 + (lane >> 4) * 8) * 2);
#pragma unroll
            for (int nt = 0; nt < 4; nt++)
                ldm_x4_t(bh[nt], smem_base + B_OFF + b_off + nt * 32);
#pragma unroll
            for (int mt = 0; mt < 2; mt++)
#pragma unroll
                for (int nt = 0; nt < 4; nt++) {
                    mma_f16(acc[mt][2*nt],   ah[mt], bh[nt][0], bh[nt][1]);
                    mma_f16(acc[mt][2*nt+1], ah[mt], bh[nt][2], bh[nt][3]);
                }
        }
    }
    __syncthreads();
}

__device__ __forceinline__ void epi_store_e(
    unsigned char* sm, float (&acc)[2][8][4], const float* __restrict__ SBIAS,
    int dstbase, int lane, int r0, int n0, const int* __restrict__ SROW, bool do_nagg)
{
#pragma unroll
    for (int mt = 0; mt < 2; mt++) {
        int ra = r0 + mt * 16 + (lane >> 2);
        int rb = ra + 8;
#pragma unroll
        for (int nb = 0; nb < 8; nb++) {
            int c = n0 + nb * 8 + (lane & 3) * 2;
            float b0 = SBIAS[c], b1 = SBIAS[c + 1];
            float v0 = silu_f(acc[mt][nb][0] + b0);
            float v1 = silu_f(acc[mt][nb][1] + b1);
            float v2 = silu_f(acc[mt][nb][2] + b0);
            float v3 = silu_f(acc[mt][nb][3] + b1);
            uint32_t oa = (uint32_t)(ra * LDA_B + (dstbase + c) * 2);
            uint32_t ob = (uint32_t)(rb * LDA_B + (dstbase + c) * 2);
            *(uint32_t*)(sm + oa) = pack2h(v0, v1);
            *(uint32_t*)(sm + ob) = pack2h(v2, v3);
            if (do_nagg) {
                float* pa = g_nagg + (size_t)SROW[ra] * HID + c;
                float* pb = g_nagg + (size_t)SROW[rb] * HID + c;
                asm volatile("red.global.add.v2.f32 [%0], {%1,%2};"
                             :: "l"(pa), "f"(v0), "f"(v1) : "memory");
                asm volatile("red.global.add.v2.f32 [%0], {%1,%2};"
                             :: "l"(pb), "f"(v2), "f"(v3) : "memory");
            }
        }
    }
}

// ============================================================================
// Fused edge kernel: 128 edges / CTA, 256 threads, 8 warps (4x2), 2 CTAs/SM.
// ============================================================================
__global__ void __launch_bounds__(ETHREADS, 2)
edge_kernel(const float* __restrict__ h, const float* __restrict__ coord,
            const int* __restrict__ row, const int* __restrict__ col,
            const float* __restrict__ e_b1, const float* __restrict__ e_b2,
            const float* __restrict__ c_b1, const float* __restrict__ c_wout)
{
    extern __shared__ unsigned char sm[];
    const int tid  = threadIdx.x;
    const int wid  = tid >> 5;
    const int lane = tid & 31;
    const int e0   = blockIdx.x * ME;
    uint32_t smem_base = smem_to_u32(sm);

    int*   SROW  = (int*)(sm + OF_ROW);
    int*   SCOL  = (int*)(sm + OF_COL);
    float* SINV  = (float*)(sm + OF_INV);
    float* SBIAS = (float*)(sm + OF_BIAS);
    float* SCWT  = (float*)(sm + OF_CW);    // [4][136] transposed c_wout
    float* SCD   = (float*)(sm + OF_CD);

    if (tid < ME)  { SROW[tid] = row[e0 + tid]; SCOL[tid] = col[e0 + tid]; }
    if (tid < 32)  SINV[tid] = 1.0f / fmaxf(sqrtf(g_sumsq[tid]), 1e-12f);
    {   // transpose c_wout [128][4] -> SCWT [4][136]
        int k = tid >> 1, half = tid & 1;
        float2 v = ((const float2*)c_wout)[tid];
        SCWT[(half * 2 + 0) * 136 + k] = v.x;
        SCWT[(half * 2 + 1) * 136 + k] = v.y;
    }
    __syncthreads();

    // ---- gather h[row]|h[col] into A cols 0..255 (fp16) ----
#pragma unroll 4
    for (int idx = tid; idx < ME * 64; idx += ETHREADS) {
        int e = idx >> 6, p4 = idx & 63;
        int half = p4 >> 5, q = p4 & 31;
        int node = half ? SCOL[e] : SROW[e];
        float4 v = ((const float4*)(h + node * HID))[q];
        store4A(sm, e, half * 128 + q * 4, v);
    }
    // ---- rad features cols 256..287; coord_diff to SCD ----
    if (tid < ME) {
        int e = tid;
        const float4* c4i = (const float4*)(coord + SROW[e] * 12);
        const float4* c4j = (const float4*)(coord + SCOL[e] * 12);
        float4 i0 = c4i[0], i1 = c4i[1], i2 = c4i[2];
        float4 j0 = c4j[0], j1 = c4j[1], j2 = c4j[2];
        float a[12] = {i0.x,i0.y,i0.z,i0.w,i1.x,i1.y,i1.z,i1.w,i2.x,i2.y,i2.z,i2.w};
        float b[12] = {j0.x,j0.y,j0.z,j0.w,j1.x,j1.y,j1.z,j1.w,j2.x,j2.y,j2.z,j2.w};
        float d[12];
#pragma unroll
        for (int i = 0; i < 12; i++) { d[i] = a[i] - b[i]; SCD[e * 12 + i] = d[i]; }
        float radv[32];
#pragma unroll
        for (int c = 0; c < 4; c++) {
#pragma unroll
            for (int f = 0; f < 4; f++) {
                float r = d[c*3+0]*d[f*3+0] + d[c*3+1]*d[f*3+1] + d[c*3+2]*d[f*3+2];
                float dx = a[c*3+0]-b[f*3+0], dy = a[c*3+1]-b[f*3+1], dz = a[c*3+2]-b[f*3+2];
                float d2 = dx*dx + dy*dy + dz*dz;
                radv[c*8 + f]     = r * SINV[c*8 + f];
                radv[c*8 + 4 + f] = sqrtf(d2) * SINV[c*8 + 4 + f];
            }
        }
#pragma unroll
        for (int q = 0; q < 32; q += 4)
            store4A(sm, e, 256 + q, make_float4(radv[q], radv[q+1], radv[q+2], radv[q+3]));
    }

    const int wm = wid & 3, wn = wid >> 2;
    const int r0 = wm * 32, n0 = wn * 64;
    float acc[2][8][4];

    // ========== GEMM1: t1 = silu(eh @ W1 + b1) -> A cols 0..127 (K=288) ===
    if (tid < 128) SBIAS[tid] = e_b1[tid];
    run_gemm_e<288>(sm, smem_base, acc, 0, g_w1t, tid, lane, r0, n0);
    epi_store_e(sm, acc, SBIAS, 0, lane, r0, n0, SROW, false);
    __syncthreads();

    // ========== GEMM2: m = silu(t1 @ W2 + b2) -> A cols 128..255, nagg ====
    if (tid < 128) SBIAS[tid] = e_b2[tid];
    __syncthreads();
    run_gemm_e<128>(sm, smem_base, acc, 0, g_w2t, tid, lane, r0, n0);
    epi_store_e(sm, acc, SBIAS, 128, lane, r0, n0, SROW, true);
    __syncthreads();

    // ========== GEMM3: t2 = silu(m @ c_w1 + b) -> fp32 buffer =============
    if (tid < 128) SBIAS[tid] = c_b1[tid];
    __syncthreads();
    run_gemm_e<128>(sm, smem_base, acc, 128, g_w3t, tid, lane, r0, n0);
    {
        float* t2f = (float*)sm;            // [128 x 132] fp32; A done after GEMM3
#pragma unroll
        for (int mt = 0; mt < 2; mt++) {
            int ra = r0 + mt * 16 + (lane >> 2);
            int rb = ra + 8;
#pragma unroll
            for (int nb = 0; nb < 8; nb++) {
                int c = n0 + nb * 8 + (lane & 3) * 2;
                float b0 = SBIAS[c], b1 = SBIAS[c + 1];
                *(float2*)(t2f + ra * 132 + c) =
                    make_float2(silu_f(acc[mt][nb][0] + b0), silu_f(acc[mt][nb][1] + b1));
                *(float2*)(t2f + rb * 132 + c) =
                    make_float2(silu_f(acc[mt][nb][2] + b0), silu_f(acc[mt][nb][3] + b1));
            }
        }
    }
    __syncthreads();

    // ========== w = t2 @ c_wout (float4 dot); coord atomics ===============
#pragma unroll
    for (int u = tid; u < ME * 4; u += ETHREADS) {
        int e = u >> 2, c = u & 3;
        const float4* tr4 = (const float4*)((const float*)sm + e * 132);
        const float4* cw4 = (const float4*)(SCWT + c * 136);
        float w = 0.0f;
#pragma unroll
        for (int i = 0; i < 32; i++) {
            float4 t = tr4[i], uq = cw4[i];
            w += t.x * uq.x + t.y * uq.y + t.z * uq.z + t.w * uq.w;
        }
        int node = SROW[e];
        const float* cd = SCD + e * 12 + c * 3;
        atomicAdd(&g_agg[node * 12 + c * 3 + 0], cd[0] * w);
        atomicAdd(&g_agg[node * 12 + c * 3 + 1], cd[1] * w);
        atomicAdd(&g_agg[node * 12 + c * 3 + 2], cd[2] * w);
        if (c == 0) atomicAdd(&g_cnt[node], 1.0f);
    }
}

// ============================================================================
// NODE GEMM machinery (64 rows/CTA, 2x4 warp grid, warp tile 32x32)
// ============================================================================
template <int KTOT>
__device__ __forceinline__ void run_gemm_n(
    unsigned char* sm, uint32_t smem_base, float (&acc)[2][4][4],
    int a_col_base, const unsigned char* __restrict__ wsrc,
    int tid, int lane, int r0, int n0)
{
#pragma unroll
    for (int mt = 0; mt < 2; mt++)
#pragma unroll
        for (int nb = 0; nb < 4; nb++)
#pragma unroll
            for (int i = 0; i < 4; i++) acc[mt][nb][i] = 0.0f;

    uint4 stg[NSTG];
    constexpr int R0 = (KTOT < 64) ? KTOT : 64;
    ld_stageN(stg, wsrc, 0, R0 * 17, tid);

#pragma unroll
    for (int k0 = 0; k0 < KTOT; k0 += 64) {
        const int rows = (KTOT - k0 < 64) ? (KTOT - k0) : 64;
        const int cn4 = rows * 17;
        __syncthreads();
        {
            uint4* db = (uint4*)(sm + NB_OFF);
#pragma unroll
            for (int i = 0; i < NSTG; i++) {
                int idx = tid + i * ETHREADS;
                if (idx < cn4) db[idx] = stg[i];
            }
        }
        __syncthreads();
        if (k0 + 64 < KTOT) {
            const int nrows = (KTOT - k0 - 64 < 64) ? (KTOT - k0 - 64) : 64;
            ld_stageN(stg, wsrc, (k0 + 64) * LDB_B, nrows * 17, tid);
        }
        const int nks = rows >> 4;
#pragma unroll
        for (int ks = 0; ks < 4; ks++) {
            if (ks >= nks) break;
            int kcol = a_col_base + k0 + ks * 16;
            uint32_t ah[2][4];
            uint32_t a_off = (uint32_t)((r0 + (lane & 15)) * LDA_B + (kcol + (lane >> 4) * 8) * 2);
            ldm_x4(ah[0], smem_base + NA_OFF + a_off);
            ldm_x4(ah[1], smem_base + NA_OFF + a_off + 16 * LDA_B);
            uint32_t bh[2][4];
            uint32_t b_off = (uint32_t)((ks * 16 + (lane & 15)) * LDB_B + (n0 + (lane >> 4) * 8) * 2);
#pragma unroll
            for (int nt = 0; nt < 2; nt++)
                ldm_x4_t(bh[nt], smem_base + NB_OFF + b_off + nt * 32);
#pragma unroll
            for (int mt = 0; mt < 2; mt++)
#pragma unroll
                for (int nt = 0; nt < 2; nt++) {
                    mma_f16(acc[mt][2*nt],   ah[mt], bh[nt][0], bh[nt][1]);
                    mma_f16(acc[mt][2*nt+1], ah[mt], bh[nt][2], bh[nt][3]);
                }
        }
    }
    __syncthreads();
}

__global__ void __launch_bounds__(ETHREADS, 3)
node_kernel(const float* __restrict__ h, const float* __restrict__ coord,
            const float* __restrict__ n_b1, const float* __restrict__ n_b2,
            float* __restrict__ out_h, float* __restrict__ out_coord)
{
    extern __shared__ unsigned char sm[];
    const int tid  = threadIdx.x;
    const int wid  = tid >> 5;
    const int lane = tid & 31;
    const int nb0  = blockIdx.x * MN;
    uint32_t smem_base = smem_to_u32(sm);
    float* SBIAS = (float*)(sm + NOF_BIAS);

    // ---- gather h[n] | nagg[n] into A cols 0..255 (fp16) ----
#pragma unroll 4
    for (int idx = tid; idx < MN * 64; idx += ETHREADS) {
        int r = idx >> 6, p4 = idx & 63;
        int half = p4 >> 5, q = p4 & 31;
        int n = nb0 + r;
        float4 v = make_float4(0.f, 0.f, 0.f, 0.f);
        if (n < N_NODE)
            v = half ? ((const float4*)(g_nagg + n * HID))[q]
                     : ((const float4*)(h + n * HID))[q];
        store4A(sm, r, half * 128 + q * 4, v);
    }

    const int wm = wid & 1, wn = wid >> 1;
    const int r0 = wm * 32, n0 = wn * 32;
    float acc[2][4][4];

    // ========== GEMM1: t = silu(nin @ nW1 + b1) -> A cols 0..127 ==========
    if (tid < 128) SBIAS[tid] = n_b1[tid];
    run_gemm_n<256>(sm, smem_base, acc, 0, g_nw1t, tid, lane, r0, n0);
    {
#pragma unroll
        for (int mt = 0; mt < 2; mt++) {
            int ra = r0 + mt * 16 + (lane >> 2);
            int rb = ra + 8;
#pragma unroll
            for (int nb = 0; nb < 4; nb++) {
                int c = n0 + nb * 8 + (lane & 3) * 2;
                float b0 = SBIAS[c], b1 = SBIAS[c + 1];
                *(uint32_t*)(sm + ra * LDA_B + c * 2) =
                    pack2h(silu_f(acc[mt][nb][0] + b0), silu_f(acc[mt][nb][1] + b1));
                *(uint32_t*)(sm + rb * LDA_B + c * 2) =
                    pack2h(silu_f(acc[mt][nb][2] + b0), silu_f(acc[mt][nb][3] + b1));
            }
        }
    }
    __syncthreads();

    // ========== GEMM2: hn = t @ nW2 + b2 ; out_h = h + hn =================
    if (tid < 128) SBIAS[tid] = n_b2[tid];
    __syncthreads();
    run_gemm_n<128>(sm, smem_base, acc, 0, g_nw2t, tid, lane, r0, n0);
    {
#pragma unroll
        for (int mt = 0; mt < 2; mt++) {
            int ra = r0 + mt * 16 + (lane >> 2);
            int rb = ra + 8;
            int na = nb0 + ra, nbv = nb0 + rb;
#pragma unroll
            for (int nb = 0; nb < 4; nb++) {
                int c = n0 + nb * 8 + (lane & 3) * 2;
                float b0 = SBIAS[c], b1 = SBIAS[c + 1];
                if (na < N_NODE) {
                    float2 hv = *(const float2*)(h + na * HID + c);
                    *(float2*)(out_h + na * HID + c) =
                        make_float2(acc[mt][nb][0] + b0 + hv.x,
                                    acc[mt][nb][1] + b1 + hv.y);
                }
                if (nbv < N_NODE) {
                    float2 hv = *(const float2*)(h + nbv * HID + c);
                    *(float2*)(out_h + nbv * HID + c) =
                        make_float2(acc[mt][nb][2] + b0 + hv.x,
                                    acc[mt][nb][3] + b1 + hv.y);
                }
            }
        }
    }
    // ---- coord epilogue ----
    for (int idx = tid; idx < MN * 12; idx += ETHREADS) {
        int r = idx / 12, d = idx % 12;
        int n = nb0 + r;
        if (n < N_NODE) {
            float cnt = fmaxf(g_cnt[n], 1.0f);
            out_coord[n * 12 + d] = coord[n * 12 + d] + g_agg[n * 12 + d] / cnt;
        }
    }
}

// ============================================================================
extern "C" void kernel_launch(void* const* d_in, const int* in_sizes, int n_in,
                              void* d_out, int out_size)
{
    const float* h      = (const float*)d_in[0];
    const float* coord  = (const float*)d_in[1];
    const int*   row    = (const int*)d_in[2];
    const int*   col    = (const int*)d_in[3];
    const float* e_w1   = (const float*)d_in[4];
    const float* e_b1   = (const float*)d_in[5];
    const float* e_w2   = (const float*)d_in[6];
    const float* e_b2   = (const float*)d_in[7];
    const float* c_w1   = (const float*)d_in[8];
    const float* c_b1   = (const float*)d_in[9];
    const float* c_wout = (const float*)d_in[10];
    const float* n_w1   = (const float*)d_in[11];
    const float* n_b1   = (const float*)d_in[12];
    const float* n_w2   = (const float*)d_in[13];
    const float* n_b2   = (const float*)d_in[14];

    float* out_h     = (float*)d_out;
    float* out_coord = out_h + N_NODE * HID;

    void *p_sumsq, *p_nagg, *p_agg, *p_cnt;
    cudaGetSymbolAddress(&p_sumsq, g_sumsq);
    cudaGetSymbolAddress(&p_nagg,  g_nagg);
    cudaGetSymbolAddress(&p_agg,   g_agg);
    cudaGetSymbolAddress(&p_cnt,   g_cnt);
    cudaMemsetAsync(p_sumsq, 0, 32 * sizeof(float));
    cudaMemsetAsync(p_nagg,  0, N_NODE * HID * sizeof(float));
    cudaMemsetAsync(p_agg,   0, N_NODE * 12 * sizeof(float));
    cudaMemsetAsync(p_cnt,   0, N_NODE * sizeof(float));

    cudaFuncSetAttribute(edge_kernel, cudaFuncAttributeMaxDynamicSharedMemorySize,
                         SMEM_EDGE_BYTES);
    cudaFuncSetAttribute(node_kernel, cudaFuncAttributeMaxDynamicSharedMemorySize,
                         SMEM_NODE_BYTES);

    prep_sumsq_kernel<<<PREP_BLOCKS + SUMSQ_BLOCKS, 256>>>(
        e_w1, e_w2, c_w1, n_w1, n_w2, coord, row, col);
    edge_kernel<<<N_EDGE / ME, ETHREADS, SMEM_EDGE_BYTES>>>(
        h, coord, row, col, e_b1, e_b2, c_b1, c_wout);
    node_kernel<<<(N_NODE + MN - 1) / MN, ETHREADS, SMEM_NODE_BYTES>>>(
        h, coord, n_b1, n_b2, out_h, out_coord);
}

// round 12
// speedup vs baseline: 2.8817x; 1.0430x over previous
#include <cuda_runtime.h>
#include <cuda_fp16.h>
#include <math.h>
#include <stdint.h>

#define N_NODE 10000
#define N_EDGE 320000
#define HID    128
#define NC     4

// ---------------- edge kernel geometry (ME=128, occ 2) ----------------
#define ME      128           // edges per CTA
#define ETHREADS 256
#define LDA_B   656           // A row stride bytes
#define LDB_B   272           // B row stride bytes (136 fp16)
#define CHB     8704          // B chunk: 32 k-rows * 272 B
#define A_OFF   0             // fp16 A image: 128*656 = 83968 B
#define B_OFF   83968         // two ping-pong chunks: 2*8704 = 17408
#define OF_ROW  101376
#define OF_COL  101888
#define OF_INV  102400
#define OF_BIAS 102528
#define OF_CW   103040        // transposed c_wout: 4 x 136 fp32 = 2176 B
#define OF_CD   105216        // coord_diff: 128*12*4 = 6144 B
#define SMEM_EDGE_BYTES 111360

// ---------------- node kernel geometry (64 rows/CTA, occ 3) ----------------
#define MN      64
#define NA_OFF  0             // 64*656 = 41984
#define NB_OFF  41984
#define NOF_BIAS 59392
#define SMEM_NODE_BYTES 60544

// ---------------- scratch ----------------
__device__ float g_sumsq[32];
__device__ float g_nagg[N_NODE * HID];
__device__ float g_agg[N_NODE * NC * 3];
__device__ float g_cnt[N_NODE];
// weight images: [K x 128] fp16, row stride 272 B
__device__ __align__(16) unsigned char g_w1t[288 * LDB_B];
__device__ __align__(16) unsigned char g_w2t[128 * LDB_B];
__device__ __align__(16) unsigned char g_w3t[128 * LDB_B];
__device__ __align__(16) unsigned char g_nw1t[256 * LDB_B];
__device__ __align__(16) unsigned char g_nw2t[128 * LDB_B];

__device__ __forceinline__ float silu_f(float x) {
    return __fdividef(x, 1.0f + __expf(-x));
}

__device__ __forceinline__ uint32_t smem_to_u32(const void* p) {
    uint32_t a;
    asm("{ .reg .u64 t; cvta.to.shared.u64 t, %1; cvt.u32.u64 %0, t; }" : "=r"(a) : "l"(p));
    return a;
}
__device__ __forceinline__ void ldm_x4(uint32_t (&r)[4], uint32_t addr) {
    asm volatile("ldmatrix.sync.aligned.m8n8.x4.shared.b16 {%0,%1,%2,%3}, [%4];"
                 : "=r"(r[0]), "=r"(r[1]), "=r"(r[2]), "=r"(r[3]) : "r"(addr));
}
__device__ __forceinline__ void ldm_x4_t(uint32_t (&r)[4], uint32_t addr) {
    asm volatile("ldmatrix.sync.aligned.m8n8.x4.trans.shared.b16 {%0,%1,%2,%3}, [%4];"
                 : "=r"(r[0]), "=r"(r[1]), "=r"(r[2]), "=r"(r[3]) : "r"(addr));
}
__device__ __forceinline__ void mma_f16(float (&d)[4], const uint32_t (&a)[4],
                                        uint32_t b0, uint32_t b1) {
    asm volatile("mma.sync.aligned.m16n8k16.row.col.f32.f16.f16.f32 "
                 "{%0,%1,%2,%3}, {%4,%5,%6,%7}, {%8,%9}, {%0,%1,%2,%3};"
                 : "+f"(d[0]), "+f"(d[1]), "+f"(d[2]), "+f"(d[3])
                 : "r"(a[0]), "r"(a[1]), "r"(a[2]), "r"(a[3]), "r"(b0), "r"(b1));
}
__device__ __forceinline__ void cp_async16(uint32_t dst, const void* src) {
    asm volatile("cp.async.cg.shared.global [%0], [%1], 16;" :: "r"(dst), "l"(src));
}
#define CP_COMMIT() asm volatile("cp.async.commit_group;" ::: "memory")
#define CP_WAIT0()  asm volatile("cp.async.wait_group 0;" ::: "memory")

__device__ __forceinline__ uint32_t pack2h(float a, float b) {
    __half2 t = __floats2half2_rn(a, b);
    return *reinterpret_cast<uint32_t*>(&t);
}
__device__ __forceinline__ void store4A(unsigned char* sm, int e, int col, float4 v) {
    uint32_t off = (uint32_t)(e * LDA_B + col * 2);
    *(uint2*)(sm + off) = make_uint2(pack2h(v.x, v.y), pack2h(v.z, v.w));
}

// ============================================================================
// Fused prep (weights -> fp16 images) + sumsq (L2-norm sums over edges).
// ============================================================================
#define PREP_BLOCKS  464
#define SUMSQ_BLOCKS 1184

__global__ void prep_sumsq_kernel(const float* __restrict__ w1,
                                  const float* __restrict__ w2,
                                  const float* __restrict__ w3,
                                  const float* __restrict__ nw1,
                                  const float* __restrict__ nw2,
                                  const float* __restrict__ coord,
                                  const int* __restrict__ row,
                                  const int* __restrict__ col)
{
    int tid = threadIdx.x;
    if (blockIdx.x < PREP_BLOCKS) {
        int idx = blockIdx.x * 256 + tid;
        const float* W; unsigned char* dst; int r;
        if (idx < 36864)       { W = w1;  dst = g_w1t;  r = idx; }
        else if (idx < 53248)  { W = w2;  dst = g_w2t;  r = idx - 36864; }
        else if (idx < 69632)  { W = w3;  dst = g_w3t;  r = idx - 53248; }
        else if (idx < 102400) { W = nw1; dst = g_nw1t; r = idx - 69632; }
        else if (idx < 118784) { W = nw2; dst = g_nw2t; r = idx - 102400; }
        else return;
        int kk = r >> 7, n = r & 127;
        *(__half*)(dst + kk * LDB_B + n * 2) = __float2half_rn(W[kk * 128 + n]);
        return;
    }
    __shared__ float s_sum[32];
    if (tid < 32) s_sum[tid] = 0.0f;
    __syncthreads();
    float p[32];
#pragma unroll
    for (int i = 0; i < 32; i++) p[i] = 0.0f;
    int bid = blockIdx.x - PREP_BLOCKS;
    for (int e = bid * 256 + tid; e < N_EDGE; e += SUMSQ_BLOCKS * 256) {
        const float4* c4i = (const float4*)(coord + row[e] * 12);
        const float4* c4j = (const float4*)(coord + col[e] * 12);
        float4 i0 = c4i[0], i1 = c4i[1], i2 = c4i[2];
        float4 j0 = c4j[0], j1 = c4j[1], j2 = c4j[2];
        float a[12] = {i0.x,i0.y,i0.z,i0.w,i1.x,i1.y,i1.z,i1.w,i2.x,i2.y,i2.z,i2.w};
        float b[12] = {j0.x,j0.y,j0.z,j0.w,j1.x,j1.y,j1.z,j1.w,j2.x,j2.y,j2.z,j2.w};
        float d[12];
#pragma unroll
        for (int i = 0; i < 12; i++) d[i] = a[i] - b[i];
#pragma unroll
        for (int c = 0; c < 4; c++) {
#pragma unroll
            for (int f = 0; f < 4; f++) {
                float r = d[c*3+0]*d[f*3+0] + d[c*3+1]*d[f*3+1] + d[c*3+2]*d[f*3+2];
                float dx = a[c*3+0]-b[f*3+0], dy = a[c*3+1]-b[f*3+1], dz = a[c*3+2]-b[f*3+2];
                float d2 = dx*dx + dy*dy + dz*dz;
                p[c*8 + f]     += r * r;
                p[c*8 + 4 + f] += d2;
            }
        }
    }
#pragma unroll
    for (int i = 0; i < 32; i++) atomicAdd(&s_sum[i], p[i]);
    __syncthreads();
    if (tid < 32) atomicAdd(&g_sumsq[tid], s_sum[tid]);
}

// ============================================================================
// cp.async staging of one 32-row B chunk (8704 B = 544 x 16B)
// ============================================================================
__device__ __forceinline__ void cp_issue_chunk(uint32_t dst,
                                               const unsigned char* __restrict__ src,
                                               int tid)
{
#pragma unroll
    for (int i = 0; i < 3; i++) {
        int idx = tid + i * ETHREADS;
        if (idx < CHB / 16) cp_async16(dst + idx * 16, src + idx * 16);
    }
}

// ============================================================================
// EDGE GEMM: 8 warps in 4x2 grid, warp tile 32 rows x 64 cols, acc[2][8][4].
// cp.async double-buffered B (32-row chunks), one barrier per chunk.
// ============================================================================
template <int KTOT>
__device__ __forceinline__ void run_gemm_e(
    unsigned char* sm, uint32_t smem_base, float (&acc)[2][8][4],
    int a_col_base, const unsigned char* __restrict__ wsrc,
    int tid, int lane, int r0, int n0)
{
#pragma unroll
    for (int mt = 0; mt < 2; mt++)
#pragma unroll
        for (int nb = 0; nb < 8; nb++)
#pragma unroll
            for (int i = 0; i < 4; i++) acc[mt][nb][i] = 0.0f;

    constexpr int NCH = KTOT / 32;
    cp_issue_chunk(smem_base + B_OFF, wsrc, tid);
    CP_COMMIT();

#pragma unroll
    for (int c = 0; c < NCH; c++) {
        CP_WAIT0();
        __syncthreads();        // chunk c visible; all warps done with buf (c+1)&1
        if (c + 1 < NCH) {
            cp_issue_chunk(smem_base + B_OFF + ((c + 1) & 1) * CHB,
                           wsrc + (c + 1) * CHB, tid);
            CP_COMMIT();
        }
        uint32_t bbase = smem_base + B_OFF + (c & 1) * CHB;
#pragma unroll
        for (int ks = 0; ks < 2; ks++) {
            int kcol = a_col_base + c * 32 + ks * 16;
            uint32_t ah[2][4];
            uint32_t a_off = (uint32_t)((r0 + (lane & 15)) * LDA_B + (kcol + (lane >> 4) * 8) * 2);
            ldm_x4(ah[0], smem_base + A_OFF + a_off);
            ldm_x4(ah[1], smem_base + A_OFF + a_off + 16 * LDA_B);
            uint32_t bh[4][4];
            uint32_t b_off = (uint32_t)((ks * 16 + (lane & 15)) * LDB_B + (n0 + (lane >> 4) * 8) * 2);
#pragma unroll
            for (int nt = 0; nt < 4; nt++)
                ldm_x4_t(bh[nt], bbase + b_off + nt * 32);
#pragma unroll
            for (int mt = 0; mt < 2; mt++)
#pragma unroll
                for (int nt = 0; nt < 4; nt++) {
                    mma_f16(acc[mt][2*nt],   ah[mt], bh[nt][0], bh[nt][1]);
                    mma_f16(acc[mt][2*nt+1], ah[mt], bh[nt][2], bh[nt][3]);
                }
        }
    }
    __syncthreads();   // last chunk's MMAs complete in all warps before A reuse
}

// bias + silu + fp16-store to A cols [dstbase, dstbase+128)
__device__ __forceinline__ void epi_store_e(
    unsigned char* sm, float (&acc)[2][8][4], const float* __restrict__ SBIAS,
    int dstbase, int lane, int r0, int n0)
{
#pragma unroll
    for (int mt = 0; mt < 2; mt++) {
        int ra = r0 + mt * 16 + (lane >> 2);
        int rb = ra + 8;
#pragma unroll
        for (int nb = 0; nb < 8; nb++) {
            int c = n0 + nb * 8 + (lane & 3) * 2;
            float b0 = SBIAS[c], b1 = SBIAS[c + 1];
            float v0 = silu_f(acc[mt][nb][0] + b0);
            float v1 = silu_f(acc[mt][nb][1] + b1);
            float v2 = silu_f(acc[mt][nb][2] + b0);
            float v3 = silu_f(acc[mt][nb][3] + b1);
            *(uint32_t*)(sm + ra * LDA_B + (dstbase + c) * 2) = pack2h(v0, v1);
            *(uint32_t*)(sm + rb * LDA_B + (dstbase + c) * 2) = pack2h(v2, v3);
        }
    }
}

// ============================================================================
// Fused edge kernel: 128 edges / CTA, 256 threads, 8 warps (4x2), 2 CTAs/SM.
// ============================================================================
__global__ void __launch_bounds__(ETHREADS, 2)
edge_kernel(const float* __restrict__ h, const float* __restrict__ coord,
            const int* __restrict__ row, const int* __restrict__ col,
            const float* __restrict__ e_b1, const float* __restrict__ e_b2,
            const float* __restrict__ c_b1, const float* __restrict__ c_wout)
{
    extern __shared__ unsigned char sm[];
    const int tid  = threadIdx.x;
    const int wid  = tid >> 5;
    const int lane = tid & 31;
    const int e0   = blockIdx.x * ME;
    uint32_t smem_base = smem_to_u32(sm);

    int*   SROW  = (int*)(sm + OF_ROW);
    int*   SCOL  = (int*)(sm + OF_COL);
    float* SINV  = (float*)(sm + OF_INV);
    float* SBIAS = (float*)(sm + OF_BIAS);
    float* SCWT  = (float*)(sm + OF_CW);    // [4][136] transposed c_wout
    float* SCD   = (float*)(sm + OF_CD);

    if (tid < ME)  { SROW[tid] = row[e0 + tid]; SCOL[tid] = col[e0 + tid]; }
    if (tid < 32)  SINV[tid] = 1.0f / fmaxf(sqrtf(g_sumsq[tid]), 1e-12f);
    {   // transpose c_wout [128][4] -> SCWT [4][136]
        int k = tid >> 1, half = tid & 1;
        float2 v = ((const float2*)c_wout)[tid];
        SCWT[(half * 2 + 0) * 136 + k] = v.x;
        SCWT[(half * 2 + 1) * 136 + k] = v.y;
    }
    __syncthreads();

    // ---- gather h[row]|h[col] into A cols 0..255 (fp16) ----
#pragma unroll 4
    for (int idx = tid; idx < ME * 64; idx += ETHREADS) {
        int e = idx >> 6, p4 = idx & 63;
        int half = p4 >> 5, q = p4 & 31;
        int node = half ? SCOL[e] : SROW[e];
        float4 v = ((const float4*)(h + node * HID))[q];
        store4A(sm, e, half * 128 + q * 4, v);
    }
    // ---- rad features cols 256..287; coord_diff to SCD ----
    if (tid < ME) {
        int e = tid;
        const float4* c4i = (const float4*)(coord + SROW[e] * 12);
        const float4* c4j = (const float4*)(coord + SCOL[e] * 12);
        float4 i0 = c4i[0], i1 = c4i[1], i2 = c4i[2];
        float4 j0 = c4j[0], j1 = c4j[1], j2 = c4j[2];
        float a[12] = {i0.x,i0.y,i0.z,i0.w,i1.x,i1.y,i1.z,i1.w,i2.x,i2.y,i2.z,i2.w};
        float b[12] = {j0.x,j0.y,j0.z,j0.w,j1.x,j1.y,j1.z,j1.w,j2.x,j2.y,j2.z,j2.w};
        float d[12];
#pragma unroll
        for (int i = 0; i < 12; i++) { d[i] = a[i] - b[i]; SCD[e * 12 + i] = d[i]; }
        float radv[32];
#pragma unroll
        for (int c = 0; c < 4; c++) {
#pragma unroll
            for (int f = 0; f < 4; f++) {
                float r = d[c*3+0]*d[f*3+0] + d[c*3+1]*d[f*3+1] + d[c*3+2]*d[f*3+2];
                float dx = a[c*3+0]-b[f*3+0], dy = a[c*3+1]-b[f*3+1], dz = a[c*3+2]-b[f*3+2];
                float d2 = dx*dx + dy*dy + dz*dz;
                radv[c*8 + f]     = r * SINV[c*8 + f];
                radv[c*8 + 4 + f] = sqrtf(d2) * SINV[c*8 + 4 + f];
            }
        }
#pragma unroll
        for (int q = 0; q < 32; q += 4)
            store4A(sm, e, 256 + q, make_float4(radv[q], radv[q+1], radv[q+2], radv[q+3]));
    }

    const int wm = wid & 3, wn = wid >> 2;
    const int r0 = wm * 32, n0 = wn * 64;
    float acc[2][8][4];

    // ========== GEMM1: t1 = silu(eh @ W1 + b1) -> A cols 0..127 (K=288) ===
    if (tid < 128) SBIAS[tid] = e_b1[tid];
    run_gemm_e<288>(sm, smem_base, acc, 0, g_w1t, tid, lane, r0, n0);
    epi_store_e(sm, acc, SBIAS, 0, lane, r0, n0);
    __syncthreads();

    // ========== GEMM2: m = silu(t1 @ W2 + b2) -> A cols 128..255 ==========
    if (tid < 128) SBIAS[tid] = e_b2[tid];
    run_gemm_e<128>(sm, smem_base, acc, 0, g_w2t, tid, lane, r0, n0);
    epi_store_e(sm, acc, SBIAS, 128, lane, r0, n0);
    __syncthreads();

    // ---- nagg scatter: coalesced red.v4 from fp16 m in smem ----
#pragma unroll 4
    for (int idx = tid; idx < ME * 32; idx += ETHREADS) {
        int e = idx >> 5, q = (idx & 31) * 4;
        uint2 hv = *(const uint2*)(sm + e * LDA_B + (128 + q) * 2);
        __half2 p0 = *reinterpret_cast<__half2*>(&hv.x);
        __half2 p1 = *reinterpret_cast<__half2*>(&hv.y);
        float2 f0 = __half22float2(p0), f1 = __half22float2(p1);
        float* dst = g_nagg + (size_t)SROW[e] * HID + q;
        asm volatile("red.global.add.v4.f32 [%0], {%1,%2,%3,%4};"
                     :: "l"(dst), "f"(f0.x), "f"(f0.y), "f"(f1.x), "f"(f1.y)
                     : "memory");
    }

    // ========== GEMM3: t2 = silu(m @ c_w1 + b) -> fp32 buffer =============
    if (tid < 128) SBIAS[tid] = c_b1[tid];
    run_gemm_e<128>(sm, smem_base, acc, 128, g_w3t, tid, lane, r0, n0);
    {
        float* t2f = (float*)sm;            // [128 x 132] fp32; A done after GEMM3
#pragma unroll
        for (int mt = 0; mt < 2; mt++) {
            int ra = r0 + mt * 16 + (lane >> 2);
            int rb = ra + 8;
#pragma unroll
            for (int nb = 0; nb < 8; nb++) {
                int c = n0 + nb * 8 + (lane & 3) * 2;
                float b0 = SBIAS[c], b1 = SBIAS[c + 1];
                *(float2*)(t2f + ra * 132 + c) =
                    make_float2(silu_f(acc[mt][nb][0] + b0), silu_f(acc[mt][nb][1] + b1));
                *(float2*)(t2f + rb * 132 + c) =
                    make_float2(silu_f(acc[mt][nb][2] + b0), silu_f(acc[mt][nb][3] + b1));
            }
        }
    }
    __syncthreads();

    // ========== w = t2 @ c_wout (float4 dot); coord atomics ===============
#pragma unroll
    for (int u = tid; u < ME * 4; u += ETHREADS) {
        int e = u >> 2, c = u & 3;
        const float4* tr4 = (const float4*)((const float*)sm + e * 132);
        const float4* cw4 = (const float4*)(SCWT + c * 136);
        float w = 0.0f;
#pragma unroll
        for (int i = 0; i < 32; i++) {
            float4 t = tr4[i], uq = cw4[i];
            w += t.x * uq.x + t.y * uq.y + t.z * uq.z + t.w * uq.w;
        }
        int node = SROW[e];
        const float* cd = SCD + e * 12 + c * 3;
        atomicAdd(&g_agg[node * 12 + c * 3 + 0], cd[0] * w);
        atomicAdd(&g_agg[node * 12 + c * 3 + 1], cd[1] * w);
        atomicAdd(&g_agg[node * 12 + c * 3 + 2], cd[2] * w);
        if (c == 0) atomicAdd(&g_cnt[node], 1.0f);
    }
}

// ============================================================================
// NODE GEMM machinery (64 rows/CTA, 2x4 warp grid, warp tile 32x32)
// ============================================================================
#define NSTG 5

__device__ __forceinline__ void ld_stageN(uint4 (&stg)[NSTG],
                                          const unsigned char* __restrict__ wsrc,
                                          int byteoff, int n4, int tid)
{
    const uint4* s = (const uint4*)(wsrc + byteoff);
#pragma unroll
    for (int i = 0; i < NSTG; i++) {
        int idx = tid + i * ETHREADS;
        if (idx < n4) stg[i] = s[idx];
    }
}

template <int KTOT>
__device__ __forceinline__ void run_gemm_n(
    unsigned char* sm, uint32_t smem_base, float (&acc)[2][4][4],
    int a_col_base, const unsigned char* __restrict__ wsrc,
    int tid, int lane, int r0, int n0)
{
#pragma unroll
    for (int mt = 0; mt < 2; mt++)
#pragma unroll
        for (int nb = 0; nb < 4; nb++)
#pragma unroll
            for (int i = 0; i < 4; i++) acc[mt][nb][i] = 0.0f;

    uint4 stg[NSTG];
    constexpr int R0 = (KTOT < 64) ? KTOT : 64;
    ld_stageN(stg, wsrc, 0, R0 * 17, tid);

#pragma unroll
    for (int k0 = 0; k0 < KTOT; k0 += 64) {
        const int rows = (KTOT - k0 < 64) ? (KTOT - k0) : 64;
        const int cn4 = rows * 17;
        __syncthreads();
        {
            uint4* db = (uint4*)(sm + NB_OFF);
#pragma unroll
            for (int i = 0; i < NSTG; i++) {
                int idx = tid + i * ETHREADS;
                if (idx < cn4) db[idx] = stg[i];
            }
        }
        __syncthreads();
        if (k0 + 64 < KTOT) {
            const int nrows = (KTOT - k0 - 64 < 64) ? (KTOT - k0 - 64) : 64;
            ld_stageN(stg, wsrc, (k0 + 64) * LDB_B, nrows * 17, tid);
        }
        const int nks = rows >> 4;
#pragma unroll
        for (int ks = 0; ks < 4; ks++) {
            if (ks >= nks) break;
            int kcol = a_col_base + k0 + ks * 16;
            uint32_t ah[2][4];
            uint32_t a_off = (uint32_t)((r0 + (lane & 15)) * LDA_B + (kcol + (lane >> 4) * 8) * 2);
            ldm_x4(ah[0], smem_base + NA_OFF + a_off);
            ldm_x4(ah[1], smem_base + NA_OFF + a_off + 16 * LDA_B);
            uint32_t bh[2][4];
            uint32_t b_off = (uint32_t)((ks * 16 + (lane & 15)) * LDB_B + (n0 + (lane >> 4) * 8) * 2);
#pragma unroll
            for (int nt = 0; nt < 2; nt++)
                ldm_x4_t(bh[nt], smem_base + NB_OFF + b_off + nt * 32);
#pragma unroll
            for (int mt = 0; mt < 2; mt++)
#pragma unroll
                for (int nt = 0; nt < 2; nt++) {
                    mma_f16(acc[mt][2*nt],   ah[mt], bh[nt][0], bh[nt][1]);
                    mma_f16(acc[mt][2*nt+1], ah[mt], bh[nt][2], bh[nt][3]);
                }
        }
    }
    __syncthreads();
}

__global__ void __launch_bounds__(ETHREADS, 3)
node_kernel(const float* __restrict__ h, const float* __restrict__ coord,
            const float* __restrict__ n_b1, const float* __restrict__ n_b2,
            float* __restrict__ out_h, float* __restrict__ out_coord)
{
    extern __shared__ unsigned char sm[];
    const int tid  = threadIdx.x;
    const int wid  = tid >> 5;
    const int lane = tid & 31;
    const int nb0  = blockIdx.x * MN;
    uint32_t smem_base = smem_to_u32(sm);
    float* SBIAS = (float*)(sm + NOF_BIAS);

    // ---- gather h[n] | nagg[n] into A cols 0..255 (fp16) ----
#pragma unroll 4
    for (int idx = tid; idx < MN * 64; idx += ETHREADS) {
        int r = idx >> 6, p4 = idx & 63;
        int half = p4 >> 5, q = p4 & 31;
        int n = nb0 + r;
        float4 v = make_float4(0.f, 0.f, 0.f, 0.f);
        if (n < N_NODE)
            v = half ? ((const float4*)(g_nagg + n * HID))[q]
                     : ((const float4*)(h + n * HID))[q];
        store4A(sm, r, half * 128 + q * 4, v);
    }

    const int wm = wid & 1, wn = wid >> 1;
    const int r0 = wm * 32, n0 = wn * 32;
    float acc[2][4][4];

    // ========== GEMM1: t = silu(nin @ nW1 + b1) -> A cols 0..127 ==========
    if (tid < 128) SBIAS[tid] = n_b1[tid];
    run_gemm_n<256>(sm, smem_base, acc, 0, g_nw1t, tid, lane, r0, n0);
    {
#pragma unroll
        for (int mt = 0; mt < 2; mt++) {
            int ra = r0 + mt * 16 + (lane >> 2);
            int rb = ra + 8;
#pragma unroll
            for (int nb = 0; nb < 4; nb++) {
                int c = n0 + nb * 8 + (lane & 3) * 2;
                float b0 = SBIAS[c], b1 = SBIAS[c + 1];
                *(uint32_t*)(sm + ra * LDA_B + c * 2) =
                    pack2h(silu_f(acc[mt][nb][0] + b0), silu_f(acc[mt][nb][1] + b1));
                *(uint32_t*)(sm + rb * LDA_B + c * 2) =
                    pack2h(silu_f(acc[mt][nb][2] + b0), silu_f(acc[mt][nb][3] + b1));
            }
        }
    }
    __syncthreads();

    // ========== GEMM2: hn = t @ nW2 + b2 ; out_h = h + hn =================
    if (tid < 128) SBIAS[tid] = n_b2[tid];
    run_gemm_n<128>(sm, smem_base, acc, 0, g_nw2t, tid, lane, r0, n0);
    {
#pragma unroll
        for (int mt = 0; mt < 2; mt++) {
            int ra = r0 + mt * 16 + (lane >> 2);
            int rb = ra + 8;
            int na = nb0 + ra, nbv = nb0 + rb;
#pragma unroll
            for (int nb = 0; nb < 4; nb++) {
                int c = n0 + nb * 8 + (lane & 3) * 2;
                float b0 = SBIAS[c], b1 = SBIAS[c + 1];
                if (na < N_NODE) {
                    float2 hv = *(const float2*)(h + na * HID + c);
                    *(float2*)(out_h + na * HID + c) =
                        make_float2(acc[mt][nb][0] + b0 + hv.x,
                                    acc[mt][nb][1] + b1 + hv.y);
                }
                if (nbv < N_NODE) {
                    float2 hv = *(const float2*)(h + nbv * HID + c);
                    *(float2*)(out_h + nbv * HID + c) =
                        make_float2(acc[mt][nb][2] + b0 + hv.x,
                                    acc[mt][nb][3] + b1 + hv.y);
                }
            }
        }
    }
    // ---- coord epilogue ----
    for (int idx = tid; idx < MN * 12; idx += ETHREADS) {
        int r = idx / 12, d = idx % 12;
        int n = nb0 + r;
        if (n < N_NODE) {
            float cnt = fmaxf(g_cnt[n], 1.0f);
            out_coord[n * 12 + d] = coord[n * 12 + d] + g_agg[n * 12 + d] / cnt;
        }
    }
}

// ============================================================================
extern "C" void kernel_launch(void* const* d_in, const int* in_sizes, int n_in,
                              void* d_out, int out_size)
{
    const float* h      = (const float*)d_in[0];
    const float* coord  = (const float*)d_in[1];
    const int*   row    = (const int*)d_in[2];
    const int*   col    = (const int*)d_in[3];
    const float* e_w1   = (const float*)d_in[4];
    const float* e_b1   = (const float*)d_in[5];
    const float* e_w2   = (const float*)d_in[6];
    const float* e_b2   = (const float*)d_in[7];
    const float* c_w1   = (const float*)d_in[8];
    const float* c_b1   = (const float*)d_in[9];
    const float* c_wout = (const float*)d_in[10];
    const float* n_w1   = (const float*)d_in[11];
    const float* n_b1   = (const float*)d_in[12];
    const float* n_w2   = (const float*)d_in[13];
    const float* n_b2   = (const float*)d_in[14];

    float* out_h     = (float*)d_out;
    float* out_coord = out_h + N_NODE * HID;

    void *p_sumsq, *p_nagg, *p_agg, *p_cnt;
    cudaGetSymbolAddress(&p_sumsq, g_sumsq);
    cudaGetSymbolAddress(&p_nagg,  g_nagg);
    cudaGetSymbolAddress(&p_agg,   g_agg);
    cudaGetSymbolAddress(&p_cnt,   g_cnt);
    cudaMemsetAsync(p_sumsq, 0, 32 * sizeof(float));
    cudaMemsetAsync(p_nagg,  0, N_NODE * HID * sizeof(float));
    cudaMemsetAsync(p_agg,   0, N_NODE * 12 * sizeof(float));
    cudaMemsetAsync(p_cnt,   0, N_NODE * sizeof(float));

    cudaFuncSetAttribute(edge_kernel, cudaFuncAttributeMaxDynamicSharedMemorySize,
                         SMEM_EDGE_BYTES);
    cudaFuncSetAttribute(node_kernel, cudaFuncAttributeMaxDynamicSharedMemorySize,
                         SMEM_NODE_BYTES);

    prep_sumsq_kernel<<<PREP_BLOCKS + SUMSQ_BLOCKS, 256>>>(
        e_w1, e_w2, c_w1, n_w1, n_w2, coord, row, col);
    edge_kernel<<<N_EDGE / ME, ETHREADS, SMEM_EDGE_BYTES>>>(
        h, coord, row, col, e_b1, e_b2, c_b1, c_wout);
    node_kernel<<<(N_NODE + MN - 1) / MN, ETHREADS, SMEM_NODE_BYTES>>>(
        h, coord, n_b1, n_b2, out_h, out_coord);
}

// round 13
// speedup vs baseline: 2.9151x; 1.0116x over previous
#include <cuda_runtime.h>
#include <cuda_fp16.h>
#include <math.h>
#include <stdint.h>

#define N_NODE 10000
#define N_EDGE 320000
#define HID    128
#define NC     4

// ---------------- edge kernel geometry (ME=128, 512 thr, occ 2) ------------
#define ME      128           // edges per CTA
#define ETHREADS 512
#define LDA_B   656           // A row stride bytes
#define LDB_B   272           // B row stride bytes (136 fp16)
#define CHB     8704          // B chunk: 32 k-rows * 272 B
#define A_OFF   0             // fp16 A image: 128*656 = 83968 B
#define B_OFF   83968         // two ping-pong chunks: 2*8704 = 17408
#define OF_ROW  101376
#define OF_COL  101888
#define OF_INV  102400
#define OF_BIAS 102528
#define OF_CW   103040        // transposed c_wout: 4 x 136 fp32 = 2176 B
#define OF_CD   105216        // coord_diff: 128*12*4 = 6144 B
#define SMEM_EDGE_BYTES 111360

// ---------------- node kernel geometry (64 rows/CTA, 256 thr, occ 3) -------
#define NTHREADS 256
#define MN      64
#define NA_OFF  0             // 64*656 = 41984
#define NB_OFF  41984
#define NOF_BIAS 59392
#define SMEM_NODE_BYTES 60544

// ---------------- scratch ----------------
__device__ float g_sumsq[32];
__device__ float g_nagg[N_NODE * HID];
__device__ float g_agg[N_NODE * NC * 3];
__device__ float g_cnt[N_NODE];
// weight images: [K x 128] fp16, row stride 272 B
__device__ __align__(16) unsigned char g_w1t[288 * LDB_B];
__device__ __align__(16) unsigned char g_w2t[128 * LDB_B];
__device__ __align__(16) unsigned char g_w3t[128 * LDB_B];
__device__ __align__(16) unsigned char g_nw1t[256 * LDB_B];
__device__ __align__(16) unsigned char g_nw2t[128 * LDB_B];

__device__ __forceinline__ float silu_f(float x) {
    return __fdividef(x, 1.0f + __expf(-x));
}

__device__ __forceinline__ uint32_t smem_to_u32(const void* p) {
    uint32_t a;
    asm("{ .reg .u64 t; cvta.to.shared.u64 t, %1; cvt.u32.u64 %0, t; }" : "=r"(a) : "l"(p));
    return a;
}
__device__ __forceinline__ void ldm_x4(uint32_t (&r)[4], uint32_t addr) {
    asm volatile("ldmatrix.sync.aligned.m8n8.x4.shared.b16 {%0,%1,%2,%3}, [%4];"
                 : "=r"(r[0]), "=r"(r[1]), "=r"(r[2]), "=r"(r[3]) : "r"(addr));
}
__device__ __forceinline__ void ldm_x4_t(uint32_t (&r)[4], uint32_t addr) {
    asm volatile("ldmatrix.sync.aligned.m8n8.x4.trans.shared.b16 {%0,%1,%2,%3}, [%4];"
                 : "=r"(r[0]), "=r"(r[1]), "=r"(r[2]), "=r"(r[3]) : "r"(addr));
}
__device__ __forceinline__ void mma_f16(float (&d)[4], const uint32_t (&a)[4],
                                        uint32_t b0, uint32_t b1) {
    asm volatile("mma.sync.aligned.m16n8k16.row.col.f32.f16.f16.f32 "
                 "{%0,%1,%2,%3}, {%4,%5,%6,%7}, {%8,%9}, {%0,%1,%2,%3};"
                 : "+f"(d[0]), "+f"(d[1]), "+f"(d[2]), "+f"(d[3])
                 : "r"(a[0]), "r"(a[1]), "r"(a[2]), "r"(a[3]), "r"(b0), "r"(b1));
}
__device__ __forceinline__ void cp_async16(uint32_t dst, const void* src) {
    asm volatile("cp.async.cg.shared.global [%0], [%1], 16;" :: "r"(dst), "l"(src));
}
#define CP_COMMIT() asm volatile("cp.async.commit_group;" ::: "memory")
#define CP_WAIT0()  asm volatile("cp.async.wait_group 0;" ::: "memory")

__device__ __forceinline__ uint32_t pack2h(float a, float b) {
    __half2 t = __floats2half2_rn(a, b);
    return *reinterpret_cast<uint32_t*>(&t);
}
__device__ __forceinline__ void store4A(unsigned char* sm, int e, int col, float4 v) {
    uint32_t off = (uint32_t)(e * LDA_B + col * 2);
    *(uint2*)(sm + off) = make_uint2(pack2h(v.x, v.y), pack2h(v.z, v.w));
}

// ============================================================================
// Fused prep (weights -> fp16 images) + sumsq (L2-norm sums over edges).
// ============================================================================
#define PREP_BLOCKS  464
#define SUMSQ_BLOCKS 1184

__global__ void prep_sumsq_kernel(const float* __restrict__ w1,
                                  const float* __restrict__ w2,
                                  const float* __restrict__ w3,
                                  const float* __restrict__ nw1,
                                  const float* __restrict__ nw2,
                                  const float* __restrict__ coord,
                                  const int* __restrict__ row,
                                  const int* __restrict__ col)
{
    int tid = threadIdx.x;
    if (blockIdx.x < PREP_BLOCKS) {
        int idx = blockIdx.x * 256 + tid;
        const float* W; unsigned char* dst; int r;
        if (idx < 36864)       { W = w1;  dst = g_w1t;  r = idx; }
        else if (idx < 53248)  { W = w2;  dst = g_w2t;  r = idx - 36864; }
        else if (idx < 69632)  { W = w3;  dst = g_w3t;  r = idx - 53248; }
        else if (idx < 102400) { W = nw1; dst = g_nw1t; r = idx - 69632; }
        else if (idx < 118784) { W = nw2; dst = g_nw2t; r = idx - 102400; }
        else return;
        int kk = r >> 7, n = r & 127;
        *(__half*)(dst + kk * LDB_B + n * 2) = __float2half_rn(W[kk * 128 + n]);
        return;
    }
    __shared__ float s_sum[32];
    if (tid < 32) s_sum[tid] = 0.0f;
    __syncthreads();
    float p[32];
#pragma unroll
    for (int i = 0; i < 32; i++) p[i] = 0.0f;
    int bid = blockIdx.x - PREP_BLOCKS;
    for (int e = bid * 256 + tid; e < N_EDGE; e += SUMSQ_BLOCKS * 256) {
        const float4* c4i = (const float4*)(coord + row[e] * 12);
        const float4* c4j = (const float4*)(coord + col[e] * 12);
        float4 i0 = c4i[0], i1 = c4i[1], i2 = c4i[2];
        float4 j0 = c4j[0], j1 = c4j[1], j2 = c4j[2];
        float a[12] = {i0.x,i0.y,i0.z,i0.w,i1.x,i1.y,i1.z,i1.w,i2.x,i2.y,i2.z,i2.w};
        float b[12] = {j0.x,j0.y,j0.z,j0.w,j1.x,j1.y,j1.z,j1.w,j2.x,j2.y,j2.z,j2.w};
        float d[12];
#pragma unroll
        for (int i = 0; i < 12; i++) d[i] = a[i] - b[i];
#pragma unroll
        for (int c = 0; c < 4; c++) {
#pragma unroll
            for (int f = 0; f < 4; f++) {
                float r = d[c*3+0]*d[f*3+0] + d[c*3+1]*d[f*3+1] + d[c*3+2]*d[f*3+2];
                float dx = a[c*3+0]-b[f*3+0], dy = a[c*3+1]-b[f*3+1], dz = a[c*3+2]-b[f*3+2];
                float d2 = dx*dx + dy*dy + dz*dz;
                p[c*8 + f]     += r * r;
                p[c*8 + 4 + f] += d2;
            }
        }
    }
#pragma unroll
    for (int i = 0; i < 32; i++) atomicAdd(&s_sum[i], p[i]);
    __syncthreads();
    if (tid < 32) atomicAdd(&g_sumsq[tid], s_sum[tid]);
}

// ============================================================================
// cp.async staging of one 32-row B chunk (8704 B = 544 x 16B), 512 threads
// ============================================================================
__device__ __forceinline__ void cp_issue_chunk(uint32_t dst,
                                               const unsigned char* __restrict__ src,
                                               int tid)
{
#pragma unroll
    for (int i = 0; i < 2; i++) {
        int idx = tid + i * ETHREADS;
        if (idx < CHB / 16) cp_async16(dst + idx * 16, src + idx * 16);
    }
}

// ============================================================================
// EDGE GEMM: 16 warps in 4x4 grid, warp tile 32 rows x 32 cols, acc[2][4][4].
// cp.async double-buffered B (32-row chunks), one barrier per chunk.
// ============================================================================
template <int KTOT>
__device__ __forceinline__ void run_gemm_e(
    unsigned char* sm, uint32_t smem_base, float (&acc)[2][4][4],
    int a_col_base, const unsigned char* __restrict__ wsrc,
    int tid, int lane, int r0, int n0)
{
#pragma unroll
    for (int mt = 0; mt < 2; mt++)
#pragma unroll
        for (int nb = 0; nb < 4; nb++)
#pragma unroll
            for (int i = 0; i < 4; i++) acc[mt][nb][i] = 0.0f;

    constexpr int NCH = KTOT / 32;
    cp_issue_chunk(smem_base + B_OFF, wsrc, tid);
    CP_COMMIT();

#pragma unroll
    for (int c = 0; c < NCH; c++) {
        CP_WAIT0();
        __syncthreads();        // chunk c visible; all warps done with buf (c+1)&1
        if (c + 1 < NCH) {
            cp_issue_chunk(smem_base + B_OFF + ((c + 1) & 1) * CHB,
                           wsrc + (c + 1) * CHB, tid);
            CP_COMMIT();
        }
        uint32_t bbase = smem_base + B_OFF + (c & 1) * CHB;
#pragma unroll
        for (int ks = 0; ks < 2; ks++) {
            int kcol = a_col_base + c * 32 + ks * 16;
            uint32_t ah[2][4];
            uint32_t a_off = (uint32_t)((r0 + (lane & 15)) * LDA_B + (kcol + (lane >> 4) * 8) * 2);
            ldm_x4(ah[0], smem_base + A_OFF + a_off);
            ldm_x4(ah[1], smem_base + A_OFF + a_off + 16 * LDA_B);
            uint32_t bh[2][4];
            uint32_t b_off = (uint32_t)((ks * 16 + (lane & 15)) * LDB_B + (n0 + (lane >> 4) * 8) * 2);
#pragma unroll
            for (int nt = 0; nt < 2; nt++)
                ldm_x4_t(bh[nt], bbase + b_off + nt * 32);
#pragma unroll
            for (int mt = 0; mt < 2; mt++)
#pragma unroll
                for (int nt = 0; nt < 2; nt++) {
                    mma_f16(acc[mt][2*nt],   ah[mt], bh[nt][0], bh[nt][1]);
                    mma_f16(acc[mt][2*nt+1], ah[mt], bh[nt][2], bh[nt][3]);
                }
        }
    }
    __syncthreads();   // last chunk's MMAs complete in all warps before A reuse
}

// bias + silu + fp16-store to A cols [dstbase, dstbase+128)
__device__ __forceinline__ void epi_store_e(
    unsigned char* sm, float (&acc)[2][4][4], const float* __restrict__ SBIAS,
    int dstbase, int lane, int r0, int n0)
{
#pragma unroll
    for (int mt = 0; mt < 2; mt++) {
        int ra = r0 + mt * 16 + (lane >> 2);
        int rb = ra + 8;
#pragma unroll
        for (int nb = 0; nb < 4; nb++) {
            int c = n0 + nb * 8 + (lane & 3) * 2;
            float b0 = SBIAS[c], b1 = SBIAS[c + 1];
            float v0 = silu_f(acc[mt][nb][0] + b0);
            float v1 = silu_f(acc[mt][nb][1] + b1);
            float v2 = silu_f(acc[mt][nb][2] + b0);
            float v3 = silu_f(acc[mt][nb][3] + b1);
            *(uint32_t*)(sm + ra * LDA_B + (dstbase + c) * 2) = pack2h(v0, v1);
            *(uint32_t*)(sm + rb * LDA_B + (dstbase + c) * 2) = pack2h(v2, v3);
        }
    }
}

// ============================================================================
// Fused edge kernel: 128 edges / CTA, 512 threads, 16 warps (4x4), 2 CTAs/SM.
// ============================================================================
__global__ void __launch_bounds__(ETHREADS, 2)
edge_kernel(const float* __restrict__ h, const float* __restrict__ coord,
            const int* __restrict__ row, const int* __restrict__ col,
            const float* __restrict__ e_b1, const float* __restrict__ e_b2,
            const float* __restrict__ c_b1, const float* __restrict__ c_wout)
{
    extern __shared__ unsigned char sm[];
    const int tid  = threadIdx.x;
    const int wid  = tid >> 5;
    const int lane = tid & 31;
    const int e0   = blockIdx.x * ME;
    uint32_t smem_base = smem_to_u32(sm);

    int*   SROW  = (int*)(sm + OF_ROW);
    int*   SCOL  = (int*)(sm + OF_COL);
    float* SINV  = (float*)(sm + OF_INV);
    float* SBIAS = (float*)(sm + OF_BIAS);
    float* SCWT  = (float*)(sm + OF_CW);    // [4][136] transposed c_wout
    float* SCD   = (float*)(sm + OF_CD);

    if (tid < ME)  { SROW[tid] = row[e0 + tid]; SCOL[tid] = col[e0 + tid]; }
    if (tid < 32)  SINV[tid] = 1.0f / fmaxf(sqrtf(g_sumsq[tid]), 1e-12f);
    if (tid < 256) {   // transpose c_wout [128][4] -> SCWT [4][136]
        int k = tid >> 1, half = tid & 1;
        float2 v = ((const float2*)c_wout)[tid];
        SCWT[(half * 2 + 0) * 136 + k] = v.x;
        SCWT[(half * 2 + 1) * 136 + k] = v.y;
    }
    __syncthreads();

    // ---- gather h[row]|h[col] into A cols 0..255 (fp16) ----
#pragma unroll 4
    for (int idx = tid; idx < ME * 64; idx += ETHREADS) {
        int e = idx >> 6, p4 = idx & 63;
        int half = p4 >> 5, q = p4 & 31;
        int node = half ? SCOL[e] : SROW[e];
        float4 v = ((const float4*)(h + node * HID))[q];
        store4A(sm, e, half * 128 + q * 4, v);
    }
    // ---- rad features cols 256..287; coord_diff to SCD ----
    if (tid < ME) {
        int e = tid;
        const float4* c4i = (const float4*)(coord + SROW[e] * 12);
        const float4* c4j = (const float4*)(coord + SCOL[e] * 12);
        float4 i0 = c4i[0], i1 = c4i[1], i2 = c4i[2];
        float4 j0 = c4j[0], j1 = c4j[1], j2 = c4j[2];
        float a[12] = {i0.x,i0.y,i0.z,i0.w,i1.x,i1.y,i1.z,i1.w,i2.x,i2.y,i2.z,i2.w};
        float b[12] = {j0.x,j0.y,j0.z,j0.w,j1.x,j1.y,j1.z,j1.w,j2.x,j2.y,j2.z,j2.w};
        float d[12];
#pragma unroll
        for (int i = 0; i < 12; i++) { d[i] = a[i] - b[i]; SCD[e * 12 + i] = d[i]; }
        float radv[32];
#pragma unroll
        for (int c = 0; c < 4; c++) {
#pragma unroll
            for (int f = 0; f < 4; f++) {
                float r = d[c*3+0]*d[f*3+0] + d[c*3+1]*d[f*3+1] + d[c*3+2]*d[f*3+2];
                float dx = a[c*3+0]-b[f*3+0], dy = a[c*3+1]-b[f*3+1], dz = a[c*3+2]-b[f*3+2];
                float d2 = dx*dx + dy*dy + dz*dz;
                radv[c*8 + f]     = r * SINV[c*8 + f];
                radv[c*8 + 4 + f] = sqrtf(d2) * SINV[c*8 + 4 + f];
            }
        }
#pragma unroll
        for (int q = 0; q < 32; q += 4)
            store4A(sm, e, 256 + q, make_float4(radv[q], radv[q+1], radv[q+2], radv[q+3]));
    }

    const int wm = wid & 3, wn = wid >> 2;
    const int r0 = wm * 32, n0 = wn * 32;
    float acc[2][4][4];

    // ========== GEMM1: t1 = silu(eh @ W1 + b1) -> A cols 0..127 (K=288) ===
    if (tid < 128) SBIAS[tid] = e_b1[tid];
    run_gemm_e<288>(sm, smem_base, acc, 0, g_w1t, tid, lane, r0, n0);
    epi_store_e(sm, acc, SBIAS, 0, lane, r0, n0);
    __syncthreads();

    // ========== GEMM2: m = silu(t1 @ W2 + b2) -> A cols 128..255 ==========
    if (tid < 128) SBIAS[tid] = e_b2[tid];
    run_gemm_e<128>(sm, smem_base, acc, 0, g_w2t, tid, lane, r0, n0);
    epi_store_e(sm, acc, SBIAS, 128, lane, r0, n0);
    __syncthreads();

    // ---- nagg scatter: coalesced red.v4 from fp16 m in smem ----
#pragma unroll 4
    for (int idx = tid; idx < ME * 32; idx += ETHREADS) {
        int e = idx >> 5, q = (idx & 31) * 4;
        uint2 hv = *(const uint2*)(sm + e * LDA_B + (128 + q) * 2);
        __half2 p0 = *reinterpret_cast<__half2*>(&hv.x);
        __half2 p1 = *reinterpret_cast<__half2*>(&hv.y);
        float2 f0 = __half22float2(p0), f1 = __half22float2(p1);
        float* dst = g_nagg + (size_t)SROW[e] * HID + q;
        asm volatile("red.global.add.v4.f32 [%0], {%1,%2,%3,%4};"
                     :: "l"(dst), "f"(f0.x), "f"(f0.y), "f"(f1.x), "f"(f1.y)
                     : "memory");
    }

    // ========== GEMM3: t2 = silu(m @ c_w1 + b) -> fp32 buffer =============
    if (tid < 128) SBIAS[tid] = c_b1[tid];
    run_gemm_e<128>(sm, smem_base, acc, 128, g_w3t, tid, lane, r0, n0);
    {
        float* t2f = (float*)sm;            // [128 x 132] fp32; A done after GEMM3
#pragma unroll
        for (int mt = 0; mt < 2; mt++) {
            int ra = r0 + mt * 16 + (lane >> 2);
            int rb = ra + 8;
#pragma unroll
            for (int nb = 0; nb < 4; nb++) {
                int c = n0 + nb * 8 + (lane & 3) * 2;
                float b0 = SBIAS[c], b1 = SBIAS[c + 1];
                *(float2*)(t2f + ra * 132 + c) =
                    make_float2(silu_f(acc[mt][nb][0] + b0), silu_f(acc[mt][nb][1] + b1));
                *(float2*)(t2f + rb * 132 + c) =
                    make_float2(silu_f(acc[mt][nb][2] + b0), silu_f(acc[mt][nb][3] + b1));
            }
        }
    }
    __syncthreads();

    // ========== w = t2 @ c_wout (float4 dot); coord atomics ===============
    if (tid < ME * 4) {
        int e = tid >> 2, c = tid & 3;
        const float4* tr4 = (const float4*)((const float*)sm + e * 132);
        const float4* cw4 = (const float4*)(SCWT + c * 136);
        float w = 0.0f;
#pragma unroll
        for (int i = 0; i < 32; i++) {
            float4 t = tr4[i], uq = cw4[i];
            w += t.x * uq.x + t.y * uq.y + t.z * uq.z + t.w * uq.w;
        }
        int node = SROW[e];
        const float* cd = SCD + e * 12 + c * 3;
        atomicAdd(&g_agg[node * 12 + c * 3 + 0], cd[0] * w);
        atomicAdd(&g_agg[node * 12 + c * 3 + 1], cd[1] * w);
        atomicAdd(&g_agg[node * 12 + c * 3 + 2], cd[2] * w);
        if (c == 0) atomicAdd(&g_cnt[node], 1.0f);
    }
}

// ============================================================================
// NODE GEMM machinery (64 rows/CTA, 256 threads, 2x4 warp grid, tile 32x32)
// ============================================================================
#define NSTG 5

__device__ __forceinline__ void ld_stageN(uint4 (&stg)[NSTG],
                                          const unsigned char* __restrict__ wsrc,
                                          int byteoff, int n4, int tid)
{
    const uint4* s = (const uint4*)(wsrc + byteoff);
#pragma unroll
    for (int i = 0; i < NSTG; i++) {
        int idx = tid + i * NTHREADS;
        if (idx < n4) stg[i] = s[idx];
    }
}

template <int KTOT>
__device__ __forceinline__ void run_gemm_n(
    unsigned char* sm, uint32_t smem_base, float (&acc)[2][4][4],
    int a_col_base, const unsigned char* __restrict__ wsrc,
    int tid, int lane, int r0, int n0)
{
#pragma unroll
    for (int mt = 0; mt < 2; mt++)
#pragma unroll
        for (int nb = 0; nb < 4; nb++)
#pragma unroll
            for (int i = 0; i < 4; i++) acc[mt][nb][i] = 0.0f;

    uint4 stg[NSTG];
    constexpr int R0 = (KTOT < 64) ? KTOT : 64;
    ld_stageN(stg, wsrc, 0, R0 * 17, tid);

#pragma unroll
    for (int k0 = 0; k0 < KTOT; k0 += 64) {
        const int rows = (KTOT - k0 < 64) ? (KTOT - k0) : 64;
        const int cn4 = rows * 17;
        __syncthreads();
        {
            uint4* db = (uint4*)(sm + NB_OFF);
#pragma unroll
            for (int i = 0; i < NSTG; i++) {
                int idx = tid + i * NTHREADS;
                if (idx < cn4) db[idx] = stg[i];
            }
        }
        __syncthreads();
        if (k0 + 64 < KTOT) {
            const int nrows = (KTOT - k0 - 64 < 64) ? (KTOT - k0 - 64) : 64;
            ld_stageN(stg, wsrc, (k0 + 64) * LDB_B, nrows * 17, tid);
        }
        const int nks = rows >> 4;
#pragma unroll
        for (int ks = 0; ks < 4; ks++) {
            if (ks >= nks) break;
            int kcol = a_col_base + k0 + ks * 16;
            uint32_t ah[2][4];
            uint32_t a_off = (uint32_t)((r0 + (lane & 15)) * LDA_B + (kcol + (lane >> 4) * 8) * 2);
            ldm_x4(ah[0], smem_base + NA_OFF + a_off);
            ldm_x4(ah[1], smem_base + NA_OFF + a_off + 16 * LDA_B);
            uint32_t bh[2][4];
            uint32_t b_off = (uint32_t)((ks * 16 + (lane & 15)) * LDB_B + (n0 + (lane >> 4) * 8) * 2);
#pragma unroll
            for (int nt = 0; nt < 2; nt++)
                ldm_x4_t(bh[nt], smem_base + NB_OFF + b_off + nt * 32);
#pragma unroll
            for (int mt = 0; mt < 2; mt++)
#pragma unroll
                for (int nt = 0; nt < 2; nt++) {
                    mma_f16(acc[mt][2*nt],   ah[mt], bh[nt][0], bh[nt][1]);
                    mma_f16(acc[mt][2*nt+1], ah[mt], bh[nt][2], bh[nt][3]);
                }
        }
    }
    __syncthreads();
}

__global__ void __launch_bounds__(NTHREADS, 3)
node_kernel(const float* __restrict__ h, const float* __restrict__ coord,
            const float* __restrict__ n_b1, const float* __restrict__ n_b2,
            float* __restrict__ out_h, float* __restrict__ out_coord)
{
    extern __shared__ unsigned char sm[];
    const int tid  = threadIdx.x;
    const int wid  = tid >> 5;
    const int lane = tid & 31;
    const int nb0  = blockIdx.x * MN;
    uint32_t smem_base = smem_to_u32(sm);
    float* SBIAS = (float*)(sm + NOF_BIAS);

    // ---- gather h[n] | nagg[n] into A cols 0..255 (fp16) ----
#pragma unroll 4
    for (int idx = tid; idx < MN * 64; idx += NTHREADS) {
        int r = idx >> 6, p4 = idx & 63;
        int half = p4 >> 5, q = p4 & 31;
        int n = nb0 + r;
        float4 v = make_float4(0.f, 0.f, 0.f, 0.f);
        if (n < N_NODE)
            v = half ? ((const float4*)(g_nagg + n * HID))[q]
                     : ((const float4*)(h + n * HID))[q];
        store4A(sm, r, half * 128 + q * 4, v);
    }

    const int wm = wid & 1, wn = wid >> 1;
    const int r0 = wm * 32, n0 = wn * 32;
    float acc[2][4][4];

    // ========== GEMM1: t = silu(nin @ nW1 + b1) -> A cols 0..127 ==========
    if (tid < 128) SBIAS[tid] = n_b1[tid];
    run_gemm_n<256>(sm, smem_base, acc, 0, g_nw1t, tid, lane, r0, n0);
    {
#pragma unroll
        for (int mt = 0; mt < 2; mt++) {
            int ra = r0 + mt * 16 + (lane >> 2);
            int rb = ra + 8;
#pragma unroll
            for (int nb = 0; nb < 4; nb++) {
                int c = n0 + nb * 8 + (lane & 3) * 2;
                float b0 = SBIAS[c], b1 = SBIAS[c + 1];
                *(uint32_t*)(sm + ra * LDA_B + c * 2) =
                    pack2h(silu_f(acc[mt][nb][0] + b0), silu_f(acc[mt][nb][1] + b1));
                *(uint32_t*)(sm + rb * LDA_B + c * 2) =
                    pack2h(silu_f(acc[mt][nb][2] + b0), silu_f(acc[mt][nb][3] + b1));
            }
        }
    }
    __syncthreads();

    // ========== GEMM2: hn = t @ nW2 + b2 ; out_h = h + hn =================
    if (tid < 128) SBIAS[tid] = n_b2[tid];
    run_gemm_n<128>(sm, smem_base, acc, 0, g_nw2t, tid, lane, r0, n0);
    {
#pragma unroll
        for (int mt = 0; mt < 2; mt++) {
            int ra = r0 + mt * 16 + (lane >> 2);
            int rb = ra + 8;
            int na = nb0 + ra, nbv = nb0 + rb;
#pragma unroll
            for (int nb = 0; nb < 4; nb++) {
                int c = n0 + nb * 8 + (lane & 3) * 2;
                float b0 = SBIAS[c], b1 = SBIAS[c + 1];
                if (na < N_NODE) {
                    float2 hv = *(const float2*)(h + na * HID + c);
                    *(float2*)(out_h + na * HID + c) =
                        make_float2(acc[mt][nb][0] + b0 + hv.x,
                                    acc[mt][nb][1] + b1 + hv.y);
                }
                if (nbv < N_NODE) {
                    float2 hv = *(const float2*)(h + nbv * HID + c);
                    *(float2*)(out_h + nbv * HID + c) =
                        make_float2(acc[mt][nb][2] + b0 + hv.x,
                                    acc[mt][nb][3] + b1 + hv.y);
                }
            }
        }
    }
    // ---- coord epilogue ----
    for (int idx = tid; idx < MN * 12; idx += NTHREADS) {
        int r = idx / 12, d = idx % 12;
        int n = nb0 + r;
        if (n < N_NODE) {
            float cnt = fmaxf(g_cnt[n], 1.0f);
            out_coord[n * 12 + d] = coord[n * 12 + d] + g_agg[n * 12 + d] / cnt;
        }
    }
}

// ============================================================================
extern "C" void kernel_launch(void* const* d_in, const int* in_sizes, int n_in,
                              void* d_out, int out_size)
{
    const float* h      = (const float*)d_in[0];
    const float* coord  = (const float*)d_in[1];
    const int*   row    = (const int*)d_in[2];
    const int*   col    = (const int*)d_in[3];
    const float* e_w1   = (const float*)d_in[4];
    const float* e_b1   = (const float*)d_in[5];
    const float* e_w2   = (const float*)d_in[6];
    const float* e_b2   = (const float*)d_in[7];
    const float* c_w1   = (const float*)d_in[8];
    const float* c_b1   = (const float*)d_in[9];
    const float* c_wout = (const float*)d_in[10];
    const float* n_w1   = (const float*)d_in[11];
    const float* n_b1   = (const float*)d_in[12];
    const float* n_w2   = (const float*)d_in[13];
    const float* n_b2   = (const float*)d_in[14];

    float* out_h     = (float*)d_out;
    float* out_coord = out_h + N_NODE * HID;

    void *p_sumsq, *p_nagg, *p_agg, *p_cnt;
    cudaGetSymbolAddress(&p_sumsq, g_sumsq);
    cudaGetSymbolAddress(&p_nagg,  g_nagg);
    cudaGetSymbolAddress(&p_agg,   g_agg);
    cudaGetSymbolAddress(&p_cnt,   g_cnt);
    cudaMemsetAsync(p_sumsq, 0, 32 * sizeof(float));
    cudaMemsetAsync(p_nagg,  0, N_NODE * HID * sizeof(float));
    cudaMemsetAsync(p_agg,   0, N_NODE * 12 * sizeof(float));
    cudaMemsetAsync(p_cnt,   0, N_NODE * sizeof(float));

    cudaFuncSetAttribute(edge_kernel, cudaFuncAttributeMaxDynamicSharedMemorySize,
                         SMEM_EDGE_BYTES);
    cudaFuncSetAttribute(node_kernel, cudaFuncAttributeMaxDynamicSharedMemorySize,
                         SMEM_NODE_BYTES);

    prep_sumsq_kernel<<<PREP_BLOCKS + SUMSQ_BLOCKS, 256>>>(
        e_w1, e_w2, c_w1, n_w1, n_w2, coord, row, col);
    edge_kernel<<<N_EDGE / ME, ETHREADS, SMEM_EDGE_BYTES>>>(
        h, coord, row, col, e_b1, e_b2, c_b1, c_wout);
    node_kernel<<<(N_NODE + MN - 1) / MN, NTHREADS, SMEM_NODE_BYTES>>>(
        h, coord, n_b1, n_b2, out_h, out_coord);
}